// round 10
// baseline (speedup 1.0000x reference)
#include <cuda_runtime.h>
#include <cuda_bf16.h>
#include <math.h>
#include <stdint.h>

#define Gn  16
#define Nn  96
#define Hd  128
#define Ed  24576
#define NGn (Gn*Nn)   // 1536
#define MSZ (NGn*Hd)
#define EPZ (Ed*Hd)

typedef unsigned long long ull;

// ---------------- packed f32x2 helpers -------------------------------------
__device__ __forceinline__ ull pk1(float x) {
    ull r; asm("mov.b64 %0, {%1,%1};" : "=l"(r) : "f"(x)); return r;
}
__device__ __forceinline__ ull pk2(float x, float y) {
    ull r; asm("mov.b64 %0, {%1,%2};" : "=l"(r) : "f"(x), "f"(y)); return r;
}
__device__ __forceinline__ void ffma2(ull& d, ull a, ull b) {
    asm("fma.rn.f32x2 %0, %1, %2, %0;" : "+l"(d) : "l"(a), "l"(b));
}
__device__ __forceinline__ float2 unpk(ull v) {
    float2 f; asm("mov.b64 {%0,%1}, %2;" : "=f"(f.x), "=f"(f.y) : "l"(v)); return f;
}

// ---------------- bf16 split helpers ---------------------------------------
__device__ __forceinline__ uint32_t pkbf(float lo, float hi) {
    uint32_t r; asm("cvt.rn.bf16x2.f32 %0, %1, %2;" : "=r"(r) : "f"(hi), "f"(lo)); return r;
}
__device__ __forceinline__ void split_store(char* hiT, char* loT, uint32_t off,
                                            float f0, float f1) {
    uint32_t h = pkbf(f0, f1);
    float h0 = __uint_as_float(h << 16);
    float h1 = __uint_as_float(h & 0xffff0000u);
    uint32_t l = pkbf(f0 - h0, f1 - h1);
    *(uint32_t*)(hiT + off) = h;
    *(uint32_t*)(loT + off) = l;
}

// HMMA m16n8k16 bf16 -> f32 accumulate (arch-agnostic PTX, sm_80+)
__device__ __forceinline__ void mma16816(float* d, const uint32_t* a, const uint32_t* b) {
    asm volatile(
        "mma.sync.aligned.m16n8k16.row.col.f32.bf16.bf16.f32 "
        "{%0,%1,%2,%3}, {%4,%5,%6,%7}, {%8,%9}, {%0,%1,%2,%3};"
        : "+f"(d[0]), "+f"(d[1]), "+f"(d[2]), "+f"(d[3])
        : "r"(a[0]), "r"(a[1]), "r"(a[2]), "r"(a[3]), "r"(b[0]), "r"(b[1]));
}

// ---------------- scratch ---------------------------------------------------
#define ARS  272              // tile row stride in bytes (136 bf16)
#define TILE_B 34816          // 128 rows * 272 B
#define WSET_B (4*TILE_B)     // W1H,W1L,W2H,W2L contiguous = 139264 B

__device__ __align__(16) float g_node[MSZ];
__device__ __align__(16) float g_hidden[MSZ];
__device__ __align__(16) float g_edgefts[EPZ];
__device__ __align__(16) float g_edgeproj[6*EPZ];     // per (layer,stream), precomputed
__device__              int   g_eidx[Gn*Nn*Nn];
__device__ __align__(16) float g_msg1[2*MSZ];         // per-stream
__device__ __align__(16) float g_msg2[2*MSZ];         // per-stream
__device__ __align__(16) float g_maxmsg[2*MSZ];       // per-stream
__device__ __align__(16) float g_out0[MSZ];
__device__ __align__(16) float g_out1[MSZ];
__device__ __align__(16) char  g_wt[6*WSET_B];        // pre-split MLP weight tiles
__device__ __align__(16) char  g_wtme[6*2*TILE_B];    // pre-split W_me tiles

extern __shared__ char dyn_smem[];

// ---------------- encoders --------------------------------------------------
__global__ void k_encode_nodes(const int* __restrict__ x,
                               const float* __restrict__ atom) {
    int n = blockIdx.x, h = threadIdx.x;
    float s = 0.f;
#pragma unroll
    for (int c = 0; c < 9; c++) {
        int id = x[n*9 + c];
        s += atom[(c*119 + id)*Hd + h];
    }
    g_node[n*Hd + h]   = s;
    g_hidden[n*Hd + h] = 0.f;
}

__global__ void k_encode_edges(const int* __restrict__ ea,
                               const float* __restrict__ bond) {
    int e = blockIdx.x, h = threadIdx.x;
    float s = 0.f;
#pragma unroll
    for (int c = 0; c < 3; c++) {
        int id = ea[e*3 + c];
        s += bond[(c*6 + id)*Hd + h];
    }
    g_edgefts[e*Hd + h] = s;
}

__global__ void k_init_eidx() {
    int i = blockIdx.x*blockDim.x + threadIdx.x;
    if (i < Gn*Nn*Nn) g_eidx[i] = -1;
}

__global__ void k_scatter(const int* __restrict__ src, const int* __restrict__ dst) {
    int e = blockIdx.x*blockDim.x + threadIdx.x;
    if (e >= Ed) return;
    int s = src[e], d = dst[e];
    int g  = s / Nn;
    int li = s % Nn;
    int lj = d % Nn;
    atomicMax(&g_eidx[(g*Nn + li)*Nn + lj], e);
}

// ---------------- one-time weight prep (W1, W2, Wme) -----------------------
__global__ void k_prepw(const float* __restrict__ Wl1, const float* __restrict__ Wl2,
                        const float* __restrict__ Wmeg) {
    int ls = blockIdx.y;
    const float* W1 = Wl1 + (size_t)ls*Hd*Hd;
    const float* W2 = Wl2 + (size_t)ls*Hd*Hd;
    const float* We = Wmeg + (size_t)ls*Hd*Hd;
    char* base  = g_wt + (size_t)ls*WSET_B;
    char* baseE = g_wtme + (size_t)ls*2*TILE_B;
    int n0 = blockIdx.x*8;
    for (int p = threadIdx.x; p < 8*64; p += 256) {
        int nl = p >> 6, k = (p & 63)*2;
        int n = n0 + nl;
        uint32_t off = (uint32_t)(n*ARS + k*2);
        split_store(base,            base + TILE_B,   off, W1[k*Hd + n], W1[(k+1)*Hd + n]);
        split_store(base + 2*TILE_B, base + 3*TILE_B, off, W2[k*Hd + n], W2[(k+1)*Hd + n]);
        split_store(baseE,           baseE + TILE_B,  off, We[k*Hd + n], We[(k+1)*Hd + n]);
    }
}

// ---------------- msg1/msg2 (ffma2), gridDim.y = stream --------------------
__global__ void k_msg12(const float* __restrict__ Wm1, const float* __restrict__ bm1g,
                        const float* __restrict__ Wm2, const float* __restrict__ bm2g,
                        const float* __restrict__ bmeg, const float* __restrict__ bmgg,
                        int layer) {
    int s = blockIdx.y, ls = layer*2 + s;
    const float* W1 = Wm1 + (size_t)ls*256*Hd;
    const float* W2 = Wm2 + (size_t)ls*256*Hd;
    __shared__ float zS[256*8];
    int tid = threadIdx.x, n0 = blockIdx.x*8;
    for (int idx = tid; idx < 8*256; idx += 128) {
        int nn = idx >> 8, k = idx & 255;
        int n = n0 + nn;
        float v = (k < Hd) ? g_node[n*Hd + k] : g_hidden[n*Hd + (k - Hd)];
        zS[k*8 + nn] = v;
    }
    __syncthreads();
    int h = tid;
    ull a1[4], a2[4];
#pragma unroll
    for (int p = 0; p < 4; p++) { a1[p] = 0ull; a2[p] = 0ull; }
    for (int k = 0; k < 256; k++) {
        ull w1 = pk1(W1[k*Hd + h]);
        ull w2 = pk1(W2[k*Hd + h]);
        const float2* zr = (const float2*)(zS + k*8);
#pragma unroll
        for (int p = 0; p < 4; p++) {
            float2 z = zr[p];
            ull zp = pk2(z.x, z.y);
            ffma2(a1[p], zp, w1);
            ffma2(a2[p], zp, w2);
        }
    }
    float bb1 = bm1g[ls*Hd + h] + bmeg[ls*Hd + h] + bmgg[ls*Hd + h];
    float bb2 = bm2g[ls*Hd + h];
    float* m1 = g_msg1 + (size_t)s*MSZ;
    float* m2 = g_msg2 + (size_t)s*MSZ;
#pragma unroll
    for (int p = 0; p < 4; p++) {
        float2 v1 = unpk(a1[p]), v2 = unpk(a2[p]);
        m1[(n0+2*p+0)*Hd + h] = v1.x + bb1;
        m1[(n0+2*p+1)*Hd + h] = v1.y + bb1;
        m2[(n0+2*p+0)*Hd + h] = v2.x + bb2;
        m2[(n0+2*p+1)*Hd + h] = v2.y + bb2;
    }
}

// ---------------- edge projection (HMMA, all 6 weight sets upfront) --------
// grid (192, 6); block = 128 edges x 128 outputs; smem = 4 tiles
#define EO_AHI 0
#define EO_ALO TILE_B
#define EO_WH  (2*TILE_B)
#define EO_WL  (3*TILE_B)
#define SMEM_EP (4*TILE_B)

__global__ void __launch_bounds__(256, 1) k_edgeproj_mma() {
    char* sh = dyn_smem;
    const int tid = threadIdx.x, w = tid >> 5, lane = tid & 31;
    const int gq = lane >> 2, t = lane & 3;
    const int rg = w >> 1, cg = w & 1;       // 4x2 warp grid
    const int R0 = rg*32, C0 = cg*64;
    const int ls = blockIdx.y;
    const int e0 = blockIdx.x*128;

    // W tiles (pre-split, contiguous)
    {
        const uint4* src = (const uint4*)(g_wtme + (size_t)ls*2*TILE_B);
        uint4* dst = (uint4*)(sh + EO_WH);
        for (int p = tid; p < 2*TILE_B/16; p += 256) dst[p] = src[p];
    }
    // stage A: edgefts rows e0..e0+127, split hi/lo
    for (int p = tid; p < 128*64; p += 256) {
        int r = p >> 6, c = (p & 63)*2;
        float2 a = *(const float2*)(g_edgefts + (size_t)(e0 + r)*Hd + c);
        split_store(sh + EO_AHI, sh + EO_ALO, (uint32_t)(r*ARS + c*2), a.x, a.y);
    }
    __syncthreads();

    float acc[2][8][4];
#pragma unroll
    for (int mi = 0; mi < 2; mi++)
#pragma unroll
        for (int ni = 0; ni < 8; ni++)
#pragma unroll
            for (int q = 0; q < 4; q++) acc[mi][ni][q] = 0.f;

#pragma unroll
    for (int ks = 0; ks < 8; ks++) {
        int kb = (ks*16 + t*2)*2;
        uint32_t afh[2][4], afl[2][4];
#pragma unroll
        for (int mi = 0; mi < 2; mi++) {
            int r = R0 + mi*16 + gq;
            afh[mi][0] = *(const uint32_t*)(sh + EO_AHI + r*ARS + kb);
            afh[mi][1] = *(const uint32_t*)(sh + EO_AHI + (r+8)*ARS + kb);
            afh[mi][2] = *(const uint32_t*)(sh + EO_AHI + r*ARS + kb + 16);
            afh[mi][3] = *(const uint32_t*)(sh + EO_AHI + (r+8)*ARS + kb + 16);
            afl[mi][0] = *(const uint32_t*)(sh + EO_ALO + r*ARS + kb);
            afl[mi][1] = *(const uint32_t*)(sh + EO_ALO + (r+8)*ARS + kb);
            afl[mi][2] = *(const uint32_t*)(sh + EO_ALO + r*ARS + kb + 16);
            afl[mi][3] = *(const uint32_t*)(sh + EO_ALO + (r+8)*ARS + kb + 16);
        }
        uint32_t bfh[8][2], bfl[8][2];
#pragma unroll
        for (int ni = 0; ni < 8; ni++) {
            int n = C0 + ni*8 + gq;
            bfh[ni][0] = *(const uint32_t*)(sh + EO_WH + n*ARS + kb);
            bfh[ni][1] = *(const uint32_t*)(sh + EO_WH + n*ARS + kb + 16);
            bfl[ni][0] = *(const uint32_t*)(sh + EO_WL + n*ARS + kb);
            bfl[ni][1] = *(const uint32_t*)(sh + EO_WL + n*ARS + kb + 16);
        }
#pragma unroll
        for (int mi = 0; mi < 2; mi++)
#pragma unroll
            for (int ni = 0; ni < 8; ni++) {
                mma16816(acc[mi][ni], afh[mi], bfh[ni]);
                mma16816(acc[mi][ni], afh[mi], bfl[ni]);
                mma16816(acc[mi][ni], afl[mi], bfh[ni]);
            }
    }

    float* ep = g_edgeproj + (size_t)ls*EPZ;
#pragma unroll
    for (int mi = 0; mi < 2; mi++)
#pragma unroll
        for (int ni = 0; ni < 8; ni++) {
            int r = R0 + mi*16 + gq, c = C0 + ni*8 + t*2;
            *(float2*)(ep + (size_t)(e0 + r)*Hd + c) =
                make_float2(acc[mi][ni][0], acc[mi][ni][1]);
            *(float2*)(ep + (size_t)(e0 + r + 8)*Hd + c) =
                make_float2(acc[mi][ni][2], acc[mi][ni][3]);
        }
}

// ---------------- fused message MLP + max (persistent HMMA) ----------------
#define O_AHI  0
#define O_ALO  26112
#define O_W1H  52224
#define O_W1L  (O_W1H + TILE_B)
#define O_W2H  (O_W1H + 2*TILE_B)
#define O_W2L  (O_W1H + 3*TILE_B)
#define O_B1   191488
#define O_M1   192000
#define O_EIX  192512
#define O_MAXR 192896
#define O_B2   193920
#define SMEM_FUSED 194432

__global__ void __launch_bounds__(256, 1)
k_fused_mma(int layer, const float* __restrict__ bl1, const float* __restrict__ bl2) {
    char* sh = dyn_smem;
    const int tid = threadIdx.x, w = tid >> 5, lane = tid & 31;
    const int gq = lane >> 2, t = lane & 3;
    const int rg = w >> 2, cg = w & 3;
    const int R0 = rg*48, C0 = cg*32;

    float* b1s  = (float*)(sh + O_B1);
    float* b2s  = (float*)(sh + O_B2);
    float* m1S  = (float*)(sh + O_M1);
    int*   eixS = (int*)(sh + O_EIX);
    float* maxr = (float*)(sh + O_MAXR);

    int cur_s = -1;
    for (int tt = blockIdx.x; tt < 2*NGn; tt += gridDim.x) {
        const int s  = (tt >= NGn) ? 1 : 0;
        const int lt = tt - s*NGn;
        const int g  = lt / Nn, j = lt - g*Nn;
        const int ls = layer*2 + s;

        if (s != cur_s) {
            const uint4* src = (const uint4*)(g_wt + (size_t)ls*WSET_B);
            uint4* dst = (uint4*)(sh + O_W1H);
            for (int p = tid; p < WSET_B/16; p += 256) dst[p] = src[p];
            if (tid < Hd) b1s[tid] = bl1[ls*Hd + tid];
            else          b2s[tid - 128] = bl2[ls*Hd + (tid - 128)];
            cur_s = s;
        }

        const float* msg1  = g_msg1 + (size_t)s*MSZ;
        const float* msg2  = g_msg2 + (size_t)s*MSZ;
        const float* eproj = g_edgeproj + (size_t)ls*EPZ;
        float* mmout = g_maxmsg + (size_t)s*MSZ;

        if (tid < Hd)       m1S[tid] = msg1[(g*Nn + j)*Hd + tid];
        else if (tid < 224) eixS[tid - 128] = g_eidx[(g*Nn + (tid - 128))*Nn + j];
        __syncthreads();

        for (int p = tid; p < Nn*64; p += 256) {
            int r = p >> 6, c = (p & 63)*2;
            float2 m2 = *(const float2*)(msg2 + (size_t)(g*Nn + r)*Hd + c);
            float f0 = m1S[c] + m2.x, f1 = m1S[c+1] + m2.y;
            int e = eixS[r];
            if (e >= 0) {
                float2 ep = *(const float2*)(eproj + (size_t)e*Hd + c);
                f0 += ep.x; f1 += ep.y;
            }
            f0 = fmaxf(f0, 0.f); f1 = fmaxf(f1, 0.f);
            split_store(sh + O_AHI, sh + O_ALO, (uint32_t)(r*ARS + c*2), f0, f1);
        }
        __syncthreads();

        float acc[3][4][4];
#pragma unroll
        for (int mi = 0; mi < 3; mi++)
#pragma unroll
            for (int ni = 0; ni < 4; ni++)
#pragma unroll
                for (int q = 0; q < 4; q++) acc[mi][ni][q] = 0.f;

        // ---- GEMM1 ----
#pragma unroll
        for (int ks = 0; ks < 8; ks++) {
            int kb = (ks*16 + t*2)*2;
            uint32_t afh[3][4], afl[3][4];
#pragma unroll
            for (int mi = 0; mi < 3; mi++) {
                int r = R0 + mi*16 + gq;
                afh[mi][0] = *(const uint32_t*)(sh + O_AHI + r*ARS + kb);
                afh[mi][1] = *(const uint32_t*)(sh + O_AHI + (r+8)*ARS + kb);
                afh[mi][2] = *(const uint32_t*)(sh + O_AHI + r*ARS + kb + 16);
                afh[mi][3] = *(const uint32_t*)(sh + O_AHI + (r+8)*ARS + kb + 16);
                afl[mi][0] = *(const uint32_t*)(sh + O_ALO + r*ARS + kb);
                afl[mi][1] = *(const uint32_t*)(sh + O_ALO + (r+8)*ARS + kb);
                afl[mi][2] = *(const uint32_t*)(sh + O_ALO + r*ARS + kb + 16);
                afl[mi][3] = *(const uint32_t*)(sh + O_ALO + (r+8)*ARS + kb + 16);
            }
            uint32_t bfh[4][2], bfl[4][2];
#pragma unroll
            for (int ni = 0; ni < 4; ni++) {
                int n = C0 + ni*8 + gq;
                bfh[ni][0] = *(const uint32_t*)(sh + O_W1H + n*ARS + kb);
                bfh[ni][1] = *(const uint32_t*)(sh + O_W1H + n*ARS + kb + 16);
                bfl[ni][0] = *(const uint32_t*)(sh + O_W1L + n*ARS + kb);
                bfl[ni][1] = *(const uint32_t*)(sh + O_W1L + n*ARS + kb + 16);
            }
#pragma unroll
            for (int mi = 0; mi < 3; mi++)
#pragma unroll
                for (int ni = 0; ni < 4; ni++) {
                    mma16816(acc[mi][ni], afh[mi], bfh[ni]);
                    mma16816(acc[mi][ni], afh[mi], bfl[ni]);
                    mma16816(acc[mi][ni], afl[mi], bfh[ni]);
                }
        }

        // ---- epilogue1 ----
        __syncthreads();
#pragma unroll
        for (int mi = 0; mi < 3; mi++) {
#pragma unroll
            for (int ni = 0; ni < 4; ni++) {
                int r = R0 + mi*16 + gq, c = C0 + ni*8 + t*2;
                float f0 = fmaxf(acc[mi][ni][0] + b1s[c],   0.f);
                float f1 = fmaxf(acc[mi][ni][1] + b1s[c+1], 0.f);
                split_store(sh + O_AHI, sh + O_ALO, (uint32_t)(r*ARS + c*2), f0, f1);
                float f2 = fmaxf(acc[mi][ni][2] + b1s[c],   0.f);
                float f3 = fmaxf(acc[mi][ni][3] + b1s[c+1], 0.f);
                split_store(sh + O_AHI, sh + O_ALO, (uint32_t)((r+8)*ARS + c*2), f2, f3);
            }
        }
        __syncthreads();

#pragma unroll
        for (int mi = 0; mi < 3; mi++)
#pragma unroll
            for (int ni = 0; ni < 4; ni++)
#pragma unroll
                for (int q = 0; q < 4; q++) acc[mi][ni][q] = 0.f;

        // ---- GEMM2 ----
#pragma unroll
        for (int ks = 0; ks < 8; ks++) {
            int kb = (ks*16 + t*2)*2;
            uint32_t afh[3][4], afl[3][4];
#pragma unroll
            for (int mi = 0; mi < 3; mi++) {
                int r = R0 + mi*16 + gq;
                afh[mi][0] = *(const uint32_t*)(sh + O_AHI + r*ARS + kb);
                afh[mi][1] = *(const uint32_t*)(sh + O_AHI + (r+8)*ARS + kb);
                afh[mi][2] = *(const uint32_t*)(sh + O_AHI + r*ARS + kb + 16);
                afh[mi][3] = *(const uint32_t*)(sh + O_AHI + (r+8)*ARS + kb + 16);
                afl[mi][0] = *(const uint32_t*)(sh + O_ALO + r*ARS + kb);
                afl[mi][1] = *(const uint32_t*)(sh + O_ALO + (r+8)*ARS + kb);
                afl[mi][2] = *(const uint32_t*)(sh + O_ALO + r*ARS + kb + 16);
                afl[mi][3] = *(const uint32_t*)(sh + O_ALO + (r+8)*ARS + kb + 16);
            }
            uint32_t bfh[4][2], bfl[4][2];
#pragma unroll
            for (int ni = 0; ni < 4; ni++) {
                int n = C0 + ni*8 + gq;
                bfh[ni][0] = *(const uint32_t*)(sh + O_W2H + n*ARS + kb);
                bfh[ni][1] = *(const uint32_t*)(sh + O_W2H + n*ARS + kb + 16);
                bfl[ni][0] = *(const uint32_t*)(sh + O_W2L + n*ARS + kb);
                bfl[ni][1] = *(const uint32_t*)(sh + O_W2L + n*ARS + kb + 16);
            }
#pragma unroll
            for (int mi = 0; mi < 3; mi++)
#pragma unroll
                for (int ni = 0; ni < 4; ni++) {
                    mma16816(acc[mi][ni], afh[mi], bfh[ni]);
                    mma16816(acc[mi][ni], afh[mi], bfl[ni]);
                    mma16816(acc[mi][ni], afl[mi], bfh[ni]);
                }
        }

        // ---- max over senders ----
#pragma unroll
        for (int ni = 0; ni < 4; ni++) {
            float v0 = fmaxf(acc[0][ni][0], acc[0][ni][2]);
            float v1 = fmaxf(acc[0][ni][1], acc[0][ni][3]);
#pragma unroll
            for (int mi = 1; mi < 3; mi++) {
                v0 = fmaxf(v0, fmaxf(acc[mi][ni][0], acc[mi][ni][2]));
                v1 = fmaxf(v1, fmaxf(acc[mi][ni][1], acc[mi][ni][3]));
            }
#pragma unroll
            for (int st = 4; st < 32; st <<= 1) {
                v0 = fmaxf(v0, __shfl_xor_sync(0xffffffffu, v0, st));
                v1 = fmaxf(v1, __shfl_xor_sync(0xffffffffu, v1, st));
            }
            if (gq == 0) {
                maxr[rg*128 + C0 + ni*8 + t*2]     = v0;
                maxr[rg*128 + C0 + ni*8 + t*2 + 1] = v1;
            }
        }
        __syncthreads();
        if (tid < Hd)
            mmout[(g*Nn + j)*Hd + tid] =
                fmaxf(maxr[tid], maxr[128 + tid]) + b2s[tid];
        __syncthreads();
    }
}

// ---------------- out + layernorm, gridDim.y = stream ----------------------
__device__ __forceinline__ float blk_sum128(float v, volatile float* red) {
    int tid = threadIdx.x;
#pragma unroll
    for (int o = 16; o; o >>= 1) v += __shfl_xor_sync(0xffffffffu, v, o);
    if ((tid & 31) == 0) red[tid >> 5] = v;
    __syncthreads();
    float t = red[0] + red[1] + red[2] + red[3];
    __syncthreads();
    return t;
}

__global__ void k_outln(const float* __restrict__ Wo1g, const float* __restrict__ bo1g,
                        const float* __restrict__ Wo2g, const float* __restrict__ bo2g,
                        const float* __restrict__ lgg,  const float* __restrict__ lbg,
                        int layer) {
    int s = blockIdx.y, ls = layer*2 + s;
    const float* Wo1 = Wo1g + (size_t)ls*256*Hd;
    const float* Wo2 = Wo2g + (size_t)ls*Hd*Hd;
    __shared__ float zS[4*256];
    __shared__ float mmS[4*128];
    __shared__ float red[4];
    int tid = threadIdx.x, n0 = blockIdx.x*4;
    const float* mm = g_maxmsg + (size_t)s*MSZ;
    for (int idx = tid; idx < 1024; idx += 128) {
        int nn = idx >> 8, k = idx & 255;
        zS[idx] = (k < Hd) ? g_node[(n0+nn)*Hd + k] : g_hidden[(n0+nn)*Hd + (k - Hd)];
    }
    for (int idx = tid; idx < 512; idx += 128) {
        int nn = idx >> 7, k = idx & 127;
        mmS[idx] = mm[(n0+nn)*Hd + k];
    }
    __syncthreads();
    int h = tid;
    float acc[4];
    float bb = bo1g[ls*Hd + h] + bo2g[ls*Hd + h];
#pragma unroll
    for (int nn = 0; nn < 4; nn++) acc[nn] = bb;
    for (int k = 0; k < 256; k++) {
        float w = Wo1[k*Hd + h];
#pragma unroll
        for (int nn = 0; nn < 4; nn++) acc[nn] += zS[nn*256 + k]*w;
    }
    for (int k = 0; k < 128; k++) {
        float w = Wo2[k*Hd + h];
#pragma unroll
        for (int nn = 0; nn < 4; nn++) acc[nn] += mmS[nn*128 + k]*w;
    }
    float lgv = lgg[ls*Hd + h], lbv = lbg[ls*Hd + h];
    float* ob = s ? g_out1 : g_out0;
    for (int nn = 0; nn < 4; nn++) {
        float v = fmaxf(acc[nn], 0.f);
        float mu = blk_sum128(v, red) * (1.f/128.f);
        float d = v - mu;
        float var = blk_sum128(d*d, red) * (1.f/128.f);
        float rstd = rsqrtf(var + 1e-5f);
        ob[(n0+nn)*Hd + h] = d*rstd*lgv + lbv;
    }
}

// ---------------- hidden = concat(out0,out1) @ W_red + b_red ---------------
__global__ void k_reduce(const float* __restrict__ Wred, const float* __restrict__ bred) {
    __shared__ float zz[4*256];
    int tid = threadIdx.x, n0 = blockIdx.x*4;
    for (int idx = tid; idx < 1024; idx += 128) {
        int nn = idx >> 8, k = idx & 255;
        zz[idx] = (k < Hd) ? g_out0[(n0+nn)*Hd + k] : g_out1[(n0+nn)*Hd + (k - Hd)];
    }
    __syncthreads();
    int h = tid;
    float acc[4];
    float bb = bred[h];
#pragma unroll
    for (int nn = 0; nn < 4; nn++) acc[nn] = bb;
    for (int k = 0; k < 256; k++) {
        float w = Wred[k*Hd + h];
#pragma unroll
        for (int nn = 0; nn < 4; nn++) acc[nn] += zz[nn*256 + k]*w;
    }
#pragma unroll
    for (int nn = 0; nn < 4; nn++) g_hidden[(n0+nn)*Hd + h] = acc[nn];
}

// ---------------- readout --------------------------------------------------
__global__ void k_final(const float* __restrict__ Wp1, const float* __restrict__ bp1,
                        const float* __restrict__ Wp2, const float* __restrict__ bp2,
                        float* __restrict__ out) {
    __shared__ float embS[128], h1S[128], red[4];
    int g = blockIdx.x, h = threadIdx.x;
    float s = 0.f;
    for (int n = 0; n < Nn; n++) s += g_hidden[(g*Nn + n)*Hd + h];
    embS[h] = s * (1.f/96.f);
    __syncthreads();
    float a = bp1[h];
    for (int k = 0; k < 128; k++) a += embS[k]*Wp1[k*Hd + h];
    h1S[h] = fmaxf(a, 0.f);
    __syncthreads();
    float v = h1S[h] * Wp2[h];
    float tot = blk_sum128(v, red);
    if (h == 0) out[g] = tot + bp2[0];
}

// ---------------- launch ---------------------------------------------------
extern "C" void kernel_launch(void* const* d_in, const int* in_sizes, int n_in,
                              void* d_out, int out_size) {
    int o = (n_in >= 32) ? 6 : 4;
    const int*   x    = (const int*)d_in[0];
    const int*   ea   = (const int*)d_in[1];
    const int*   src  = (const int*)d_in[2];
    const int*   dst  = (const int*)d_in[3];
    const float* atom = (const float*)d_in[o+0];
    const float* bond = (const float*)d_in[o+1];
    const float* Wm1  = (const float*)d_in[o+2];
    const float* bm1  = (const float*)d_in[o+3];
    const float* Wm2  = (const float*)d_in[o+4];
    const float* bm2  = (const float*)d_in[o+5];
    const float* Wme  = (const float*)d_in[o+6];
    const float* bme  = (const float*)d_in[o+7];
    const float* bmg  = (const float*)d_in[o+9];   // W_mg unused (graph_fts == 0)
    const float* Wl1  = (const float*)d_in[o+10];
    const float* bl1  = (const float*)d_in[o+11];
    const float* Wl2  = (const float*)d_in[o+12];
    const float* bl2  = (const float*)d_in[o+13];
    const float* Wo1  = (const float*)d_in[o+14];
    const float* bo1  = (const float*)d_in[o+15];
    const float* Wo2  = (const float*)d_in[o+16];
    const float* bo2  = (const float*)d_in[o+17];
    const float* lng  = (const float*)d_in[o+18];
    const float* lnb  = (const float*)d_in[o+19];
    const float* Wred = (const float*)d_in[o+20];
    const float* bred = (const float*)d_in[o+21];
    const float* Wp1  = (const float*)d_in[o+22];
    const float* bp1  = (const float*)d_in[o+23];
    const float* Wp2  = (const float*)d_in[o+24];
    const float* bp2  = (const float*)d_in[o+25];
    float* out = (float*)d_out;

    cudaFuncSetAttribute(k_fused_mma,    cudaFuncAttributeMaxDynamicSharedMemorySize, SMEM_FUSED);
    cudaFuncSetAttribute(k_edgeproj_mma, cudaFuncAttributeMaxDynamicSharedMemorySize, SMEM_EP);

    k_encode_nodes<<<NGn, 128>>>(x, atom);
    k_encode_edges<<<Ed, 128>>>(ea, bond);
    k_init_eidx<<<(Gn*Nn*Nn + 255)/256, 256>>>();
    k_scatter<<<(Ed + 255)/256, 256>>>(src, dst);
    k_prepw<<<dim3(16, 6), 256>>>(Wl1, Wl2, Wme);
    k_edgeproj_mma<<<dim3(Ed/128, 6), 256, SMEM_EP>>>();

    for (int i = 0; i < 3; i++) {
        k_msg12<<<dim3(NGn/8, 2), 128>>>(Wm1, bm1, Wm2, bm2, bme, bmg, i);
        k_fused_mma<<<148, 256, SMEM_FUSED>>>(i, bl1, bl2);
        k_outln<<<dim3(NGn/4, 2), 128>>>(Wo1, bo1, Wo2, bo2, lng, lnb, i);
        k_reduce<<<NGn/4, 128>>>(Wred + (size_t)i*256*Hd, bred + i*Hd);
    }
    k_final<<<Gn, 128>>>(Wp1, bp1, Wp2, bp2, out);
    (void)in_sizes; (void)out_size;
}

// round 11
// speedup vs baseline: 1.2141x; 1.2141x over previous
#include <cuda_runtime.h>
#include <cuda_bf16.h>
#include <math.h>
#include <stdint.h>

#define Gn  16
#define Nn  96
#define Hd  128
#define Ed  24576
#define NGn (Gn*Nn)   // 1536
#define MSZ (NGn*Hd)
#define EPZ (Ed*Hd)

typedef unsigned long long ull;

// ---------------- packed f32x2 helpers -------------------------------------
__device__ __forceinline__ ull pk1(float x) {
    ull r; asm("mov.b64 %0, {%1,%1};" : "=l"(r) : "f"(x)); return r;
}
__device__ __forceinline__ ull pk2(float x, float y) {
    ull r; asm("mov.b64 %0, {%1,%2};" : "=l"(r) : "f"(x), "f"(y)); return r;
}
__device__ __forceinline__ void ffma2(ull& d, ull a, ull b) {
    asm("fma.rn.f32x2 %0, %1, %2, %0;" : "+l"(d) : "l"(a), "l"(b));
}
__device__ __forceinline__ float2 unpk(ull v) {
    float2 f; asm("mov.b64 {%0,%1}, %2;" : "=f"(f.x), "=f"(f.y) : "l"(v)); return f;
}

// ---------------- bf16 split helpers ---------------------------------------
__device__ __forceinline__ uint32_t pkbf(float lo, float hi) {
    uint32_t r; asm("cvt.rn.bf16x2.f32 %0, %1, %2;" : "=r"(r) : "f"(hi), "f"(lo)); return r;
}
__device__ __forceinline__ void split_store(char* hiT, char* loT, uint32_t off,
                                            float f0, float f1) {
    uint32_t h = pkbf(f0, f1);
    float h0 = __uint_as_float(h << 16);
    float h1 = __uint_as_float(h & 0xffff0000u);
    uint32_t l = pkbf(f0 - h0, f1 - h1);
    *(uint32_t*)(hiT + off) = h;
    *(uint32_t*)(loT + off) = l;
}

// HMMA m16n8k16 bf16 -> f32 accumulate (arch-agnostic PTX, sm_80+)
__device__ __forceinline__ void mma16816(float* d, const uint32_t* a, const uint32_t* b) {
    asm volatile(
        "mma.sync.aligned.m16n8k16.row.col.f32.bf16.bf16.f32 "
        "{%0,%1,%2,%3}, {%4,%5,%6,%7}, {%8,%9}, {%0,%1,%2,%3};"
        : "+f"(d[0]), "+f"(d[1]), "+f"(d[2]), "+f"(d[3])
        : "r"(a[0]), "r"(a[1]), "r"(a[2]), "r"(a[3]), "r"(b[0]), "r"(b[1]));
}

// ---------------- scratch ---------------------------------------------------
#define ARS  272              // tile row stride in bytes (136 bf16)
#define TILE_B 34816          // 128 rows * 272 B
#define WSET_B (4*TILE_B)     // W1H,W1L,W2H,W2L contiguous = 139264 B

__device__ __align__(16) float g_node[MSZ];
__device__ __align__(16) float g_hidden[MSZ];
__device__ __align__(16) float g_edgefts[EPZ];
__device__ __align__(16) float g_edgeproj[2*EPZ];     // per-stream, per-layer (L2-hot)
__device__              int   g_eidx[Gn*Nn*Nn];
__device__ __align__(16) float g_msg1[2*MSZ];         // per-stream
__device__ __align__(16) float g_msg2[2*MSZ];         // per-stream
__device__ __align__(16) float g_maxmsg[2*MSZ];       // per-stream
__device__ __align__(16) float g_out0[MSZ];
__device__ __align__(16) float g_out1[MSZ];
__device__ __align__(16) char  g_wt[6*WSET_B];        // pre-split MLP weight tiles
__device__ __align__(16) char  g_wtme[6*2*TILE_B];    // pre-split W_me tiles

extern __shared__ char dyn_smem[];

// ---------------- encoders --------------------------------------------------
__global__ void k_encode_nodes(const int* __restrict__ x,
                               const float* __restrict__ atom) {
    int n = blockIdx.x, h = threadIdx.x;
    float s = 0.f;
#pragma unroll
    for (int c = 0; c < 9; c++) {
        int id = x[n*9 + c];
        s += atom[(c*119 + id)*Hd + h];
    }
    g_node[n*Hd + h]   = s;
    g_hidden[n*Hd + h] = 0.f;
}

__global__ void k_encode_edges(const int* __restrict__ ea,
                               const float* __restrict__ bond) {
    int e = blockIdx.x, h = threadIdx.x;
    float s = 0.f;
#pragma unroll
    for (int c = 0; c < 3; c++) {
        int id = ea[e*3 + c];
        s += bond[(c*6 + id)*Hd + h];
    }
    g_edgefts[e*Hd + h] = s;
}

__global__ void k_init_eidx() {
    int i = blockIdx.x*blockDim.x + threadIdx.x;
    if (i < Gn*Nn*Nn) g_eidx[i] = -1;
}

__global__ void k_scatter(const int* __restrict__ src, const int* __restrict__ dst) {
    int e = blockIdx.x*blockDim.x + threadIdx.x;
    if (e >= Ed) return;
    int s = src[e], d = dst[e];
    int g  = s / Nn;
    int li = s % Nn;
    int lj = d % Nn;
    atomicMax(&g_eidx[(g*Nn + li)*Nn + lj], e);
}

// ---------------- one-time weight prep (W1, W2, Wme) -----------------------
__global__ void k_prepw(const float* __restrict__ Wl1, const float* __restrict__ Wl2,
                        const float* __restrict__ Wmeg) {
    int ls = blockIdx.y;
    const float* W1 = Wl1 + (size_t)ls*Hd*Hd;
    const float* W2 = Wl2 + (size_t)ls*Hd*Hd;
    const float* We = Wmeg + (size_t)ls*Hd*Hd;
    char* base  = g_wt + (size_t)ls*WSET_B;
    char* baseE = g_wtme + (size_t)ls*2*TILE_B;
    int n0 = blockIdx.x*8;
    for (int p = threadIdx.x; p < 8*64; p += 256) {
        int nl = p >> 6, k = (p & 63)*2;
        int n = n0 + nl;
        uint32_t off = (uint32_t)(n*ARS + k*2);
        split_store(base,            base + TILE_B,   off, W1[k*Hd + n], W1[(k+1)*Hd + n]);
        split_store(base + 2*TILE_B, base + 3*TILE_B, off, W2[k*Hd + n], W2[(k+1)*Hd + n]);
        split_store(baseE,           baseE + TILE_B,  off, We[k*Hd + n], We[(k+1)*Hd + n]);
    }
}

// ---------------- msg1/msg2 (ffma2), gridDim.y = stream --------------------
__global__ void k_msg12(const float* __restrict__ Wm1, const float* __restrict__ bm1g,
                        const float* __restrict__ Wm2, const float* __restrict__ bm2g,
                        const float* __restrict__ bmeg, const float* __restrict__ bmgg,
                        int layer) {
    int s = blockIdx.y, ls = layer*2 + s;
    const float* W1 = Wm1 + (size_t)ls*256*Hd;
    const float* W2 = Wm2 + (size_t)ls*256*Hd;
    __shared__ float zS[256*8];
    int tid = threadIdx.x, n0 = blockIdx.x*8;
    for (int idx = tid; idx < 8*256; idx += 128) {
        int nn = idx >> 8, k = idx & 255;
        int n = n0 + nn;
        float v = (k < Hd) ? g_node[n*Hd + k] : g_hidden[n*Hd + (k - Hd)];
        zS[k*8 + nn] = v;
    }
    __syncthreads();
    int h = tid;
    ull a1[4], a2[4];
#pragma unroll
    for (int p = 0; p < 4; p++) { a1[p] = 0ull; a2[p] = 0ull; }
    for (int k = 0; k < 256; k++) {
        ull w1 = pk1(W1[k*Hd + h]);
        ull w2 = pk1(W2[k*Hd + h]);
        const float2* zr = (const float2*)(zS + k*8);
#pragma unroll
        for (int p = 0; p < 4; p++) {
            float2 z = zr[p];
            ull zp = pk2(z.x, z.y);
            ffma2(a1[p], zp, w1);
            ffma2(a2[p], zp, w2);
        }
    }
    float bb1 = bm1g[ls*Hd + h] + bmeg[ls*Hd + h] + bmgg[ls*Hd + h];
    float bb2 = bm2g[ls*Hd + h];
    float* m1 = g_msg1 + (size_t)s*MSZ;
    float* m2 = g_msg2 + (size_t)s*MSZ;
#pragma unroll
    for (int p = 0; p < 4; p++) {
        float2 v1 = unpk(a1[p]), v2 = unpk(a2[p]);
        m1[(n0+2*p+0)*Hd + h] = v1.x + bb1;
        m1[(n0+2*p+1)*Hd + h] = v1.y + bb1;
        m2[(n0+2*p+0)*Hd + h] = v2.x + bb2;
        m2[(n0+2*p+1)*Hd + h] = v2.y + bb2;
    }
}

// ---------------- edge projection (HMMA, per-layer, gridDim.y = stream) ----
#define EO_AHI 0
#define EO_ALO TILE_B
#define EO_WH  (2*TILE_B)
#define EO_WL  (3*TILE_B)
#define SMEM_EP (4*TILE_B)

__global__ void __launch_bounds__(256, 1) k_edgeproj_mma(int layer) {
    char* sh = dyn_smem;
    const int tid = threadIdx.x, w = tid >> 5, lane = tid & 31;
    const int gq = lane >> 2, t = lane & 3;
    const int rg = w >> 1, cg = w & 1;       // 4x2 warp grid
    const int R0 = rg*32, C0 = cg*64;
    const int s = blockIdx.y, ls = layer*2 + s;
    const int e0 = blockIdx.x*128;

    // W tiles (pre-split, contiguous)
    {
        const uint4* src = (const uint4*)(g_wtme + (size_t)ls*2*TILE_B);
        uint4* dst = (uint4*)(sh + EO_WH);
        for (int p = tid; p < 2*TILE_B/16; p += 256) dst[p] = src[p];
    }
    // stage A: edgefts rows e0..e0+127, split hi/lo
    for (int p = tid; p < 128*64; p += 256) {
        int r = p >> 6, c = (p & 63)*2;
        float2 a = *(const float2*)(g_edgefts + (size_t)(e0 + r)*Hd + c);
        split_store(sh + EO_AHI, sh + EO_ALO, (uint32_t)(r*ARS + c*2), a.x, a.y);
    }
    __syncthreads();

    float acc[2][8][4];
#pragma unroll
    for (int mi = 0; mi < 2; mi++)
#pragma unroll
        for (int ni = 0; ni < 8; ni++)
#pragma unroll
            for (int q = 0; q < 4; q++) acc[mi][ni][q] = 0.f;

#pragma unroll
    for (int ks = 0; ks < 8; ks++) {
        int kb = (ks*16 + t*2)*2;
        uint32_t afh[2][4], afl[2][4];
#pragma unroll
        for (int mi = 0; mi < 2; mi++) {
            int r = R0 + mi*16 + gq;
            afh[mi][0] = *(const uint32_t*)(sh + EO_AHI + r*ARS + kb);
            afh[mi][1] = *(const uint32_t*)(sh + EO_AHI + (r+8)*ARS + kb);
            afh[mi][2] = *(const uint32_t*)(sh + EO_AHI + r*ARS + kb + 16);
            afh[mi][3] = *(const uint32_t*)(sh + EO_AHI + (r+8)*ARS + kb + 16);
            afl[mi][0] = *(const uint32_t*)(sh + EO_ALO + r*ARS + kb);
            afl[mi][1] = *(const uint32_t*)(sh + EO_ALO + (r+8)*ARS + kb);
            afl[mi][2] = *(const uint32_t*)(sh + EO_ALO + r*ARS + kb + 16);
            afl[mi][3] = *(const uint32_t*)(sh + EO_ALO + (r+8)*ARS + kb + 16);
        }
        uint32_t bfh[8][2], bfl[8][2];
#pragma unroll
        for (int ni = 0; ni < 8; ni++) {
            int n = C0 + ni*8 + gq;
            bfh[ni][0] = *(const uint32_t*)(sh + EO_WH + n*ARS + kb);
            bfh[ni][1] = *(const uint32_t*)(sh + EO_WH + n*ARS + kb + 16);
            bfl[ni][0] = *(const uint32_t*)(sh + EO_WL + n*ARS + kb);
            bfl[ni][1] = *(const uint32_t*)(sh + EO_WL + n*ARS + kb + 16);
        }
#pragma unroll
        for (int mi = 0; mi < 2; mi++)
#pragma unroll
            for (int ni = 0; ni < 8; ni++) {
                mma16816(acc[mi][ni], afh[mi], bfh[ni]);
                mma16816(acc[mi][ni], afh[mi], bfl[ni]);
                mma16816(acc[mi][ni], afl[mi], bfh[ni]);
            }
    }

    float* ep = g_edgeproj + (size_t)s*EPZ;
#pragma unroll
    for (int mi = 0; mi < 2; mi++)
#pragma unroll
        for (int ni = 0; ni < 8; ni++) {
            int r = R0 + mi*16 + gq, c = C0 + ni*8 + t*2;
            *(float2*)(ep + (size_t)(e0 + r)*Hd + c) =
                make_float2(acc[mi][ni][0], acc[mi][ni][1]);
            *(float2*)(ep + (size_t)(e0 + r + 8)*Hd + c) =
                make_float2(acc[mi][ni][2], acc[mi][ni][3]);
        }
}

// ---------------- fused message MLP + max (persistent HMMA) ----------------
#define O_AHI  0
#define O_ALO  26112
#define O_W1H  52224
#define O_W1L  (O_W1H + TILE_B)
#define O_W2H  (O_W1H + 2*TILE_B)
#define O_W2L  (O_W1H + 3*TILE_B)
#define O_B1   191488
#define O_M1   192000
#define O_EIX  192512
#define O_MAXR 192896
#define O_B2   193920
#define SMEM_FUSED 194432

__global__ void __launch_bounds__(256, 1)
k_fused_mma(int layer, const float* __restrict__ bl1, const float* __restrict__ bl2) {
    char* sh = dyn_smem;
    const int tid = threadIdx.x, w = tid >> 5, lane = tid & 31;
    const int gq = lane >> 2, t = lane & 3;
    const int rg = w >> 2, cg = w & 3;
    const int R0 = rg*48, C0 = cg*32;

    float* b1s  = (float*)(sh + O_B1);
    float* b2s  = (float*)(sh + O_B2);
    float* m1S  = (float*)(sh + O_M1);
    int*   eixS = (int*)(sh + O_EIX);
    float* maxr = (float*)(sh + O_MAXR);

    int cur_s = -1;
    for (int tt = blockIdx.x; tt < 2*NGn; tt += gridDim.x) {
        const int s  = (tt >= NGn) ? 1 : 0;
        const int lt = tt - s*NGn;
        const int g  = lt / Nn, j = lt - g*Nn;
        const int ls = layer*2 + s;

        if (s != cur_s) {
            const uint4* src = (const uint4*)(g_wt + (size_t)ls*WSET_B);
            uint4* dst = (uint4*)(sh + O_W1H);
            for (int p = tid; p < WSET_B/16; p += 256) dst[p] = src[p];
            if (tid < Hd) b1s[tid] = bl1[ls*Hd + tid];
            else          b2s[tid - 128] = bl2[ls*Hd + (tid - 128)];
            cur_s = s;
        }

        const float* msg1  = g_msg1 + (size_t)s*MSZ;
        const float* msg2  = g_msg2 + (size_t)s*MSZ;
        const float* eproj = g_edgeproj + (size_t)s*EPZ;
        float* mmout = g_maxmsg + (size_t)s*MSZ;

        if (tid < Hd)       m1S[tid] = msg1[(g*Nn + j)*Hd + tid];
        else if (tid < 224) eixS[tid - 128] = g_eidx[(g*Nn + (tid - 128))*Nn + j];
        __syncthreads();

        for (int p = tid; p < Nn*64; p += 256) {
            int r = p >> 6, c = (p & 63)*2;
            float2 m2 = *(const float2*)(msg2 + (size_t)(g*Nn + r)*Hd + c);
            float f0 = m1S[c] + m2.x, f1 = m1S[c+1] + m2.y;
            int e = eixS[r];
            if (e >= 0) {
                float2 ep = *(const float2*)(eproj + (size_t)e*Hd + c);
                f0 += ep.x; f1 += ep.y;
            }
            f0 = fmaxf(f0, 0.f); f1 = fmaxf(f1, 0.f);
            split_store(sh + O_AHI, sh + O_ALO, (uint32_t)(r*ARS + c*2), f0, f1);
        }
        __syncthreads();

        float acc[3][4][4];
#pragma unroll
        for (int mi = 0; mi < 3; mi++)
#pragma unroll
            for (int ni = 0; ni < 4; ni++)
#pragma unroll
                for (int q = 0; q < 4; q++) acc[mi][ni][q] = 0.f;

        // ---- GEMM1 ----
#pragma unroll
        for (int ks = 0; ks < 8; ks++) {
            int kb = (ks*16 + t*2)*2;
            uint32_t afh[3][4], afl[3][4];
#pragma unroll
            for (int mi = 0; mi < 3; mi++) {
                int r = R0 + mi*16 + gq;
                afh[mi][0] = *(const uint32_t*)(sh + O_AHI + r*ARS + kb);
                afh[mi][1] = *(const uint32_t*)(sh + O_AHI + (r+8)*ARS + kb);
                afh[mi][2] = *(const uint32_t*)(sh + O_AHI + r*ARS + kb + 16);
                afh[mi][3] = *(const uint32_t*)(sh + O_AHI + (r+8)*ARS + kb + 16);
                afl[mi][0] = *(const uint32_t*)(sh + O_ALO + r*ARS + kb);
                afl[mi][1] = *(const uint32_t*)(sh + O_ALO + (r+8)*ARS + kb);
                afl[mi][2] = *(const uint32_t*)(sh + O_ALO + r*ARS + kb + 16);
                afl[mi][3] = *(const uint32_t*)(sh + O_ALO + (r+8)*ARS + kb + 16);
            }
            uint32_t bfh[4][2], bfl[4][2];
#pragma unroll
            for (int ni = 0; ni < 4; ni++) {
                int n = C0 + ni*8 + gq;
                bfh[ni][0] = *(const uint32_t*)(sh + O_W1H + n*ARS + kb);
                bfh[ni][1] = *(const uint32_t*)(sh + O_W1H + n*ARS + kb + 16);
                bfl[ni][0] = *(const uint32_t*)(sh + O_W1L + n*ARS + kb);
                bfl[ni][1] = *(const uint32_t*)(sh + O_W1L + n*ARS + kb + 16);
            }
#pragma unroll
            for (int mi = 0; mi < 3; mi++)
#pragma unroll
                for (int ni = 0; ni < 4; ni++) {
                    mma16816(acc[mi][ni], afh[mi], bfh[ni]);
                    mma16816(acc[mi][ni], afh[mi], bfl[ni]);
                    mma16816(acc[mi][ni], afl[mi], bfh[ni]);
                }
        }

        // ---- epilogue1 ----
        __syncthreads();
#pragma unroll
        for (int mi = 0; mi < 3; mi++) {
#pragma unroll
            for (int ni = 0; ni < 4; ni++) {
                int r = R0 + mi*16 + gq, c = C0 + ni*8 + t*2;
                float f0 = fmaxf(acc[mi][ni][0] + b1s[c],   0.f);
                float f1 = fmaxf(acc[mi][ni][1] + b1s[c+1], 0.f);
                split_store(sh + O_AHI, sh + O_ALO, (uint32_t)(r*ARS + c*2), f0, f1);
                float f2 = fmaxf(acc[mi][ni][2] + b1s[c],   0.f);
                float f3 = fmaxf(acc[mi][ni][3] + b1s[c+1], 0.f);
                split_store(sh + O_AHI, sh + O_ALO, (uint32_t)((r+8)*ARS + c*2), f2, f3);
            }
        }
        __syncthreads();

#pragma unroll
        for (int mi = 0; mi < 3; mi++)
#pragma unroll
            for (int ni = 0; ni < 4; ni++)
#pragma unroll
                for (int q = 0; q < 4; q++) acc[mi][ni][q] = 0.f;

        // ---- GEMM2 ----
#pragma unroll
        for (int ks = 0; ks < 8; ks++) {
            int kb = (ks*16 + t*2)*2;
            uint32_t afh[3][4], afl[3][4];
#pragma unroll
            for (int mi = 0; mi < 3; mi++) {
                int r = R0 + mi*16 + gq;
                afh[mi][0] = *(const uint32_t*)(sh + O_AHI + r*ARS + kb);
                afh[mi][1] = *(const uint32_t*)(sh + O_AHI + (r+8)*ARS + kb);
                afh[mi][2] = *(const uint32_t*)(sh + O_AHI + r*ARS + kb + 16);
                afh[mi][3] = *(const uint32_t*)(sh + O_AHI + (r+8)*ARS + kb + 16);
                afl[mi][0] = *(const uint32_t*)(sh + O_ALO + r*ARS + kb);
                afl[mi][1] = *(const uint32_t*)(sh + O_ALO + (r+8)*ARS + kb);
                afl[mi][2] = *(const uint32_t*)(sh + O_ALO + r*ARS + kb + 16);
                afl[mi][3] = *(const uint32_t*)(sh + O_ALO + (r+8)*ARS + kb + 16);
            }
            uint32_t bfh[4][2], bfl[4][2];
#pragma unroll
            for (int ni = 0; ni < 4; ni++) {
                int n = C0 + ni*8 + gq;
                bfh[ni][0] = *(const uint32_t*)(sh + O_W2H + n*ARS + kb);
                bfh[ni][1] = *(const uint32_t*)(sh + O_W2H + n*ARS + kb + 16);
                bfl[ni][0] = *(const uint32_t*)(sh + O_W2L + n*ARS + kb);
                bfl[ni][1] = *(const uint32_t*)(sh + O_W2L + n*ARS + kb + 16);
            }
#pragma unroll
            for (int mi = 0; mi < 3; mi++)
#pragma unroll
                for (int ni = 0; ni < 4; ni++) {
                    mma16816(acc[mi][ni], afh[mi], bfh[ni]);
                    mma16816(acc[mi][ni], afh[mi], bfl[ni]);
                    mma16816(acc[mi][ni], afl[mi], bfh[ni]);
                }
        }

        // ---- max over senders ----
#pragma unroll
        for (int ni = 0; ni < 4; ni++) {
            float v0 = fmaxf(acc[0][ni][0], acc[0][ni][2]);
            float v1 = fmaxf(acc[0][ni][1], acc[0][ni][3]);
#pragma unroll
            for (int mi = 1; mi < 3; mi++) {
                v0 = fmaxf(v0, fmaxf(acc[mi][ni][0], acc[mi][ni][2]));
                v1 = fmaxf(v1, fmaxf(acc[mi][ni][1], acc[mi][ni][3]));
            }
#pragma unroll
            for (int st = 4; st < 32; st <<= 1) {
                v0 = fmaxf(v0, __shfl_xor_sync(0xffffffffu, v0, st));
                v1 = fmaxf(v1, __shfl_xor_sync(0xffffffffu, v1, st));
            }
            if (gq == 0) {
                maxr[rg*128 + C0 + ni*8 + t*2]     = v0;
                maxr[rg*128 + C0 + ni*8 + t*2 + 1] = v1;
            }
        }
        __syncthreads();
        if (tid < Hd)
            mmout[(g*Nn + j)*Hd + tid] =
                fmaxf(maxr[tid], maxr[128 + tid]) + b2s[tid];
        __syncthreads();
    }
}

// ---------------- out + layernorm, gridDim.y = stream ----------------------
__device__ __forceinline__ float blk_sum128(float v, volatile float* red) {
    int tid = threadIdx.x;
#pragma unroll
    for (int o = 16; o; o >>= 1) v += __shfl_xor_sync(0xffffffffu, v, o);
    if ((tid & 31) == 0) red[tid >> 5] = v;
    __syncthreads();
    float t = red[0] + red[1] + red[2] + red[3];
    __syncthreads();
    return t;
}

__global__ void k_outln(const float* __restrict__ Wo1g, const float* __restrict__ bo1g,
                        const float* __restrict__ Wo2g, const float* __restrict__ bo2g,
                        const float* __restrict__ lgg,  const float* __restrict__ lbg,
                        int layer) {
    int s = blockIdx.y, ls = layer*2 + s;
    const float* Wo1 = Wo1g + (size_t)ls*256*Hd;
    const float* Wo2 = Wo2g + (size_t)ls*Hd*Hd;
    __shared__ float zS[4*256];
    __shared__ float mmS[4*128];
    __shared__ float red[4];
    int tid = threadIdx.x, n0 = blockIdx.x*4;
    const float* mm = g_maxmsg + (size_t)s*MSZ;
    for (int idx = tid; idx < 1024; idx += 128) {
        int nn = idx >> 8, k = idx & 255;
        zS[idx] = (k < Hd) ? g_node[(n0+nn)*Hd + k] : g_hidden[(n0+nn)*Hd + (k - Hd)];
    }
    for (int idx = tid; idx < 512; idx += 128) {
        int nn = idx >> 7, k = idx & 127;
        mmS[idx] = mm[(n0+nn)*Hd + k];
    }
    __syncthreads();
    int h = tid;
    float acc[4];
    float bb = bo1g[ls*Hd + h] + bo2g[ls*Hd + h];
#pragma unroll
    for (int nn = 0; nn < 4; nn++) acc[nn] = bb;
    for (int k = 0; k < 256; k++) {
        float w = Wo1[k*Hd + h];
#pragma unroll
        for (int nn = 0; nn < 4; nn++) acc[nn] += zS[nn*256 + k]*w;
    }
    for (int k = 0; k < 128; k++) {
        float w = Wo2[k*Hd + h];
#pragma unroll
        for (int nn = 0; nn < 4; nn++) acc[nn] += mmS[nn*128 + k]*w;
    }
    float lgv = lgg[ls*Hd + h], lbv = lbg[ls*Hd + h];
    float* ob = s ? g_out1 : g_out0;
    for (int nn = 0; nn < 4; nn++) {
        float v = fmaxf(acc[nn], 0.f);
        float mu = blk_sum128(v, red) * (1.f/128.f);
        float d = v - mu;
        float var = blk_sum128(d*d, red) * (1.f/128.f);
        float rstd = rsqrtf(var + 1e-5f);
        ob[(n0+nn)*Hd + h] = d*rstd*lgv + lbv;
    }
}

// ---------------- hidden = concat(out0,out1) @ W_red + b_red ---------------
__global__ void k_reduce(const float* __restrict__ Wred, const float* __restrict__ bred) {
    __shared__ float zz[4*256];
    int tid = threadIdx.x, n0 = blockIdx.x*4;
    for (int idx = tid; idx < 1024; idx += 128) {
        int nn = idx >> 8, k = idx & 255;
        zz[idx] = (k < Hd) ? g_out0[(n0+nn)*Hd + k] : g_out1[(n0+nn)*Hd + (k - Hd)];
    }
    __syncthreads();
    int h = tid;
    float acc[4];
    float bb = bred[h];
#pragma unroll
    for (int nn = 0; nn < 4; nn++) acc[nn] = bb;
    for (int k = 0; k < 256; k++) {
        float w = Wred[k*Hd + h];
#pragma unroll
        for (int nn = 0; nn < 4; nn++) acc[nn] += zz[nn*256 + k]*w;
    }
#pragma unroll
    for (int nn = 0; nn < 4; nn++) g_hidden[(n0+nn)*Hd + h] = acc[nn];
}

// ---------------- readout --------------------------------------------------
__global__ void k_final(const float* __restrict__ Wp1, const float* __restrict__ bp1,
                        const float* __restrict__ Wp2, const float* __restrict__ bp2,
                        float* __restrict__ out) {
    __shared__ float embS[128], h1S[128], red[4];
    int g = blockIdx.x, h = threadIdx.x;
    float s = 0.f;
    for (int n = 0; n < Nn; n++) s += g_hidden[(g*Nn + n)*Hd + h];
    embS[h] = s * (1.f/96.f);
    __syncthreads();
    float a = bp1[h];
    for (int k = 0; k < 128; k++) a += embS[k]*Wp1[k*Hd + h];
    h1S[h] = fmaxf(a, 0.f);
    __syncthreads();
    float v = h1S[h] * Wp2[h];
    float tot = blk_sum128(v, red);
    if (h == 0) out[g] = tot + bp2[0];
}

// ---------------- launch ---------------------------------------------------
extern "C" void kernel_launch(void* const* d_in, const int* in_sizes, int n_in,
                              void* d_out, int out_size) {
    int o = (n_in >= 32) ? 6 : 4;
    const int*   x    = (const int*)d_in[0];
    const int*   ea   = (const int*)d_in[1];
    const int*   src  = (const int*)d_in[2];
    const int*   dst  = (const int*)d_in[3];
    const float* atom = (const float*)d_in[o+0];
    const float* bond = (const float*)d_in[o+1];
    const float* Wm1  = (const float*)d_in[o+2];
    const float* bm1  = (const float*)d_in[o+3];
    const float* Wm2  = (const float*)d_in[o+4];
    const float* bm2  = (const float*)d_in[o+5];
    const float* Wme  = (const float*)d_in[o+6];
    const float* bme  = (const float*)d_in[o+7];
    const float* bmg  = (const float*)d_in[o+9];   // W_mg unused (graph_fts == 0)
    const float* Wl1  = (const float*)d_in[o+10];
    const float* bl1  = (const float*)d_in[o+11];
    const float* Wl2  = (const float*)d_in[o+12];
    const float* bl2  = (const float*)d_in[o+13];
    const float* Wo1  = (const float*)d_in[o+14];
    const float* bo1  = (const float*)d_in[o+15];
    const float* Wo2  = (const float*)d_in[o+16];
    const float* bo2  = (const float*)d_in[o+17];
    const float* lng  = (const float*)d_in[o+18];
    const float* lnb  = (const float*)d_in[o+19];
    const float* Wred = (const float*)d_in[o+20];
    const float* bred = (const float*)d_in[o+21];
    const float* Wp1  = (const float*)d_in[o+22];
    const float* bp1  = (const float*)d_in[o+23];
    const float* Wp2  = (const float*)d_in[o+24];
    const float* bp2  = (const float*)d_in[o+25];
    float* out = (float*)d_out;

    cudaFuncSetAttribute(k_fused_mma,    cudaFuncAttributeMaxDynamicSharedMemorySize, SMEM_FUSED);
    cudaFuncSetAttribute(k_edgeproj_mma, cudaFuncAttributeMaxDynamicSharedMemorySize, SMEM_EP);

    k_encode_nodes<<<NGn, 128>>>(x, atom);
    k_encode_edges<<<Ed, 128>>>(ea, bond);
    k_init_eidx<<<(Gn*Nn*Nn + 255)/256, 256>>>();
    k_scatter<<<(Ed + 255)/256, 256>>>(src, dst);
    k_prepw<<<dim3(16, 6), 256>>>(Wl1, Wl2, Wme);

    for (int i = 0; i < 3; i++) {
        k_msg12<<<dim3(NGn/8, 2), 128>>>(Wm1, bm1, Wm2, bm2, bme, bmg, i);
        k_edgeproj_mma<<<dim3(Ed/128, 2), 256, SMEM_EP>>>(i);
        k_fused_mma<<<148, 256, SMEM_FUSED>>>(i, bl1, bl2);
        k_outln<<<dim3(NGn/4, 2), 128>>>(Wo1, bo1, Wo2, bo2, lng, lnb, i);
        k_reduce<<<NGn/4, 128>>>(Wred + (size_t)i*256*Hd, bred + i*Hd);
    }
    k_final<<<Gn, 128>>>(Wp1, bp1, Wp2, bp2, out);
    (void)in_sizes; (void)out_size;
}

// round 12
// speedup vs baseline: 1.2234x; 1.0076x over previous
#include <cuda_runtime.h>
#include <cuda_bf16.h>
#include <math.h>
#include <stdint.h>

#define Gn  16
#define Nn  96
#define Hd  128
#define Ed  24576
#define NGn (Gn*Nn)   // 1536
#define MSZ (NGn*Hd)
#define EPZ (Ed*Hd)

typedef unsigned long long ull;

// ---------------- packed f32x2 helpers -------------------------------------
__device__ __forceinline__ ull pk1(float x) {
    ull r; asm("mov.b64 %0, {%1,%1};" : "=l"(r) : "f"(x)); return r;
}
__device__ __forceinline__ ull pk2(float x, float y) {
    ull r; asm("mov.b64 %0, {%1,%2};" : "=l"(r) : "f"(x), "f"(y)); return r;
}
__device__ __forceinline__ void ffma2(ull& d, ull a, ull b) {
    asm("fma.rn.f32x2 %0, %1, %2, %0;" : "+l"(d) : "l"(a), "l"(b));
}
__device__ __forceinline__ float2 unpk(ull v) {
    float2 f; asm("mov.b64 {%0,%1}, %2;" : "=f"(f.x), "=f"(f.y) : "l"(v)); return f;
}

// ---------------- misc helpers ---------------------------------------------
__device__ __forceinline__ uint32_t s2u(const void* p) {
    uint32_t a;
    asm("{ .reg .u64 t; cvta.to.shared.u64 t, %1; cvt.u32.u64 %0, t; }" : "=r"(a) : "l"(p));
    return a;
}
__device__ __forceinline__ uint32_t pkbf(float lo, float hi) {
    uint32_t r; asm("cvt.rn.bf16x2.f32 %0, %1, %2;" : "=r"(r) : "f"(hi), "f"(lo)); return r;
}
__device__ __forceinline__ void split_store(char* hiT, char* loT, uint32_t off,
                                            float f0, float f1) {
    uint32_t h = pkbf(f0, f1);
    float h0 = __uint_as_float(h << 16);
    float h1 = __uint_as_float(h & 0xffff0000u);
    uint32_t l = pkbf(f0 - h0, f1 - h1);
    *(uint32_t*)(hiT + off) = h;
    *(uint32_t*)(loT + off) = l;
}

// HMMA m16n8k16 bf16 -> f32 accumulate (arch-agnostic PTX, sm_80+)
__device__ __forceinline__ void mma16816(float* d, const uint32_t* a, const uint32_t* b) {
    asm volatile(
        "mma.sync.aligned.m16n8k16.row.col.f32.bf16.bf16.f32 "
        "{%0,%1,%2,%3}, {%4,%5,%6,%7}, {%8,%9}, {%0,%1,%2,%3};"
        : "+f"(d[0]), "+f"(d[1]), "+f"(d[2]), "+f"(d[3])
        : "r"(a[0]), "r"(a[1]), "r"(a[2]), "r"(a[3]), "r"(b[0]), "r"(b[1]));
}
// ldmatrix x4 (sm_75+, arch-agnostic)
__device__ __forceinline__ void ldsm4(uint32_t* r, uint32_t addr) {
    asm volatile("ldmatrix.sync.aligned.m8n8.x4.shared.b16 {%0,%1,%2,%3}, [%4];"
        : "=r"(r[0]), "=r"(r[1]), "=r"(r[2]), "=r"(r[3]) : "r"(addr));
}

// ---------------- scratch ---------------------------------------------------
#define ARS  272              // tile row stride in bytes (136 bf16)
#define TILE_B 34816          // 128 rows * 272 B
#define WSET_B (4*TILE_B)     // W1H,W1L,W2H,W2L contiguous = 139264 B

__device__ __align__(16) float g_node[MSZ];
__device__ __align__(16) float g_hidden[MSZ];
__device__ __align__(16) float g_edgefts[EPZ];
__device__ __align__(16) float g_edgeproj[2*EPZ];     // per-stream, per-layer (L2-hot)
__device__              int   g_eidx[Gn*Nn*Nn];
__device__ __align__(16) float g_msg1[2*MSZ];
__device__ __align__(16) float g_msg2[2*MSZ];
__device__ __align__(16) float g_maxmsg[2*MSZ];
__device__ __align__(16) float g_out0[MSZ];
__device__ __align__(16) float g_out1[MSZ];
__device__ __align__(16) char  g_wt[6*WSET_B];        // pre-split MLP weight tiles
__device__ __align__(16) char  g_wtme[6*2*TILE_B];    // pre-split W_me tiles

extern __shared__ char dyn_smem[];

// ---------------- encoders --------------------------------------------------
__global__ void k_encode_nodes(const int* __restrict__ x,
                               const float* __restrict__ atom) {
    int n = blockIdx.x, h = threadIdx.x;
    float s = 0.f;
#pragma unroll
    for (int c = 0; c < 9; c++) {
        int id = x[n*9 + c];
        s += atom[(c*119 + id)*Hd + h];
    }
    g_node[n*Hd + h]   = s;
    g_hidden[n*Hd + h] = 0.f;
}

__global__ void k_encode_edges(const int* __restrict__ ea,
                               const float* __restrict__ bond) {
    int e = blockIdx.x, h = threadIdx.x;
    float s = 0.f;
#pragma unroll
    for (int c = 0; c < 3; c++) {
        int id = ea[e*3 + c];
        s += bond[(c*6 + id)*Hd + h];
    }
    g_edgefts[e*Hd + h] = s;
}

__global__ void k_init_eidx() {
    int i = blockIdx.x*blockDim.x + threadIdx.x;
    if (i < Gn*Nn*Nn) g_eidx[i] = -1;
}

__global__ void k_scatter(const int* __restrict__ src, const int* __restrict__ dst) {
    int e = blockIdx.x*blockDim.x + threadIdx.x;
    if (e >= Ed) return;
    int s = src[e], d = dst[e];
    int g  = s / Nn;
    int li = s % Nn;
    int lj = d % Nn;
    atomicMax(&g_eidx[(g*Nn + li)*Nn + lj], e);
}

// ---------------- one-time weight prep (W1, W2, Wme) -----------------------
__global__ void k_prepw(const float* __restrict__ Wl1, const float* __restrict__ Wl2,
                        const float* __restrict__ Wmeg) {
    int ls = blockIdx.y;
    const float* W1 = Wl1 + (size_t)ls*Hd*Hd;
    const float* W2 = Wl2 + (size_t)ls*Hd*Hd;
    const float* We = Wmeg + (size_t)ls*Hd*Hd;
    char* base  = g_wt + (size_t)ls*WSET_B;
    char* baseE = g_wtme + (size_t)ls*2*TILE_B;
    int n0 = blockIdx.x*8;
    for (int p = threadIdx.x; p < 8*64; p += 256) {
        int nl = p >> 6, k = (p & 63)*2;
        int n = n0 + nl;
        uint32_t off = (uint32_t)(n*ARS + k*2);
        split_store(base,            base + TILE_B,   off, W1[k*Hd + n], W1[(k+1)*Hd + n]);
        split_store(base + 2*TILE_B, base + 3*TILE_B, off, W2[k*Hd + n], W2[(k+1)*Hd + n]);
        split_store(baseE,           baseE + TILE_B,  off, We[k*Hd + n], We[(k+1)*Hd + n]);
    }
}

// ---------------- msg1/msg2 (ffma2), gridDim.y = stream --------------------
__global__ void k_msg12(const float* __restrict__ Wm1, const float* __restrict__ bm1g,
                        const float* __restrict__ Wm2, const float* __restrict__ bm2g,
                        const float* __restrict__ bmeg, const float* __restrict__ bmgg,
                        int layer) {
    int s = blockIdx.y, ls = layer*2 + s;
    const float* W1 = Wm1 + (size_t)ls*256*Hd;
    const float* W2 = Wm2 + (size_t)ls*256*Hd;
    __shared__ float zS[256*8];
    int tid = threadIdx.x, n0 = blockIdx.x*8;
    for (int idx = tid; idx < 8*256; idx += 128) {
        int nn = idx >> 8, k = idx & 255;
        int n = n0 + nn;
        float v = (k < Hd) ? g_node[n*Hd + k] : g_hidden[n*Hd + (k - Hd)];
        zS[k*8 + nn] = v;
    }
    __syncthreads();
    int h = tid;
    ull a1[4], a2[4];
#pragma unroll
    for (int p = 0; p < 4; p++) { a1[p] = 0ull; a2[p] = 0ull; }
    for (int k = 0; k < 256; k++) {
        ull w1 = pk1(W1[k*Hd + h]);
        ull w2 = pk1(W2[k*Hd + h]);
        const float2* zr = (const float2*)(zS + k*8);
#pragma unroll
        for (int p = 0; p < 4; p++) {
            float2 z = zr[p];
            ull zp = pk2(z.x, z.y);
            ffma2(a1[p], zp, w1);
            ffma2(a2[p], zp, w2);
        }
    }
    float bb1 = bm1g[ls*Hd + h] + bmeg[ls*Hd + h] + bmgg[ls*Hd + h];
    float bb2 = bm2g[ls*Hd + h];
    float* m1 = g_msg1 + (size_t)s*MSZ;
    float* m2 = g_msg2 + (size_t)s*MSZ;
#pragma unroll
    for (int p = 0; p < 4; p++) {
        float2 v1 = unpk(a1[p]), v2 = unpk(a2[p]);
        m1[(n0+2*p+0)*Hd + h] = v1.x + bb1;
        m1[(n0+2*p+1)*Hd + h] = v1.y + bb1;
        m2[(n0+2*p+0)*Hd + h] = v2.x + bb2;
        m2[(n0+2*p+1)*Hd + h] = v2.y + bb2;
    }
}

// ---------------- edge projection (HMMA + ldmatrix) ------------------------
#define EO_AHI 0
#define EO_ALO TILE_B
#define EO_WH  (2*TILE_B)
#define EO_WL  (3*TILE_B)
#define SMEM_EP (4*TILE_B)

__global__ void __launch_bounds__(256, 1) k_edgeproj_mma(int layer) {
    char* sh = dyn_smem;
    const uint32_t sb = s2u(sh);
    const int tid = threadIdx.x, w = tid >> 5, lane = tid & 31;
    const int gq = lane >> 2, t = lane & 3;
    const int rg = w >> 1, cg = w & 1;       // 4x2 warp grid
    const int R0 = rg*32, C0 = cg*64;
    const int s = blockIdx.y, ls = layer*2 + s;
    const int e0 = blockIdx.x*128;

    // ldmatrix per-lane offsets
    const uint32_t aoff = (uint32_t)(((lane & 7) + ((lane >> 3) & 1)*8)*ARS
                                     + ((lane >> 4) & 1)*16);
    const uint32_t boff = (uint32_t)((((lane >> 4) & 1)*8 + (lane & 7))*ARS
                                     + ((lane >> 3) & 1)*16);

    {
        const uint4* src = (const uint4*)(g_wtme + (size_t)ls*2*TILE_B);
        uint4* dst = (uint4*)(sh + EO_WH);
        for (int p = tid; p < 2*TILE_B/16; p += 256) dst[p] = src[p];
    }
    for (int p = tid; p < 128*64; p += 256) {
        int r = p >> 6, c = (p & 63)*2;
        float2 a = *(const float2*)(g_edgefts + (size_t)(e0 + r)*Hd + c);
        split_store(sh + EO_AHI, sh + EO_ALO, (uint32_t)(r*ARS + c*2), a.x, a.y);
    }
    __syncthreads();

    float acc[2][8][4];
#pragma unroll
    for (int mi = 0; mi < 2; mi++)
#pragma unroll
        for (int ni = 0; ni < 8; ni++)
#pragma unroll
            for (int q = 0; q < 4; q++) acc[mi][ni][q] = 0.f;

#pragma unroll
    for (int ks = 0; ks < 8; ks++) {
        uint32_t kbase = ks*32;
        uint32_t afh[2][4], afl[2][4], bh[4][4], bl2[4][4];
#pragma unroll
        for (int mi = 0; mi < 2; mi++) {
            uint32_t ro = (uint32_t)((R0 + mi*16)*ARS) + kbase + aoff;
            ldsm4(afh[mi], sb + EO_AHI + ro);
            ldsm4(afl[mi], sb + EO_ALO + ro);
        }
#pragma unroll
        for (int p = 0; p < 4; p++) {
            uint32_t no = (uint32_t)((C0 + p*16)*ARS) + kbase + boff;
            ldsm4(bh[p],  sb + EO_WH + no);
            ldsm4(bl2[p], sb + EO_WL + no);
        }
#pragma unroll
        for (int mi = 0; mi < 2; mi++)
#pragma unroll
            for (int p = 0; p < 4; p++)
#pragma unroll
                for (int hh = 0; hh < 2; hh++) {
                    int ni = p*2 + hh;
                    mma16816(acc[mi][ni], afh[mi], &bh[p][hh*2]);
                    mma16816(acc[mi][ni], afh[mi], &bl2[p][hh*2]);
                    mma16816(acc[mi][ni], afl[mi], &bh[p][hh*2]);
                }
    }

    float* ep = g_edgeproj + (size_t)s*EPZ;
#pragma unroll
    for (int mi = 0; mi < 2; mi++)
#pragma unroll
        for (int ni = 0; ni < 8; ni++) {
            int r = R0 + mi*16 + gq, c = C0 + ni*8 + t*2;
            *(float2*)(ep + (size_t)(e0 + r)*Hd + c) =
                make_float2(acc[mi][ni][0], acc[mi][ni][1]);
            *(float2*)(ep + (size_t)(e0 + r + 8)*Hd + c) =
                make_float2(acc[mi][ni][2], acc[mi][ni][3]);
        }
}

// ---------------- fused message MLP + max (persistent HMMA + ldmatrix) -----
#define O_AHI  0
#define O_ALO  26112
#define O_W1H  52224
#define O_W1L  (O_W1H + TILE_B)
#define O_W2H  (O_W1H + 2*TILE_B)
#define O_W2L  (O_W1H + 3*TILE_B)
#define O_B1   191488
#define O_M1   192000
#define O_EIX  192512
#define O_MAXR 192896
#define O_B2   193920
#define SMEM_FUSED 194432

__global__ void __launch_bounds__(256, 1)
k_fused_mma(int layer, const float* __restrict__ bl1, const float* __restrict__ bl2) {
    char* sh = dyn_smem;
    const uint32_t sb = s2u(sh);
    const int tid = threadIdx.x, w = tid >> 5, lane = tid & 31;
    const int gq = lane >> 2, t = lane & 3;
    const int rg = w >> 2, cg = w & 3;
    const int R0 = rg*48, C0 = cg*32;

    const uint32_t aoff = (uint32_t)(((lane & 7) + ((lane >> 3) & 1)*8)*ARS
                                     + ((lane >> 4) & 1)*16);
    const uint32_t boff = (uint32_t)((((lane >> 4) & 1)*8 + (lane & 7))*ARS
                                     + ((lane >> 3) & 1)*16);

    float* b1s  = (float*)(sh + O_B1);
    float* b2s  = (float*)(sh + O_B2);
    float* m1S  = (float*)(sh + O_M1);
    int*   eixS = (int*)(sh + O_EIX);
    float* maxr = (float*)(sh + O_MAXR);

    int cur_s = -1;
    for (int tt = blockIdx.x; tt < 2*NGn; tt += gridDim.x) {
        const int s  = (tt >= NGn) ? 1 : 0;
        const int lt = tt - s*NGn;
        const int g  = lt / Nn, j = lt - g*Nn;
        const int ls = layer*2 + s;

        if (s != cur_s) {
            const uint4* src = (const uint4*)(g_wt + (size_t)ls*WSET_B);
            uint4* dst = (uint4*)(sh + O_W1H);
            for (int p = tid; p < WSET_B/16; p += 256) dst[p] = src[p];
            if (tid < Hd) b1s[tid] = bl1[ls*Hd + tid];
            else          b2s[tid - 128] = bl2[ls*Hd + (tid - 128)];
            cur_s = s;
        }

        const float* msg1  = g_msg1 + (size_t)s*MSZ;
        const float* msg2  = g_msg2 + (size_t)s*MSZ;
        const float* eproj = g_edgeproj + (size_t)s*EPZ;
        float* mmout = g_maxmsg + (size_t)s*MSZ;

        if (tid < Hd)       m1S[tid] = msg1[(g*Nn + j)*Hd + tid];
        else if (tid < 224) eixS[tid - 128] = g_eidx[(g*Nn + (tid - 128))*Nn + j];
        __syncthreads();

        for (int p = tid; p < Nn*64; p += 256) {
            int r = p >> 6, c = (p & 63)*2;
            float2 m2 = *(const float2*)(msg2 + (size_t)(g*Nn + r)*Hd + c);
            float f0 = m1S[c] + m2.x, f1 = m1S[c+1] + m2.y;
            int e = eixS[r];
            if (e >= 0) {
                float2 ep = *(const float2*)(eproj + (size_t)e*Hd + c);
                f0 += ep.x; f1 += ep.y;
            }
            f0 = fmaxf(f0, 0.f); f1 = fmaxf(f1, 0.f);
            split_store(sh + O_AHI, sh + O_ALO, (uint32_t)(r*ARS + c*2), f0, f1);
        }
        __syncthreads();

        float acc[3][4][4];
#pragma unroll
        for (int mi = 0; mi < 3; mi++)
#pragma unroll
            for (int ni = 0; ni < 4; ni++)
#pragma unroll
                for (int q = 0; q < 4; q++) acc[mi][ni][q] = 0.f;

        // ---- GEMM1 (ldmatrix fragments) ----
#pragma unroll
        for (int ks = 0; ks < 8; ks++) {
            uint32_t kbase = ks*32;
            uint32_t afh[3][4], afl[3][4], bh[2][4], bl2[2][4];
#pragma unroll
            for (int mi = 0; mi < 3; mi++) {
                uint32_t ro = (uint32_t)((R0 + mi*16)*ARS) + kbase + aoff;
                ldsm4(afh[mi], sb + O_AHI + ro);
                ldsm4(afl[mi], sb + O_ALO + ro);
            }
#pragma unroll
            for (int p = 0; p < 2; p++) {
                uint32_t no = (uint32_t)((C0 + p*16)*ARS) + kbase + boff;
                ldsm4(bh[p],  sb + O_W1H + no);
                ldsm4(bl2[p], sb + O_W1L + no);
            }
#pragma unroll
            for (int mi = 0; mi < 3; mi++)
#pragma unroll
                for (int p = 0; p < 2; p++)
#pragma unroll
                    for (int hh = 0; hh < 2; hh++) {
                        int ni = p*2 + hh;
                        mma16816(acc[mi][ni], afh[mi], &bh[p][hh*2]);
                        mma16816(acc[mi][ni], afh[mi], &bl2[p][hh*2]);
                        mma16816(acc[mi][ni], afl[mi], &bh[p][hh*2]);
                    }
        }

        // ---- epilogue1 ----
        __syncthreads();
#pragma unroll
        for (int mi = 0; mi < 3; mi++) {
#pragma unroll
            for (int ni = 0; ni < 4; ni++) {
                int r = R0 + mi*16 + gq, c = C0 + ni*8 + t*2;
                float f0 = fmaxf(acc[mi][ni][0] + b1s[c],   0.f);
                float f1 = fmaxf(acc[mi][ni][1] + b1s[c+1], 0.f);
                split_store(sh + O_AHI, sh + O_ALO, (uint32_t)(r*ARS + c*2), f0, f1);
                float f2 = fmaxf(acc[mi][ni][2] + b1s[c],   0.f);
                float f3 = fmaxf(acc[mi][ni][3] + b1s[c+1], 0.f);
                split_store(sh + O_AHI, sh + O_ALO, (uint32_t)((r+8)*ARS + c*2), f2, f3);
            }
        }
        __syncthreads();

#pragma unroll
        for (int mi = 0; mi < 3; mi++)
#pragma unroll
            for (int ni = 0; ni < 4; ni++)
#pragma unroll
                for (int q = 0; q < 4; q++) acc[mi][ni][q] = 0.f;

        // ---- GEMM2 (ldmatrix fragments) ----
#pragma unroll
        for (int ks = 0; ks < 8; ks++) {
            uint32_t kbase = ks*32;
            uint32_t afh[3][4], afl[3][4], bh[2][4], bl2[2][4];
#pragma unroll
            for (int mi = 0; mi < 3; mi++) {
                uint32_t ro = (uint32_t)((R0 + mi*16)*ARS) + kbase + aoff;
                ldsm4(afh[mi], sb + O_AHI + ro);
                ldsm4(afl[mi], sb + O_ALO + ro);
            }
#pragma unroll
            for (int p = 0; p < 2; p++) {
                uint32_t no = (uint32_t)((C0 + p*16)*ARS) + kbase + boff;
                ldsm4(bh[p],  sb + O_W2H + no);
                ldsm4(bl2[p], sb + O_W2L + no);
            }
#pragma unroll
            for (int mi = 0; mi < 3; mi++)
#pragma unroll
                for (int p = 0; p < 2; p++)
#pragma unroll
                    for (int hh = 0; hh < 2; hh++) {
                        int ni = p*2 + hh;
                        mma16816(acc[mi][ni], afh[mi], &bh[p][hh*2]);
                        mma16816(acc[mi][ni], afh[mi], &bl2[p][hh*2]);
                        mma16816(acc[mi][ni], afl[mi], &bh[p][hh*2]);
                    }
        }

        // ---- max over senders ----
#pragma unroll
        for (int ni = 0; ni < 4; ni++) {
            float v0 = fmaxf(acc[0][ni][0], acc[0][ni][2]);
            float v1 = fmaxf(acc[0][ni][1], acc[0][ni][3]);
#pragma unroll
            for (int mi = 1; mi < 3; mi++) {
                v0 = fmaxf(v0, fmaxf(acc[mi][ni][0], acc[mi][ni][2]));
                v1 = fmaxf(v1, fmaxf(acc[mi][ni][1], acc[mi][ni][3]));
            }
#pragma unroll
            for (int st = 4; st < 32; st <<= 1) {
                v0 = fmaxf(v0, __shfl_xor_sync(0xffffffffu, v0, st));
                v1 = fmaxf(v1, __shfl_xor_sync(0xffffffffu, v1, st));
            }
            if (gq == 0) {
                maxr[rg*128 + C0 + ni*8 + t*2]     = v0;
                maxr[rg*128 + C0 + ni*8 + t*2 + 1] = v1;
            }
        }
        __syncthreads();
        if (tid < Hd)
            mmout[(g*Nn + j)*Hd + tid] =
                fmaxf(maxr[tid], maxr[128 + tid]) + b2s[tid];
        __syncthreads();
    }
}

// ---------------- out + layernorm, gridDim.y = stream ----------------------
__device__ __forceinline__ float blk_sum128(float v, volatile float* red) {
    int tid = threadIdx.x;
#pragma unroll
    for (int o = 16; o; o >>= 1) v += __shfl_xor_sync(0xffffffffu, v, o);
    if ((tid & 31) == 0) red[tid >> 5] = v;
    __syncthreads();
    float t = red[0] + red[1] + red[2] + red[3];
    __syncthreads();
    return t;
}

__global__ void k_outln(const float* __restrict__ Wo1g, const float* __restrict__ bo1g,
                        const float* __restrict__ Wo2g, const float* __restrict__ bo2g,
                        const float* __restrict__ lgg,  const float* __restrict__ lbg,
                        int layer) {
    int s = blockIdx.y, ls = layer*2 + s;
    const float* Wo1 = Wo1g + (size_t)ls*256*Hd;
    const float* Wo2 = Wo2g + (size_t)ls*Hd*Hd;
    __shared__ float zS[4*256];
    __shared__ float mmS[4*128];
    __shared__ float red[4];
    int tid = threadIdx.x, n0 = blockIdx.x*4;
    const float* mm = g_maxmsg + (size_t)s*MSZ;
    for (int idx = tid; idx < 1024; idx += 128) {
        int nn = idx >> 8, k = idx & 255;
        zS[idx] = (k < Hd) ? g_node[(n0+nn)*Hd + k] : g_hidden[(n0+nn)*Hd + (k - Hd)];
    }
    for (int idx = tid; idx < 512; idx += 128) {
        int nn = idx >> 7, k = idx & 127;
        mmS[idx] = mm[(n0+nn)*Hd + k];
    }
    __syncthreads();
    int h = tid;
    float acc[4];
    float bb = bo1g[ls*Hd + h] + bo2g[ls*Hd + h];
#pragma unroll
    for (int nn = 0; nn < 4; nn++) acc[nn] = bb;
    for (int k = 0; k < 256; k++) {
        float w = Wo1[k*Hd + h];
#pragma unroll
        for (int nn = 0; nn < 4; nn++) acc[nn] += zS[nn*256 + k]*w;
    }
    for (int k = 0; k < 128; k++) {
        float w = Wo2[k*Hd + h];
#pragma unroll
        for (int nn = 0; nn < 4; nn++) acc[nn] += mmS[nn*128 + k]*w;
    }
    float lgv = lgg[ls*Hd + h], lbv = lbg[ls*Hd + h];
    float* ob = s ? g_out1 : g_out0;
    for (int nn = 0; nn < 4; nn++) {
        float v = fmaxf(acc[nn], 0.f);
        float mu = blk_sum128(v, red) * (1.f/128.f);
        float d = v - mu;
        float var = blk_sum128(d*d, red) * (1.f/128.f);
        float rstd = rsqrtf(var + 1e-5f);
        ob[(n0+nn)*Hd + h] = d*rstd*lgv + lbv;
    }
}

// ---------------- hidden = concat(out0,out1) @ W_red + b_red ---------------
__global__ void k_reduce(const float* __restrict__ Wred, const float* __restrict__ bred) {
    __shared__ float zz[4*256];
    int tid = threadIdx.x, n0 = blockIdx.x*4;
    for (int idx = tid; idx < 1024; idx += 128) {
        int nn = idx >> 8, k = idx & 255;
        zz[idx] = (k < Hd) ? g_out0[(n0+nn)*Hd + k] : g_out1[(n0+nn)*Hd + (k - Hd)];
    }
    __syncthreads();
    int h = tid;
    float acc[4];
    float bb = bred[h];
#pragma unroll
    for (int nn = 0; nn < 4; nn++) acc[nn] = bb;
    for (int k = 0; k < 256; k++) {
        float w = Wred[k*Hd + h];
#pragma unroll
        for (int nn = 0; nn < 4; nn++) acc[nn] += zz[nn*256 + k]*w;
    }
#pragma unroll
    for (int nn = 0; nn < 4; nn++) g_hidden[(n0+nn)*Hd + h] = acc[nn];
}

// ---------------- readout --------------------------------------------------
__global__ void k_final(const float* __restrict__ Wp1, const float* __restrict__ bp1,
                        const float* __restrict__ Wp2, const float* __restrict__ bp2,
                        float* __restrict__ out) {
    __shared__ float embS[128], h1S[128], red[4];
    int g = blockIdx.x, h = threadIdx.x;
    float s = 0.f;
    for (int n = 0; n < Nn; n++) s += g_hidden[(g*Nn + n)*Hd + h];
    embS[h] = s * (1.f/96.f);
    __syncthreads();
    float a = bp1[h];
    for (int k = 0; k < 128; k++) a += embS[k]*Wp1[k*Hd + h];
    h1S[h] = fmaxf(a, 0.f);
    __syncthreads();
    float v = h1S[h] * Wp2[h];
    float tot = blk_sum128(v, red);
    if (h == 0) out[g] = tot + bp2[0];
}

// ---------------- launch ---------------------------------------------------
extern "C" void kernel_launch(void* const* d_in, const int* in_sizes, int n_in,
                              void* d_out, int out_size) {
    int o = (n_in >= 32) ? 6 : 4;
    const int*   x    = (const int*)d_in[0];
    const int*   ea   = (const int*)d_in[1];
    const int*   src  = (const int*)d_in[2];
    const int*   dst  = (const int*)d_in[3];
    const float* atom = (const float*)d_in[o+0];
    const float* bond = (const float*)d_in[o+1];
    const float* Wm1  = (const float*)d_in[o+2];
    const float* bm1  = (const float*)d_in[o+3];
    const float* Wm2  = (const float*)d_in[o+4];
    const float* bm2  = (const float*)d_in[o+5];
    const float* Wme  = (const float*)d_in[o+6];
    const float* bme  = (const float*)d_in[o+7];
    const float* bmg  = (const float*)d_in[o+9];   // W_mg unused (graph_fts == 0)
    const float* Wl1  = (const float*)d_in[o+10];
    const float* bl1  = (const float*)d_in[o+11];
    const float* Wl2  = (const float*)d_in[o+12];
    const float* bl2  = (const float*)d_in[o+13];
    const float* Wo1  = (const float*)d_in[o+14];
    const float* bo1  = (const float*)d_in[o+15];
    const float* Wo2  = (const float*)d_in[o+16];
    const float* bo2  = (const float*)d_in[o+17];
    const float* lng  = (const float*)d_in[o+18];
    const float* lnb  = (const float*)d_in[o+19];
    const float* Wred = (const float*)d_in[o+20];
    const float* bred = (const float*)d_in[o+21];
    const float* Wp1  = (const float*)d_in[o+22];
    const float* bp1  = (const float*)d_in[o+23];
    const float* Wp2  = (const float*)d_in[o+24];
    const float* bp2  = (const float*)d_in[o+25];
    float* out = (float*)d_out;

    cudaFuncSetAttribute(k_fused_mma,    cudaFuncAttributeMaxDynamicSharedMemorySize, SMEM_FUSED);
    cudaFuncSetAttribute(k_edgeproj_mma, cudaFuncAttributeMaxDynamicSharedMemorySize, SMEM_EP);

    k_encode_nodes<<<NGn, 128>>>(x, atom);
    k_encode_edges<<<Ed, 128>>>(ea, bond);
    k_init_eidx<<<(Gn*Nn*Nn + 255)/256, 256>>>();
    k_scatter<<<(Ed + 255)/256, 256>>>(src, dst);
    k_prepw<<<dim3(16, 6), 256>>>(Wl1, Wl2, Wme);

    for (int i = 0; i < 3; i++) {
        k_msg12<<<dim3(NGn/8, 2), 128>>>(Wm1, bm1, Wm2, bm2, bme, bmg, i);
        k_edgeproj_mma<<<dim3(Ed/128, 2), 256, SMEM_EP>>>(i);
        k_fused_mma<<<148, 256, SMEM_FUSED>>>(i, bl1, bl2);
        k_outln<<<dim3(NGn/4, 2), 128>>>(Wo1, bo1, Wo2, bo2, lng, lnb, i);
        k_reduce<<<NGn/4, 128>>>(Wred + (size_t)i*256*Hd, bred + i*Hd);
    }
    k_final<<<Gn, 128>>>(Wp1, bp1, Wp2, bp2, out);
    (void)in_sizes; (void)out_size;
}

// round 13
// speedup vs baseline: 1.4241x; 1.1641x over previous
#include <cuda_runtime.h>
#include <cuda_bf16.h>
#include <math.h>
#include <stdint.h>

#define Gn  16
#define Nn  96
#define Hd  128
#define Ed  24576
#define NGn (Gn*Nn)   // 1536
#define MSZ (NGn*Hd)
#define EPZ (Ed*Hd)

typedef unsigned long long ull;

// ---------------- packed f32x2 helpers -------------------------------------
__device__ __forceinline__ ull pk1(float x) {
    ull r; asm("mov.b64 %0, {%1,%1};" : "=l"(r) : "f"(x)); return r;
}
__device__ __forceinline__ ull pk2(float x, float y) {
    ull r; asm("mov.b64 %0, {%1,%2};" : "=l"(r) : "f"(x), "f"(y)); return r;
}
__device__ __forceinline__ void ffma2(ull& d, ull a, ull b) {
    asm("fma.rn.f32x2 %0, %1, %2, %0;" : "+l"(d) : "l"(a), "l"(b));
}
__device__ __forceinline__ float2 unpk(ull v) {
    float2 f; asm("mov.b64 {%0,%1}, %2;" : "=f"(f.x), "=f"(f.y) : "l"(v)); return f;
}

// ---------------- misc helpers ---------------------------------------------
__device__ __forceinline__ uint32_t s2u(const void* p) {
    uint32_t a;
    asm("{ .reg .u64 t; cvta.to.shared.u64 t, %1; cvt.u32.u64 %0, t; }" : "=r"(a) : "l"(p));
    return a;
}
__device__ __forceinline__ uint32_t pkbf(float lo, float hi) {
    uint32_t r; asm("cvt.rn.bf16x2.f32 %0, %1, %2;" : "=r"(r) : "f"(hi), "f"(lo)); return r;
}
__device__ __forceinline__ void split_store(char* hiT, char* loT, uint32_t off,
                                            float f0, float f1) {
    uint32_t h = pkbf(f0, f1);
    float h0 = __uint_as_float(h << 16);
    float h1 = __uint_as_float(h & 0xffff0000u);
    uint32_t l = pkbf(f0 - h0, f1 - h1);
    *(uint32_t*)(hiT + off) = h;
    *(uint32_t*)(loT + off) = l;
}

// HMMA m16n8k16 bf16 -> f32 accumulate (arch-agnostic PTX, sm_80+)
__device__ __forceinline__ void mma16816(float* d, const uint32_t* a, const uint32_t* b) {
    asm volatile(
        "mma.sync.aligned.m16n8k16.row.col.f32.bf16.bf16.f32 "
        "{%0,%1,%2,%3}, {%4,%5,%6,%7}, {%8,%9}, {%0,%1,%2,%3};"
        : "+f"(d[0]), "+f"(d[1]), "+f"(d[2]), "+f"(d[3])
        : "r"(a[0]), "r"(a[1]), "r"(a[2]), "r"(a[3]), "r"(b[0]), "r"(b[1]));
}
// ldmatrix x4 (sm_75+, arch-agnostic)
__device__ __forceinline__ void ldsm4(uint32_t* r, uint32_t addr) {
    asm volatile("ldmatrix.sync.aligned.m8n8.x4.shared.b16 {%0,%1,%2,%3}, [%4];"
        : "=r"(r[0]), "=r"(r[1]), "=r"(r[2]), "=r"(r[3]) : "r"(addr));
}

// ---------------- scratch ---------------------------------------------------
#define ARS  272              // tile row stride in bytes (136 bf16)
#define TILE_B 34816          // 128 rows * 272 B
#define WSET_B (4*TILE_B)     // W1H,W1L,W2H,W2L contiguous = 139264 B

__device__ __align__(16) float g_node[MSZ];
__device__ __align__(16) float g_hidden[MSZ];
__device__ __align__(16) float g_edgefts[EPZ];
__device__ __align__(16) float g_edgeproj[2*EPZ];     // per-stream, per-layer (L2-hot)
__device__              int   g_eidx[Gn*Nn*Nn];
__device__ __align__(16) float g_msg1[2*MSZ];
__device__ __align__(16) float g_msg2[2*MSZ];
__device__ __align__(16) float g_maxmsg[2*MSZ];
__device__ __align__(16) float g_out0[MSZ];
__device__ __align__(16) float g_out1[MSZ];
__device__ __align__(16) char  g_wt[6*WSET_B];        // pre-split MLP weight tiles
__device__ __align__(16) char  g_wtme[6*2*TILE_B];    // pre-split W_me tiles

extern __shared__ char dyn_smem[];

// ---------------- encoders --------------------------------------------------
__global__ void k_encode_nodes(const int* __restrict__ x,
                               const float* __restrict__ atom) {
    int n = blockIdx.x, h = threadIdx.x;
    float s = 0.f;
#pragma unroll
    for (int c = 0; c < 9; c++) {
        int id = x[n*9 + c];
        s += atom[(c*119 + id)*Hd + h];
    }
    g_node[n*Hd + h]   = s;
    g_hidden[n*Hd + h] = 0.f;
}

__global__ void k_encode_edges(const int* __restrict__ ea,
                               const float* __restrict__ bond) {
    int e = blockIdx.x, h = threadIdx.x;
    float s = 0.f;
#pragma unroll
    for (int c = 0; c < 3; c++) {
        int id = ea[e*3 + c];
        s += bond[(c*6 + id)*Hd + h];
    }
    g_edgefts[e*Hd + h] = s;
}

__global__ void k_init_eidx() {
    int i = blockIdx.x*blockDim.x + threadIdx.x;
    if (i < Gn*Nn*Nn) g_eidx[i] = -1;
}

__global__ void k_scatter(const int* __restrict__ src, const int* __restrict__ dst) {
    int e = blockIdx.x*blockDim.x + threadIdx.x;
    if (e >= Ed) return;
    int s = src[e], d = dst[e];
    int g  = s / Nn;
    int li = s % Nn;
    int lj = d % Nn;
    atomicMax(&g_eidx[(g*Nn + li)*Nn + lj], e);
}

// ---------------- one-time weight prep (W1, W2, Wme) -----------------------
__global__ void k_prepw(const float* __restrict__ Wl1, const float* __restrict__ Wl2,
                        const float* __restrict__ Wmeg) {
    int ls = blockIdx.y;
    const float* W1 = Wl1 + (size_t)ls*Hd*Hd;
    const float* W2 = Wl2 + (size_t)ls*Hd*Hd;
    const float* We = Wmeg + (size_t)ls*Hd*Hd;
    char* base  = g_wt + (size_t)ls*WSET_B;
    char* baseE = g_wtme + (size_t)ls*2*TILE_B;
    int n0 = blockIdx.x*8;
    for (int p = threadIdx.x; p < 8*64; p += 256) {
        int nl = p >> 6, k = (p & 63)*2;
        int n = n0 + nl;
        uint32_t off = (uint32_t)(n*ARS + k*2);
        split_store(base,            base + TILE_B,   off, W1[k*Hd + n], W1[(k+1)*Hd + n]);
        split_store(base + 2*TILE_B, base + 3*TILE_B, off, W2[k*Hd + n], W2[(k+1)*Hd + n]);
        split_store(baseE,           baseE + TILE_B,  off, We[k*Hd + n], We[(k+1)*Hd + n]);
    }
}

// ---------------- msg1/msg2 (ffma2), gridDim.y = stream --------------------
__global__ void k_msg12(const float* __restrict__ Wm1, const float* __restrict__ bm1g,
                        const float* __restrict__ Wm2, const float* __restrict__ bm2g,
                        const float* __restrict__ bmeg, const float* __restrict__ bmgg,
                        int layer) {
    int s = blockIdx.y, ls = layer*2 + s;
    const float* W1 = Wm1 + (size_t)ls*256*Hd;
    const float* W2 = Wm2 + (size_t)ls*256*Hd;
    __shared__ float zS[256*8];
    int tid = threadIdx.x, n0 = blockIdx.x*8;
    for (int idx = tid; idx < 8*256; idx += 128) {
        int nn = idx >> 8, k = idx & 255;
        int n = n0 + nn;
        float v = (k < Hd) ? g_node[n*Hd + k] : g_hidden[n*Hd + (k - Hd)];
        zS[k*8 + nn] = v;
    }
    __syncthreads();
    int h = tid;
    ull a1[4], a2[4];
#pragma unroll
    for (int p = 0; p < 4; p++) { a1[p] = 0ull; a2[p] = 0ull; }
    for (int k = 0; k < 256; k++) {
        ull w1 = pk1(W1[k*Hd + h]);
        ull w2 = pk1(W2[k*Hd + h]);
        const float2* zr = (const float2*)(zS + k*8);
#pragma unroll
        for (int p = 0; p < 4; p++) {
            float2 z = zr[p];
            ull zp = pk2(z.x, z.y);
            ffma2(a1[p], zp, w1);
            ffma2(a2[p], zp, w2);
        }
    }
    float bb1 = bm1g[ls*Hd + h] + bmeg[ls*Hd + h] + bmgg[ls*Hd + h];
    float bb2 = bm2g[ls*Hd + h];
    float* m1 = g_msg1 + (size_t)s*MSZ;
    float* m2 = g_msg2 + (size_t)s*MSZ;
#pragma unroll
    for (int p = 0; p < 4; p++) {
        float2 v1 = unpk(a1[p]), v2 = unpk(a2[p]);
        m1[(n0+2*p+0)*Hd + h] = v1.x + bb1;
        m1[(n0+2*p+1)*Hd + h] = v1.y + bb1;
        m2[(n0+2*p+0)*Hd + h] = v2.x + bb2;
        m2[(n0+2*p+1)*Hd + h] = v2.y + bb2;
    }
}

// ---------------- edge projection (HMMA + ldmatrix) ------------------------
#define EO_AHI 0
#define EO_ALO TILE_B
#define EO_WH  (2*TILE_B)
#define EO_WL  (3*TILE_B)
#define SMEM_EP (4*TILE_B)

__global__ void __launch_bounds__(256, 1) k_edgeproj_mma(int layer) {
    char* sh = dyn_smem;
    const uint32_t sb = s2u(sh);
    const int tid = threadIdx.x, w = tid >> 5, lane = tid & 31;
    const int gq = lane >> 2, t = lane & 3;
    const int rg = w >> 1, cg = w & 1;       // 4x2 warp grid
    const int R0 = rg*32, C0 = cg*64;
    const int s = blockIdx.y, ls = layer*2 + s;
    const int e0 = blockIdx.x*128;

    const uint32_t aoff = (uint32_t)(((lane & 7) + ((lane >> 3) & 1)*8)*ARS
                                     + ((lane >> 4) & 1)*16);
    const uint32_t boff = (uint32_t)((((lane >> 4) & 1)*8 + (lane & 7))*ARS
                                     + ((lane >> 3) & 1)*16);

    {
        const uint4* src = (const uint4*)(g_wtme + (size_t)ls*2*TILE_B);
        uint4* dst = (uint4*)(sh + EO_WH);
        for (int p = tid; p < 2*TILE_B/16; p += 256) dst[p] = src[p];
    }
    for (int p = tid; p < 128*64; p += 256) {
        int r = p >> 6, c = (p & 63)*2;
        float2 a = *(const float2*)(g_edgefts + (size_t)(e0 + r)*Hd + c);
        split_store(sh + EO_AHI, sh + EO_ALO, (uint32_t)(r*ARS + c*2), a.x, a.y);
    }
    __syncthreads();

    float acc[2][8][4];
#pragma unroll
    for (int mi = 0; mi < 2; mi++)
#pragma unroll
        for (int ni = 0; ni < 8; ni++)
#pragma unroll
            for (int q = 0; q < 4; q++) acc[mi][ni][q] = 0.f;

#pragma unroll
    for (int ks = 0; ks < 8; ks++) {
        uint32_t kbase = ks*32;
        uint32_t afh[2][4], afl[2][4], bh[4][4], bl2[4][4];
#pragma unroll
        for (int mi = 0; mi < 2; mi++) {
            uint32_t ro = (uint32_t)((R0 + mi*16)*ARS) + kbase + aoff;
            ldsm4(afh[mi], sb + EO_AHI + ro);
            ldsm4(afl[mi], sb + EO_ALO + ro);
        }
#pragma unroll
        for (int p = 0; p < 4; p++) {
            uint32_t no = (uint32_t)((C0 + p*16)*ARS) + kbase + boff;
            ldsm4(bh[p],  sb + EO_WH + no);
            ldsm4(bl2[p], sb + EO_WL + no);
        }
#pragma unroll
        for (int mi = 0; mi < 2; mi++)
#pragma unroll
            for (int p = 0; p < 4; p++)
#pragma unroll
                for (int hh = 0; hh < 2; hh++) {
                    int ni = p*2 + hh;
                    mma16816(acc[mi][ni], afh[mi], &bh[p][hh*2]);
                    mma16816(acc[mi][ni], afh[mi], &bl2[p][hh*2]);
                    mma16816(acc[mi][ni], afl[mi], &bh[p][hh*2]);
                }
    }

    float* ep = g_edgeproj + (size_t)s*EPZ;
#pragma unroll
    for (int mi = 0; mi < 2; mi++)
#pragma unroll
        for (int ni = 0; ni < 8; ni++) {
            int r = R0 + mi*16 + gq, c = C0 + ni*8 + t*2;
            *(float2*)(ep + (size_t)(e0 + r)*Hd + c) =
                make_float2(acc[mi][ni][0], acc[mi][ni][1]);
            *(float2*)(ep + (size_t)(e0 + r + 8)*Hd + c) =
                make_float2(acc[mi][ni][2], acc[mi][ni][3]);
        }
}

// ---------------- fused message MLP + max (512 threads, persistent) --------
#define O_AHI  0
#define O_ALO  26112
#define O_W1H  52224
#define O_W1L  (O_W1H + TILE_B)
#define O_W2H  (O_W1H + 2*TILE_B)
#define O_W2L  (O_W1H + 3*TILE_B)
#define O_B1   191488
#define O_M1   192000
#define O_EIX  192512
#define O_MAXR 192896
#define O_B2   193920
#define SMEM_FUSED 194432

__global__ void __launch_bounds__(512, 1)
k_fused_mma(int layer, const float* __restrict__ bl1, const float* __restrict__ bl2) {
    char* sh = dyn_smem;
    const uint32_t sb = s2u(sh);
    const int tid = threadIdx.x, w = tid >> 5, lane = tid & 31;
    const int gq = lane >> 2, t = lane & 3;
    const int rg = w >> 3, cg = w & 7;      // 2 x 8 warp grid
    const int R0 = rg*48, C0 = cg*16;

    const uint32_t aoff = (uint32_t)(((lane & 7) + ((lane >> 3) & 1)*8)*ARS
                                     + ((lane >> 4) & 1)*16);
    const uint32_t boff = (uint32_t)((((lane >> 4) & 1)*8 + (lane & 7))*ARS
                                     + ((lane >> 3) & 1)*16);

    float* b1s  = (float*)(sh + O_B1);
    float* b2s  = (float*)(sh + O_B2);
    float* m1S  = (float*)(sh + O_M1);
    int*   eixS = (int*)(sh + O_EIX);
    float* maxr = (float*)(sh + O_MAXR);

    int cur_s = -1;
    for (int tt = blockIdx.x; tt < 2*NGn; tt += gridDim.x) {
        const int s  = (tt >= NGn) ? 1 : 0;
        const int lt = tt - s*NGn;
        const int g  = lt / Nn, j = lt - g*Nn;
        const int ls = layer*2 + s;

        if (s != cur_s) {
            const uint4* src = (const uint4*)(g_wt + (size_t)ls*WSET_B);
            uint4* dst = (uint4*)(sh + O_W1H);
            for (int p = tid; p < WSET_B/16; p += 512) dst[p] = src[p];
            if (tid < Hd)       b1s[tid] = bl1[ls*Hd + tid];
            else if (tid < 256) b2s[tid - 128] = bl2[ls*Hd + (tid - 128)];
            cur_s = s;
        }

        const float* msg1  = g_msg1 + (size_t)s*MSZ;
        const float* msg2  = g_msg2 + (size_t)s*MSZ;
        const float* eproj = g_edgeproj + (size_t)s*EPZ;
        float* mmout = g_maxmsg + (size_t)s*MSZ;

        if (tid < Hd)       m1S[tid] = msg1[(g*Nn + j)*Hd + tid];
        else if (tid < 224) eixS[tid - 128] = g_eidx[(g*Nn + (tid - 128))*Nn + j];
        __syncthreads();

        for (int p = tid; p < Nn*64; p += 512) {
            int r = p >> 6, c = (p & 63)*2;
            float2 m2 = *(const float2*)(msg2 + (size_t)(g*Nn + r)*Hd + c);
            float f0 = m1S[c] + m2.x, f1 = m1S[c+1] + m2.y;
            int e = eixS[r];
            if (e >= 0) {
                float2 ep = *(const float2*)(eproj + (size_t)e*Hd + c);
                f0 += ep.x; f1 += ep.y;
            }
            f0 = fmaxf(f0, 0.f); f1 = fmaxf(f1, 0.f);
            split_store(sh + O_AHI, sh + O_ALO, (uint32_t)(r*ARS + c*2), f0, f1);
        }
        __syncthreads();

        float acc[3][2][4];
#pragma unroll
        for (int mi = 0; mi < 3; mi++)
#pragma unroll
            for (int ni = 0; ni < 2; ni++)
#pragma unroll
                for (int q = 0; q < 4; q++) acc[mi][ni][q] = 0.f;

        // ---- GEMM1 ----
#pragma unroll
        for (int ks = 0; ks < 8; ks++) {
            uint32_t kbase = ks*32;
            uint32_t afh[3][4], afl[3][4], bh[4], bl2r[4];
#pragma unroll
            for (int mi = 0; mi < 3; mi++) {
                uint32_t ro = (uint32_t)((R0 + mi*16)*ARS) + kbase + aoff;
                ldsm4(afh[mi], sb + O_AHI + ro);
                ldsm4(afl[mi], sb + O_ALO + ro);
            }
            {
                uint32_t no = (uint32_t)(C0*ARS) + kbase + boff;
                ldsm4(bh,   sb + O_W1H + no);
                ldsm4(bl2r, sb + O_W1L + no);
            }
#pragma unroll
            for (int mi = 0; mi < 3; mi++)
#pragma unroll
                for (int hh = 0; hh < 2; hh++) {
                    mma16816(acc[mi][hh], afh[mi], &bh[hh*2]);
                    mma16816(acc[mi][hh], afh[mi], &bl2r[hh*2]);
                    mma16816(acc[mi][hh], afl[mi], &bh[hh*2]);
                }
        }

        // ---- epilogue1 ----
        __syncthreads();
#pragma unroll
        for (int mi = 0; mi < 3; mi++) {
#pragma unroll
            for (int ni = 0; ni < 2; ni++) {
                int r = R0 + mi*16 + gq, c = C0 + ni*8 + t*2;
                float f0 = fmaxf(acc[mi][ni][0] + b1s[c],   0.f);
                float f1 = fmaxf(acc[mi][ni][1] + b1s[c+1], 0.f);
                split_store(sh + O_AHI, sh + O_ALO, (uint32_t)(r*ARS + c*2), f0, f1);
                float f2 = fmaxf(acc[mi][ni][2] + b1s[c],   0.f);
                float f3 = fmaxf(acc[mi][ni][3] + b1s[c+1], 0.f);
                split_store(sh + O_AHI, sh + O_ALO, (uint32_t)((r+8)*ARS + c*2), f2, f3);
            }
        }
        __syncthreads();

#pragma unroll
        for (int mi = 0; mi < 3; mi++)
#pragma unroll
            for (int ni = 0; ni < 2; ni++)
#pragma unroll
                for (int q = 0; q < 4; q++) acc[mi][ni][q] = 0.f;

        // ---- GEMM2 ----
#pragma unroll
        for (int ks = 0; ks < 8; ks++) {
            uint32_t kbase = ks*32;
            uint32_t afh[3][4], afl[3][4], bh[4], bl2r[4];
#pragma unroll
            for (int mi = 0; mi < 3; mi++) {
                uint32_t ro = (uint32_t)((R0 + mi*16)*ARS) + kbase + aoff;
                ldsm4(afh[mi], sb + O_AHI + ro);
                ldsm4(afl[mi], sb + O_ALO + ro);
            }
            {
                uint32_t no = (uint32_t)(C0*ARS) + kbase + boff;
                ldsm4(bh,   sb + O_W2H + no);
                ldsm4(bl2r, sb + O_W2L + no);
            }
#pragma unroll
            for (int mi = 0; mi < 3; mi++)
#pragma unroll
                for (int hh = 0; hh < 2; hh++) {
                    mma16816(acc[mi][hh], afh[mi], &bh[hh*2]);
                    mma16816(acc[mi][hh], afh[mi], &bl2r[hh*2]);
                    mma16816(acc[mi][hh], afl[mi], &bh[hh*2]);
                }
        }

        // ---- max over senders ----
#pragma unroll
        for (int ni = 0; ni < 2; ni++) {
            float v0 = fmaxf(acc[0][ni][0], acc[0][ni][2]);
            float v1 = fmaxf(acc[0][ni][1], acc[0][ni][3]);
#pragma unroll
            for (int mi = 1; mi < 3; mi++) {
                v0 = fmaxf(v0, fmaxf(acc[mi][ni][0], acc[mi][ni][2]));
                v1 = fmaxf(v1, fmaxf(acc[mi][ni][1], acc[mi][ni][3]));
            }
#pragma unroll
            for (int st = 4; st < 32; st <<= 1) {
                v0 = fmaxf(v0, __shfl_xor_sync(0xffffffffu, v0, st));
                v1 = fmaxf(v1, __shfl_xor_sync(0xffffffffu, v1, st));
            }
            if (gq == 0) {
                maxr[rg*128 + C0 + ni*8 + t*2]     = v0;
                maxr[rg*128 + C0 + ni*8 + t*2 + 1] = v1;
            }
        }
        __syncthreads();
        if (tid < Hd)
            mmout[(g*Nn + j)*Hd + tid] =
                fmaxf(maxr[tid], maxr[128 + tid]) + b2s[tid];
        __syncthreads();
    }
}

// ---------------- out + layernorm, gridDim.y = stream ----------------------
__device__ __forceinline__ float blk_sum128(float v, volatile float* red) {
    int tid = threadIdx.x;
#pragma unroll
    for (int o = 16; o; o >>= 1) v += __shfl_xor_sync(0xffffffffu, v, o);
    if ((tid & 31) == 0) red[tid >> 5] = v;
    __syncthreads();
    float t = red[0] + red[1] + red[2] + red[3];
    __syncthreads();
    return t;
}

__global__ void k_outln(const float* __restrict__ Wo1g, const float* __restrict__ bo1g,
                        const float* __restrict__ Wo2g, const float* __restrict__ bo2g,
                        const float* __restrict__ lgg,  const float* __restrict__ lbg,
                        int layer) {
    int s = blockIdx.y, ls = layer*2 + s;
    const float* Wo1 = Wo1g + (size_t)ls*256*Hd;
    const float* Wo2 = Wo2g + (size_t)ls*Hd*Hd;
    __shared__ float zS[4*256];
    __shared__ float mmS[4*128];
    __shared__ float red[4];
    int tid = threadIdx.x, n0 = blockIdx.x*4;
    const float* mm = g_maxmsg + (size_t)s*MSZ;
    for (int idx = tid; idx < 1024; idx += 128) {
        int nn = idx >> 8, k = idx & 255;
        zS[idx] = (k < Hd) ? g_node[(n0+nn)*Hd + k] : g_hidden[(n0+nn)*Hd + (k - Hd)];
    }
    for (int idx = tid; idx < 512; idx += 128) {
        int nn = idx >> 7, k = idx & 127;
        mmS[idx] = mm[(n0+nn)*Hd + k];
    }
    __syncthreads();
    int h = tid;
    float acc[4];
    float bb = bo1g[ls*Hd + h] + bo2g[ls*Hd + h];
#pragma unroll
    for (int nn = 0; nn < 4; nn++) acc[nn] = bb;
    for (int k = 0; k < 256; k++) {
        float w = Wo1[k*Hd + h];
#pragma unroll
        for (int nn = 0; nn < 4; nn++) acc[nn] += zS[nn*256 + k]*w;
    }
    for (int k = 0; k < 128; k++) {
        float w = Wo2[k*Hd + h];
#pragma unroll
        for (int nn = 0; nn < 4; nn++) acc[nn] += mmS[nn*128 + k]*w;
    }
    float lgv = lgg[ls*Hd + h], lbv = lbg[ls*Hd + h];
    float* ob = s ? g_out1 : g_out0;
    for (int nn = 0; nn < 4; nn++) {
        float v = fmaxf(acc[nn], 0.f);
        float mu = blk_sum128(v, red) * (1.f/128.f);
        float d = v - mu;
        float var = blk_sum128(d*d, red) * (1.f/128.f);
        float rstd = rsqrtf(var + 1e-5f);
        ob[(n0+nn)*Hd + h] = d*rstd*lgv + lbv;
    }
}

// ---------------- hidden = concat(out0,out1) @ W_red + b_red ---------------
__global__ void k_reduce(const float* __restrict__ Wred, const float* __restrict__ bred) {
    __shared__ float zz[4*256];
    int tid = threadIdx.x, n0 = blockIdx.x*4;
    for (int idx = tid; idx < 1024; idx += 128) {
        int nn = idx >> 8, k = idx & 255;
        zz[idx] = (k < Hd) ? g_out0[(n0+nn)*Hd + k] : g_out1[(n0+nn)*Hd + (k - Hd)];
    }
    __syncthreads();
    int h = tid;
    float acc[4];
    float bb = bred[h];
#pragma unroll
    for (int nn = 0; nn < 4; nn++) acc[nn] = bb;
    for (int k = 0; k < 256; k++) {
        float w = Wred[k*Hd + h];
#pragma unroll
        for (int nn = 0; nn < 4; nn++) acc[nn] += zz[nn*256 + k]*w;
    }
#pragma unroll
    for (int nn = 0; nn < 4; nn++) g_hidden[(n0+nn)*Hd + h] = acc[nn];
}

// ---------------- readout --------------------------------------------------
__global__ void k_final(const float* __restrict__ Wp1, const float* __restrict__ bp1,
                        const float* __restrict__ Wp2, const float* __restrict__ bp2,
                        float* __restrict__ out) {
    __shared__ float embS[128], h1S[128], red[4];
    int g = blockIdx.x, h = threadIdx.x;
    float s = 0.f;
    for (int n = 0; n < Nn; n++) s += g_hidden[(g*Nn + n)*Hd + h];
    embS[h] = s * (1.f/96.f);
    __syncthreads();
    float a = bp1[h];
    for (int k = 0; k < 128; k++) a += embS[k]*Wp1[k*Hd + h];
    h1S[h] = fmaxf(a, 0.f);
    __syncthreads();
    float v = h1S[h] * Wp2[h];
    float tot = blk_sum128(v, red);
    if (h == 0) out[g] = tot + bp2[0];
}

// ---------------- launch ---------------------------------------------------
extern "C" void kernel_launch(void* const* d_in, const int* in_sizes, int n_in,
                              void* d_out, int out_size) {
    int o = (n_in >= 32) ? 6 : 4;
    const int*   x    = (const int*)d_in[0];
    const int*   ea   = (const int*)d_in[1];
    const int*   src  = (const int*)d_in[2];
    const int*   dst  = (const int*)d_in[3];
    const float* atom = (const float*)d_in[o+0];
    const float* bond = (const float*)d_in[o+1];
    const float* Wm1  = (const float*)d_in[o+2];
    const float* bm1  = (const float*)d_in[o+3];
    const float* Wm2  = (const float*)d_in[o+4];
    const float* bm2  = (const float*)d_in[o+5];
    const float* Wme  = (const float*)d_in[o+6];
    const float* bme  = (const float*)d_in[o+7];
    const float* bmg  = (const float*)d_in[o+9];   // W_mg unused (graph_fts == 0)
    const float* Wl1  = (const float*)d_in[o+10];
    const float* bl1  = (const float*)d_in[o+11];
    const float* Wl2  = (const float*)d_in[o+12];
    const float* bl2  = (const float*)d_in[o+13];
    const float* Wo1  = (const float*)d_in[o+14];
    const float* bo1  = (const float*)d_in[o+15];
    const float* Wo2  = (const float*)d_in[o+16];
    const float* bo2  = (const float*)d_in[o+17];
    const float* lng  = (const float*)d_in[o+18];
    const float* lnb  = (const float*)d_in[o+19];
    const float* Wred = (const float*)d_in[o+20];
    const float* bred = (const float*)d_in[o+21];
    const float* Wp1  = (const float*)d_in[o+22];
    const float* bp1  = (const float*)d_in[o+23];
    const float* Wp2  = (const float*)d_in[o+24];
    const float* bp2  = (const float*)d_in[o+25];
    float* out = (float*)d_out;

    cudaFuncSetAttribute(k_fused_mma,    cudaFuncAttributeMaxDynamicSharedMemorySize, SMEM_FUSED);
    cudaFuncSetAttribute(k_edgeproj_mma, cudaFuncAttributeMaxDynamicSharedMemorySize, SMEM_EP);

    k_encode_nodes<<<NGn, 128>>>(x, atom);
    k_encode_edges<<<Ed, 128>>>(ea, bond);
    k_init_eidx<<<(Gn*Nn*Nn + 255)/256, 256>>>();
    k_scatter<<<(Ed + 255)/256, 256>>>(src, dst);
    k_prepw<<<dim3(16, 6), 256>>>(Wl1, Wl2, Wme);

    for (int i = 0; i < 3; i++) {
        k_msg12<<<dim3(NGn/8, 2), 128>>>(Wm1, bm1, Wm2, bm2, bme, bmg, i);
        k_edgeproj_mma<<<dim3(Ed/128, 2), 256, SMEM_EP>>>(i);
        k_fused_mma<<<148, 512, SMEM_FUSED>>>(i, bl1, bl2);
        k_outln<<<dim3(NGn/4, 2), 128>>>(Wo1, bo1, Wo2, bo2, lng, lnb, i);
        k_reduce<<<NGn/4, 128>>>(Wred + (size_t)i*256*Hd, bred + i*Hd);
    }
    k_final<<<Gn, 128>>>(Wp1, bp1, Wp2, bp2, out);
    (void)in_sizes; (void)out_size;
}

// round 14
// speedup vs baseline: 1.4594x; 1.0247x over previous
#include <cuda_runtime.h>
#include <cuda_bf16.h>
#include <math.h>
#include <stdint.h>

#define Gn  16
#define Nn  96
#define Hd  128
#define Ed  24576
#define NGn (Gn*Nn)   // 1536
#define MSZ (NGn*Hd)
#define EPZ (Ed*Hd)

typedef unsigned long long ull;

// ---------------- packed f32x2 helpers -------------------------------------
__device__ __forceinline__ ull pk1(float x) {
    ull r; asm("mov.b64 %0, {%1,%1};" : "=l"(r) : "f"(x)); return r;
}
__device__ __forceinline__ ull pk2(float x, float y) {
    ull r; asm("mov.b64 %0, {%1,%2};" : "=l"(r) : "f"(x), "f"(y)); return r;
}
__device__ __forceinline__ void ffma2(ull& d, ull a, ull b) {
    asm("fma.rn.f32x2 %0, %1, %2, %0;" : "+l"(d) : "l"(a), "l"(b));
}
__device__ __forceinline__ float2 unpk(ull v) {
    float2 f; asm("mov.b64 {%0,%1}, %2;" : "=f"(f.x), "=f"(f.y) : "l"(v)); return f;
}

// ---------------- misc helpers ---------------------------------------------
__device__ __forceinline__ uint32_t s2u(const void* p) {
    uint32_t a;
    asm("{ .reg .u64 t; cvta.to.shared.u64 t, %1; cvt.u32.u64 %0, t; }" : "=r"(a) : "l"(p));
    return a;
}
__device__ __forceinline__ uint32_t pkbf(float lo, float hi) {
    uint32_t r; asm("cvt.rn.bf16x2.f32 %0, %1, %2;" : "=r"(r) : "f"(hi), "f"(lo)); return r;
}
__device__ __forceinline__ void split_store(char* hiT, char* loT, uint32_t off,
                                            float f0, float f1) {
    uint32_t h = pkbf(f0, f1);
    float h0 = __uint_as_float(h << 16);
    float h1 = __uint_as_float(h & 0xffff0000u);
    uint32_t l = pkbf(f0 - h0, f1 - h1);
    *(uint32_t*)(hiT + off) = h;
    *(uint32_t*)(loT + off) = l;
}

// HMMA m16n8k16 bf16 -> f32 accumulate (arch-agnostic PTX, sm_80+)
__device__ __forceinline__ void mma16816(float* d, const uint32_t* a, const uint32_t* b) {
    asm volatile(
        "mma.sync.aligned.m16n8k16.row.col.f32.bf16.bf16.f32 "
        "{%0,%1,%2,%3}, {%4,%5,%6,%7}, {%8,%9}, {%0,%1,%2,%3};"
        : "+f"(d[0]), "+f"(d[1]), "+f"(d[2]), "+f"(d[3])
        : "r"(a[0]), "r"(a[1]), "r"(a[2]), "r"(a[3]), "r"(b[0]), "r"(b[1]));
}
// ldmatrix x4 (sm_75+, arch-agnostic)
__device__ __forceinline__ void ldsm4(uint32_t* r, uint32_t addr) {
    asm volatile("ldmatrix.sync.aligned.m8n8.x4.shared.b16 {%0,%1,%2,%3}, [%4];"
        : "=r"(r[0]), "=r"(r[1]), "=r"(r[2]), "=r"(r[3]) : "r"(addr));
}

// ---------------- scratch ---------------------------------------------------
#define ARS  272              // tile row stride in bytes (136 bf16)
#define TILE_B 34816          // 128 rows * 272 B
#define WSET_B (4*TILE_B)     // W1H,W1L,W2H,W2L contiguous = 139264 B

__device__ __align__(16) float g_node[MSZ];
__device__ __align__(16) float g_hidden[MSZ];
__device__ __align__(16) float g_edgefts[EPZ];
__device__ __align__(16) float g_edgeproj[2*EPZ];     // per-stream, per-layer (L2-hot)
__device__              int   g_eidx[Gn*Nn*Nn];
__device__ __align__(16) float g_msg1[2*MSZ];
__device__ __align__(16) float g_msg2[2*MSZ];
__device__ __align__(16) float g_maxmsg[2*MSZ];
__device__ __align__(16) float g_out0[MSZ];
__device__ __align__(16) float g_out1[MSZ];
__device__ __align__(16) char  g_wt[6*WSET_B];        // pre-split MLP weight tiles
__device__ __align__(16) char  g_wtme[6*2*TILE_B];    // pre-split W_me tiles

extern __shared__ char dyn_smem[];

// ---------------- encoders --------------------------------------------------
__global__ void k_encode_nodes(const int* __restrict__ x,
                               const float* __restrict__ atom) {
    int n = blockIdx.x, h = threadIdx.x;
    float s = 0.f;
#pragma unroll
    for (int c = 0; c < 9; c++) {
        int id = x[n*9 + c];
        s += atom[(c*119 + id)*Hd + h];
    }
    g_node[n*Hd + h]   = s;
    g_hidden[n*Hd + h] = 0.f;
}

__global__ void k_encode_edges(const int* __restrict__ ea,
                               const float* __restrict__ bond) {
    int e = blockIdx.x, h = threadIdx.x;
    float s = 0.f;
#pragma unroll
    for (int c = 0; c < 3; c++) {
        int id = ea[e*3 + c];
        s += bond[(c*6 + id)*Hd + h];
    }
    g_edgefts[e*Hd + h] = s;
}

__global__ void k_init_eidx() {
    int i = blockIdx.x*blockDim.x + threadIdx.x;
    if (i < Gn*Nn*Nn) g_eidx[i] = -1;
}

__global__ void k_scatter(const int* __restrict__ src, const int* __restrict__ dst) {
    int e = blockIdx.x*blockDim.x + threadIdx.x;
    if (e >= Ed) return;
    int s = src[e], d = dst[e];
    int g  = s / Nn;
    int li = s % Nn;
    int lj = d % Nn;
    atomicMax(&g_eidx[(g*Nn + li)*Nn + lj], e);
}

// ---------------- one-time weight prep (W1, W2, Wme) -----------------------
__global__ void k_prepw(const float* __restrict__ Wl1, const float* __restrict__ Wl2,
                        const float* __restrict__ Wmeg) {
    int ls = blockIdx.y;
    const float* W1 = Wl1 + (size_t)ls*Hd*Hd;
    const float* W2 = Wl2 + (size_t)ls*Hd*Hd;
    const float* We = Wmeg + (size_t)ls*Hd*Hd;
    char* base  = g_wt + (size_t)ls*WSET_B;
    char* baseE = g_wtme + (size_t)ls*2*TILE_B;
    int n0 = blockIdx.x*8;
    for (int p = threadIdx.x; p < 8*64; p += 256) {
        int nl = p >> 6, k = (p & 63)*2;
        int n = n0 + nl;
        uint32_t off = (uint32_t)(n*ARS + k*2);
        split_store(base,            base + TILE_B,   off, W1[k*Hd + n], W1[(k+1)*Hd + n]);
        split_store(base + 2*TILE_B, base + 3*TILE_B, off, W2[k*Hd + n], W2[(k+1)*Hd + n]);
        split_store(baseE,           baseE + TILE_B,  off, We[k*Hd + n], We[(k+1)*Hd + n]);
    }
}

// ---------------- msg1/msg2 (ffma2), gridDim.y = stream --------------------
__global__ void k_msg12(const float* __restrict__ Wm1, const float* __restrict__ bm1g,
                        const float* __restrict__ Wm2, const float* __restrict__ bm2g,
                        const float* __restrict__ bmeg, const float* __restrict__ bmgg,
                        int layer) {
    int s = blockIdx.y, ls = layer*2 + s;
    const float* W1 = Wm1 + (size_t)ls*256*Hd;
    const float* W2 = Wm2 + (size_t)ls*256*Hd;
    __shared__ float zS[256*8];
    int tid = threadIdx.x, n0 = blockIdx.x*8;
    for (int idx = tid; idx < 8*256; idx += 128) {
        int nn = idx >> 8, k = idx & 255;
        int n = n0 + nn;
        float v = (k < Hd) ? g_node[n*Hd + k] : g_hidden[n*Hd + (k - Hd)];
        zS[k*8 + nn] = v;
    }
    __syncthreads();
    int h = tid;
    ull a1[4], a2[4];
#pragma unroll
    for (int p = 0; p < 4; p++) { a1[p] = 0ull; a2[p] = 0ull; }
    for (int k = 0; k < 256; k++) {
        ull w1 = pk1(W1[k*Hd + h]);
        ull w2 = pk1(W2[k*Hd + h]);
        const float2* zr = (const float2*)(zS + k*8);
#pragma unroll
        for (int p = 0; p < 4; p++) {
            float2 z = zr[p];
            ull zp = pk2(z.x, z.y);
            ffma2(a1[p], zp, w1);
            ffma2(a2[p], zp, w2);
        }
    }
    float bb1 = bm1g[ls*Hd + h] + bmeg[ls*Hd + h] + bmgg[ls*Hd + h];
    float bb2 = bm2g[ls*Hd + h];
    float* m1 = g_msg1 + (size_t)s*MSZ;
    float* m2 = g_msg2 + (size_t)s*MSZ;
#pragma unroll
    for (int p = 0; p < 4; p++) {
        float2 v1 = unpk(a1[p]), v2 = unpk(a2[p]);
        m1[(n0+2*p+0)*Hd + h] = v1.x + bb1;
        m1[(n0+2*p+1)*Hd + h] = v1.y + bb1;
        m2[(n0+2*p+0)*Hd + h] = v2.x + bb2;
        m2[(n0+2*p+1)*Hd + h] = v2.y + bb2;
    }
}

// ---------------- edge projection (HMMA + ldmatrix) ------------------------
#define EO_AHI 0
#define EO_ALO TILE_B
#define EO_WH  (2*TILE_B)
#define EO_WL  (3*TILE_B)
#define SMEM_EP (4*TILE_B)

__global__ void __launch_bounds__(256, 1) k_edgeproj_mma(int layer) {
    char* sh = dyn_smem;
    const uint32_t sb = s2u(sh);
    const int tid = threadIdx.x, w = tid >> 5, lane = tid & 31;
    const int gq = lane >> 2, t = lane & 3;
    const int rg = w >> 1, cg = w & 1;       // 4x2 warp grid
    const int R0 = rg*32, C0 = cg*64;
    const int s = blockIdx.y, ls = layer*2 + s;
    const int e0 = blockIdx.x*128;

    const uint32_t aoff = (uint32_t)(((lane & 7) + ((lane >> 3) & 1)*8)*ARS
                                     + ((lane >> 4) & 1)*16);
    const uint32_t boff = (uint32_t)((((lane >> 4) & 1)*8 + (lane & 7))*ARS
                                     + ((lane >> 3) & 1)*16);

    {
        const uint4* src = (const uint4*)(g_wtme + (size_t)ls*2*TILE_B);
        uint4* dst = (uint4*)(sh + EO_WH);
        for (int p = tid; p < 2*TILE_B/16; p += 256) dst[p] = src[p];
    }
    for (int p = tid; p < 128*64; p += 256) {
        int r = p >> 6, c = (p & 63)*2;
        float2 a = *(const float2*)(g_edgefts + (size_t)(e0 + r)*Hd + c);
        split_store(sh + EO_AHI, sh + EO_ALO, (uint32_t)(r*ARS + c*2), a.x, a.y);
    }
    __syncthreads();

    float acc[2][8][4];
#pragma unroll
    for (int mi = 0; mi < 2; mi++)
#pragma unroll
        for (int ni = 0; ni < 8; ni++)
#pragma unroll
            for (int q = 0; q < 4; q++) acc[mi][ni][q] = 0.f;

#pragma unroll
    for (int ks = 0; ks < 8; ks++) {
        uint32_t kbase = ks*32;
        uint32_t afh[2][4], afl[2][4], bh[4][4], bl2[4][4];
#pragma unroll
        for (int mi = 0; mi < 2; mi++) {
            uint32_t ro = (uint32_t)((R0 + mi*16)*ARS) + kbase + aoff;
            ldsm4(afh[mi], sb + EO_AHI + ro);
            ldsm4(afl[mi], sb + EO_ALO + ro);
        }
#pragma unroll
        for (int p = 0; p < 4; p++) {
            uint32_t no = (uint32_t)((C0 + p*16)*ARS) + kbase + boff;
            ldsm4(bh[p],  sb + EO_WH + no);
            ldsm4(bl2[p], sb + EO_WL + no);
        }
#pragma unroll
        for (int mi = 0; mi < 2; mi++)
#pragma unroll
            for (int p = 0; p < 4; p++)
#pragma unroll
                for (int hh = 0; hh < 2; hh++) {
                    int ni = p*2 + hh;
                    mma16816(acc[mi][ni], afh[mi], &bh[p][hh*2]);
                    mma16816(acc[mi][ni], afh[mi], &bl2[p][hh*2]);
                    mma16816(acc[mi][ni], afl[mi], &bh[p][hh*2]);
                }
    }

    float* ep = g_edgeproj + (size_t)s*EPZ;
#pragma unroll
    for (int mi = 0; mi < 2; mi++)
#pragma unroll
        for (int ni = 0; ni < 8; ni++) {
            int r = R0 + mi*16 + gq, c = C0 + ni*8 + t*2;
            *(float2*)(ep + (size_t)(e0 + r)*Hd + c) =
                make_float2(acc[mi][ni][0], acc[mi][ni][1]);
            *(float2*)(ep + (size_t)(e0 + r + 8)*Hd + c) =
                make_float2(acc[mi][ni][2], acc[mi][ni][3]);
        }
}

// ---------------- fused message MLP + max (512 threads, persistent) --------
#define O_AHI  0
#define O_ALO  26112
#define O_W1H  52224
#define O_W1L  (O_W1H + TILE_B)
#define O_W2H  (O_W1H + 2*TILE_B)
#define O_W2L  (O_W1H + 3*TILE_B)
#define O_B1   191488
#define O_M1   192000
#define O_EIX  192512
#define O_MAXR 192896
#define O_B2   193920
#define SMEM_FUSED 194432

__global__ void __launch_bounds__(512, 1)
k_fused_mma(int layer, const float* __restrict__ bl1, const float* __restrict__ bl2) {
    char* sh = dyn_smem;
    const uint32_t sb = s2u(sh);
    const int tid = threadIdx.x, w = tid >> 5, lane = tid & 31;
    const int gq = lane >> 2, t = lane & 3;
    const int rg = w >> 3, cg = w & 7;      // 2 x 8 warp grid
    const int R0 = rg*48, C0 = cg*16;

    const uint32_t aoff = (uint32_t)(((lane & 7) + ((lane >> 3) & 1)*8)*ARS
                                     + ((lane >> 4) & 1)*16);
    const uint32_t boff = (uint32_t)((((lane >> 4) & 1)*8 + (lane & 7))*ARS
                                     + ((lane >> 3) & 1)*16);

    float* b1s  = (float*)(sh + O_B1);
    float* b2s  = (float*)(sh + O_B2);
    float* m1S  = (float*)(sh + O_M1);
    int*   eixS = (int*)(sh + O_EIX);
    float* maxr = (float*)(sh + O_MAXR);

    int cur_s = -1;
    for (int tt = blockIdx.x; tt < 2*NGn; tt += gridDim.x) {
        const int s  = (tt >= NGn) ? 1 : 0;
        const int lt = tt - s*NGn;
        const int g  = lt / Nn, j = lt - g*Nn;
        const int ls = layer*2 + s;

        if (s != cur_s) {
            const uint4* src = (const uint4*)(g_wt + (size_t)ls*WSET_B);
            uint4* dst = (uint4*)(sh + O_W1H);
            for (int p = tid; p < WSET_B/16; p += 512) dst[p] = src[p];
            if (tid < Hd)       b1s[tid] = bl1[ls*Hd + tid];
            else if (tid < 256) b2s[tid - 128] = bl2[ls*Hd + (tid - 128)];
            cur_s = s;
        }

        const float* msg1  = g_msg1 + (size_t)s*MSZ;
        const float* msg2  = g_msg2 + (size_t)s*MSZ;
        const float* eproj = g_edgeproj + (size_t)s*EPZ;
        float* mmout = g_maxmsg + (size_t)s*MSZ;

        if (tid < Hd)       m1S[tid] = msg1[(g*Nn + j)*Hd + tid];
        else if (tid < 224) eixS[tid - 128] = g_eidx[(g*Nn + (tid - 128))*Nn + j];
        __syncthreads();

        for (int p = tid; p < Nn*64; p += 512) {
            int r = p >> 6, c = (p & 63)*2;
            float2 m2 = *(const float2*)(msg2 + (size_t)(g*Nn + r)*Hd + c);
            float f0 = m1S[c] + m2.x, f1 = m1S[c+1] + m2.y;
            int e = eixS[r];
            if (e >= 0) {
                float2 ep = *(const float2*)(eproj + (size_t)e*Hd + c);
                f0 += ep.x; f1 += ep.y;
            }
            f0 = fmaxf(f0, 0.f); f1 = fmaxf(f1, 0.f);
            split_store(sh + O_AHI, sh + O_ALO, (uint32_t)(r*ARS + c*2), f0, f1);
        }
        __syncthreads();

        float acc[3][2][4];
#pragma unroll
        for (int mi = 0; mi < 3; mi++)
#pragma unroll
            for (int ni = 0; ni < 2; ni++)
#pragma unroll
                for (int q = 0; q < 4; q++) acc[mi][ni][q] = 0.f;

        // ---- GEMM1 ----
#pragma unroll
        for (int ks = 0; ks < 8; ks++) {
            uint32_t kbase = ks*32;
            uint32_t afh[3][4], afl[3][4], bh[4], bl2r[4];
#pragma unroll
            for (int mi = 0; mi < 3; mi++) {
                uint32_t ro = (uint32_t)((R0 + mi*16)*ARS) + kbase + aoff;
                ldsm4(afh[mi], sb + O_AHI + ro);
                ldsm4(afl[mi], sb + O_ALO + ro);
            }
            {
                uint32_t no = (uint32_t)(C0*ARS) + kbase + boff;
                ldsm4(bh,   sb + O_W1H + no);
                ldsm4(bl2r, sb + O_W1L + no);
            }
#pragma unroll
            for (int mi = 0; mi < 3; mi++)
#pragma unroll
                for (int hh = 0; hh < 2; hh++) {
                    mma16816(acc[mi][hh], afh[mi], &bh[hh*2]);
                    mma16816(acc[mi][hh], afh[mi], &bl2r[hh*2]);
                    mma16816(acc[mi][hh], afl[mi], &bh[hh*2]);
                }
        }

        // ---- epilogue1 ----
        __syncthreads();
#pragma unroll
        for (int mi = 0; mi < 3; mi++) {
#pragma unroll
            for (int ni = 0; ni < 2; ni++) {
                int r = R0 + mi*16 + gq, c = C0 + ni*8 + t*2;
                float f0 = fmaxf(acc[mi][ni][0] + b1s[c],   0.f);
                float f1 = fmaxf(acc[mi][ni][1] + b1s[c+1], 0.f);
                split_store(sh + O_AHI, sh + O_ALO, (uint32_t)(r*ARS + c*2), f0, f1);
                float f2 = fmaxf(acc[mi][ni][2] + b1s[c],   0.f);
                float f3 = fmaxf(acc[mi][ni][3] + b1s[c+1], 0.f);
                split_store(sh + O_AHI, sh + O_ALO, (uint32_t)((r+8)*ARS + c*2), f2, f3);
            }
        }
        __syncthreads();

#pragma unroll
        for (int mi = 0; mi < 3; mi++)
#pragma unroll
            for (int ni = 0; ni < 2; ni++)
#pragma unroll
                for (int q = 0; q < 4; q++) acc[mi][ni][q] = 0.f;

        // ---- GEMM2 ----
#pragma unroll
        for (int ks = 0; ks < 8; ks++) {
            uint32_t kbase = ks*32;
            uint32_t afh[3][4], afl[3][4], bh[4], bl2r[4];
#pragma unroll
            for (int mi = 0; mi < 3; mi++) {
                uint32_t ro = (uint32_t)((R0 + mi*16)*ARS) + kbase + aoff;
                ldsm4(afh[mi], sb + O_AHI + ro);
                ldsm4(afl[mi], sb + O_ALO + ro);
            }
            {
                uint32_t no = (uint32_t)(C0*ARS) + kbase + boff;
                ldsm4(bh,   sb + O_W2H + no);
                ldsm4(bl2r, sb + O_W2L + no);
            }
#pragma unroll
            for (int mi = 0; mi < 3; mi++)
#pragma unroll
                for (int hh = 0; hh < 2; hh++) {
                    mma16816(acc[mi][hh], afh[mi], &bh[hh*2]);
                    mma16816(acc[mi][hh], afh[mi], &bl2r[hh*2]);
                    mma16816(acc[mi][hh], afl[mi], &bh[hh*2]);
                }
        }

        // ---- max over senders ----
#pragma unroll
        for (int ni = 0; ni < 2; ni++) {
            float v0 = fmaxf(acc[0][ni][0], acc[0][ni][2]);
            float v1 = fmaxf(acc[0][ni][1], acc[0][ni][3]);
#pragma unroll
            for (int mi = 1; mi < 3; mi++) {
                v0 = fmaxf(v0, fmaxf(acc[mi][ni][0], acc[mi][ni][2]));
                v1 = fmaxf(v1, fmaxf(acc[mi][ni][1], acc[mi][ni][3]));
            }
#pragma unroll
            for (int st = 4; st < 32; st <<= 1) {
                v0 = fmaxf(v0, __shfl_xor_sync(0xffffffffu, v0, st));
                v1 = fmaxf(v1, __shfl_xor_sync(0xffffffffu, v1, st));
            }
            if (gq == 0) {
                maxr[rg*128 + C0 + ni*8 + t*2]     = v0;
                maxr[rg*128 + C0 + ni*8 + t*2 + 1] = v1;
            }
        }
        __syncthreads();
        if (tid < Hd)
            mmout[(g*Nn + j)*Hd + tid] =
                fmaxf(maxr[tid], maxr[128 + tid]) + b2s[tid];
        __syncthreads();
    }
}

// ---------------- out + layernorm (ffma2-packed), gridDim.y = stream -------
__device__ __forceinline__ float blk_sum128(float v, volatile float* red) {
    int tid = threadIdx.x;
#pragma unroll
    for (int o = 16; o; o >>= 1) v += __shfl_xor_sync(0xffffffffu, v, o);
    if ((tid & 31) == 0) red[tid >> 5] = v;
    __syncthreads();
    float t = red[0] + red[1] + red[2] + red[3];
    __syncthreads();
    return t;
}

__global__ void k_outln(const float* __restrict__ Wo1g, const float* __restrict__ bo1g,
                        const float* __restrict__ Wo2g, const float* __restrict__ bo2g,
                        const float* __restrict__ lgg,  const float* __restrict__ lbg,
                        int layer) {
    int s = blockIdx.y, ls = layer*2 + s;
    const float* Wo1 = Wo1g + (size_t)ls*256*Hd;
    const float* Wo2 = Wo2g + (size_t)ls*Hd*Hd;
    __shared__ float zS[256*4];    // transposed [k*4 + nn]
    __shared__ float mmS[128*4];   // transposed [k*4 + nn]
    __shared__ float red[4];
    int tid = threadIdx.x, n0 = blockIdx.x*4;
    const float* mm = g_maxmsg + (size_t)s*MSZ;
    for (int idx = tid; idx < 1024; idx += 128) {
        int nn = idx >> 8, k = idx & 255;
        float v = (k < Hd) ? g_node[(n0+nn)*Hd + k] : g_hidden[(n0+nn)*Hd + (k - Hd)];
        zS[k*4 + nn] = v;
    }
    for (int idx = tid; idx < 512; idx += 128) {
        int nn = idx >> 7, k = idx & 127;
        mmS[k*4 + nn] = mm[(n0+nn)*Hd + k];
    }
    __syncthreads();
    int h = tid;
    float bb = bo1g[ls*Hd + h] + bo2g[ls*Hd + h];
    ull a01 = pk2(bb, bb), a23 = pk2(bb, bb);
    for (int k = 0; k < 256; k++) {
        ull w = pk1(Wo1[k*Hd + h]);
        const float2* zr = (const float2*)(zS + k*4);
        float2 z01 = zr[0], z23 = zr[1];
        ffma2(a01, pk2(z01.x, z01.y), w);
        ffma2(a23, pk2(z23.x, z23.y), w);
    }
    for (int k = 0; k < 128; k++) {
        ull w = pk1(Wo2[k*Hd + h]);
        const float2* zr = (const float2*)(mmS + k*4);
        float2 z01 = zr[0], z23 = zr[1];
        ffma2(a01, pk2(z01.x, z01.y), w);
        ffma2(a23, pk2(z23.x, z23.y), w);
    }
    float acc[4];
    {
        float2 v01 = unpk(a01), v23 = unpk(a23);
        acc[0] = v01.x; acc[1] = v01.y; acc[2] = v23.x; acc[3] = v23.y;
    }
    float lgv = lgg[ls*Hd + h], lbv = lbg[ls*Hd + h];
    float* ob = s ? g_out1 : g_out0;
    for (int nn = 0; nn < 4; nn++) {
        float v = fmaxf(acc[nn], 0.f);
        float mu = blk_sum128(v, red) * (1.f/128.f);
        float d = v - mu;
        float var = blk_sum128(d*d, red) * (1.f/128.f);
        float rstd = rsqrtf(var + 1e-5f);
        ob[(n0+nn)*Hd + h] = d*rstd*lgv + lbv;
    }
}

// ---------------- hidden = concat(out0,out1) @ W_red + b_red (ffma2) -------
__global__ void k_reduce(const float* __restrict__ Wred, const float* __restrict__ bred) {
    __shared__ float zz[256*4];    // transposed [k*4 + nn]
    int tid = threadIdx.x, n0 = blockIdx.x*4;
    for (int idx = tid; idx < 1024; idx += 128) {
        int nn = idx >> 8, k = idx & 255;
        float v = (k < Hd) ? g_out0[(n0+nn)*Hd + k] : g_out1[(n0+nn)*Hd + (k - Hd)];
        zz[k*4 + nn] = v;
    }
    __syncthreads();
    int h = tid;
    float bb = bred[h];
    ull a01 = pk2(bb, bb), a23 = pk2(bb, bb);
    for (int k = 0; k < 256; k++) {
        ull w = pk1(Wred[k*Hd + h]);
        const float2* zr = (const float2*)(zz + k*4);
        float2 z01 = zr[0], z23 = zr[1];
        ffma2(a01, pk2(z01.x, z01.y), w);
        ffma2(a23, pk2(z23.x, z23.y), w);
    }
    float2 v01 = unpk(a01), v23 = unpk(a23);
    g_hidden[(n0+0)*Hd + h] = v01.x;
    g_hidden[(n0+1)*Hd + h] = v01.y;
    g_hidden[(n0+2)*Hd + h] = v23.x;
    g_hidden[(n0+3)*Hd + h] = v23.y;
}

// ---------------- readout --------------------------------------------------
__global__ void k_final(const float* __restrict__ Wp1, const float* __restrict__ bp1,
                        const float* __restrict__ Wp2, const float* __restrict__ bp2,
                        float* __restrict__ out) {
    __shared__ float embS[128], h1S[128], red[4];
    int g = blockIdx.x, h = threadIdx.x;
    float s = 0.f;
    for (int n = 0; n < Nn; n++) s += g_hidden[(g*Nn + n)*Hd + h];
    embS[h] = s * (1.f/96.f);
    __syncthreads();
    float a = bp1[h];
    for (int k = 0; k < 128; k++) a += embS[k]*Wp1[k*Hd + h];
    h1S[h] = fmaxf(a, 0.f);
    __syncthreads();
    float v = h1S[h] * Wp2[h];
    float tot = blk_sum128(v, red);
    if (h == 0) out[g] = tot + bp2[0];
}

// ---------------- launch ---------------------------------------------------
extern "C" void kernel_launch(void* const* d_in, const int* in_sizes, int n_in,
                              void* d_out, int out_size) {
    int o = (n_in >= 32) ? 6 : 4;
    const int*   x    = (const int*)d_in[0];
    const int*   ea   = (const int*)d_in[1];
    const int*   src  = (const int*)d_in[2];
    const int*   dst  = (const int*)d_in[3];
    const float* atom = (const float*)d_in[o+0];
    const float* bond = (const float*)d_in[o+1];
    const float* Wm1  = (const float*)d_in[o+2];
    const float* bm1  = (const float*)d_in[o+3];
    const float* Wm2  = (const float*)d_in[o+4];
    const float* bm2  = (const float*)d_in[o+5];
    const float* Wme  = (const float*)d_in[o+6];
    const float* bme  = (const float*)d_in[o+7];
    const float* bmg  = (const float*)d_in[o+9];   // W_mg unused (graph_fts == 0)
    const float* Wl1  = (const float*)d_in[o+10];
    const float* bl1  = (const float*)d_in[o+11];
    const float* Wl2  = (const float*)d_in[o+12];
    const float* bl2  = (const float*)d_in[o+13];
    const float* Wo1  = (const float*)d_in[o+14];
    const float* bo1  = (const float*)d_in[o+15];
    const float* Wo2  = (const float*)d_in[o+16];
    const float* bo2  = (const float*)d_in[o+17];
    const float* lng  = (const float*)d_in[o+18];
    const float* lnb  = (const float*)d_in[o+19];
    const float* Wred = (const float*)d_in[o+20];
    const float* bred = (const float*)d_in[o+21];
    const float* Wp1  = (const float*)d_in[o+22];
    const float* bp1  = (const float*)d_in[o+23];
    const float* Wp2  = (const float*)d_in[o+24];
    const float* bp2  = (const float*)d_in[o+25];
    float* out = (float*)d_out;

    cudaFuncSetAttribute(k_fused_mma,    cudaFuncAttributeMaxDynamicSharedMemorySize, SMEM_FUSED);
    cudaFuncSetAttribute(k_edgeproj_mma, cudaFuncAttributeMaxDynamicSharedMemorySize, SMEM_EP);

    k_encode_nodes<<<NGn, 128>>>(x, atom);
    k_encode_edges<<<Ed, 128>>>(ea, bond);
    k_init_eidx<<<(Gn*Nn*Nn + 255)/256, 256>>>();
    k_scatter<<<(Ed + 255)/256, 256>>>(src, dst);
    k_prepw<<<dim3(16, 6), 256>>>(Wl1, Wl2, Wme);

    for (int i = 0; i < 3; i++) {
        k_msg12<<<dim3(NGn/8, 2), 128>>>(Wm1, bm1, Wm2, bm2, bme, bmg, i);
        k_edgeproj_mma<<<dim3(Ed/128, 2), 256, SMEM_EP>>>(i);
        k_fused_mma<<<148, 512, SMEM_FUSED>>>(i, bl1, bl2);
        k_outln<<<dim3(NGn/4, 2), 128>>>(Wo1, bo1, Wo2, bo2, lng, lnb, i);
        k_reduce<<<NGn/4, 128>>>(Wred + (size_t)i*256*Hd, bred + i*Hd);
    }
    k_final<<<Gn, 128>>>(Wp1, bp1, Wp2, bp2, out);
    (void)in_sizes; (void)out_size;
}

// round 15
// speedup vs baseline: 1.4599x; 1.0003x over previous
#include <cuda_runtime.h>
#include <cuda_bf16.h>
#include <math.h>
#include <stdint.h>

#define Gn  16
#define Nn  96
#define Hd  128
#define Ed  24576
#define NGn (Gn*Nn)   // 1536
#define MSZ (NGn*Hd)
#define EPZ (Ed*Hd)

typedef unsigned long long ull;

// ---------------- packed f32x2 helpers -------------------------------------
__device__ __forceinline__ ull pk1(float x) {
    ull r; asm("mov.b64 %0, {%1,%1};" : "=l"(r) : "f"(x)); return r;
}
__device__ __forceinline__ ull pk2(float x, float y) {
    ull r; asm("mov.b64 %0, {%1,%2};" : "=l"(r) : "f"(x), "f"(y)); return r;
}
__device__ __forceinline__ void ffma2(ull& d, ull a, ull b) {
    asm("fma.rn.f32x2 %0, %1, %2, %0;" : "+l"(d) : "l"(a), "l"(b));
}
__device__ __forceinline__ float2 unpk(ull v) {
    float2 f; asm("mov.b64 {%0,%1}, %2;" : "=f"(f.x), "=f"(f.y) : "l"(v)); return f;
}

// ---------------- misc helpers ---------------------------------------------
__device__ __forceinline__ uint32_t s2u(const void* p) {
    uint32_t a;
    asm("{ .reg .u64 t; cvta.to.shared.u64 t, %1; cvt.u32.u64 %0, t; }" : "=r"(a) : "l"(p));
    return a;
}
__device__ __forceinline__ uint32_t pkbf(float lo, float hi) {
    uint32_t r; asm("cvt.rn.bf16x2.f32 %0, %1, %2;" : "=r"(r) : "f"(hi), "f"(lo)); return r;
}
__device__ __forceinline__ void split_store(char* hiT, char* loT, uint32_t off,
                                            float f0, float f1) {
    uint32_t h = pkbf(f0, f1);
    float h0 = __uint_as_float(h << 16);
    float h1 = __uint_as_float(h & 0xffff0000u);
    uint32_t l = pkbf(f0 - h0, f1 - h1);
    *(uint32_t*)(hiT + off) = h;
    *(uint32_t*)(loT + off) = l;
}

// HMMA m16n8k16 bf16 -> f32 accumulate (arch-agnostic PTX, sm_80+)
__device__ __forceinline__ void mma16816(float* d, const uint32_t* a, const uint32_t* b) {
    asm volatile(
        "mma.sync.aligned.m16n8k16.row.col.f32.bf16.bf16.f32 "
        "{%0,%1,%2,%3}, {%4,%5,%6,%7}, {%8,%9}, {%0,%1,%2,%3};"
        : "+f"(d[0]), "+f"(d[1]), "+f"(d[2]), "+f"(d[3])
        : "r"(a[0]), "r"(a[1]), "r"(a[2]), "r"(a[3]), "r"(b[0]), "r"(b[1]));
}
// ldmatrix x4 (sm_75+, arch-agnostic)
__device__ __forceinline__ void ldsm4(uint32_t* r, uint32_t addr) {
    asm volatile("ldmatrix.sync.aligned.m8n8.x4.shared.b16 {%0,%1,%2,%3}, [%4];"
        : "=r"(r[0]), "=r"(r[1]), "=r"(r[2]), "=r"(r[3]) : "r"(addr));
}

// ---------------- scratch ---------------------------------------------------
#define ARS  272              // tile row stride in bytes (136 bf16)
#define TILE_B 34816          // 128 rows * 272 B
#define WSET_B (4*TILE_B)     // W1H,W1L,W2H,W2L contiguous = 139264 B

__device__ __align__(16) float g_node[MSZ];
__device__ __align__(16) float g_hidden[MSZ];
__device__ __align__(16) float g_edgefts[EPZ];
__device__ __align__(16) float g_edgeproj[2*EPZ];     // per-stream, per-layer (L2-hot)
__device__              int   g_eidx[Gn*Nn*Nn];
__device__ __align__(16) float g_msg1[2*MSZ];
__device__ __align__(16) float g_msg2[2*MSZ];
__device__ __align__(16) float g_maxmsg[2*MSZ];
__device__ __align__(16) float g_out0[MSZ];
__device__ __align__(16) float g_out1[MSZ];
__device__ __align__(16) char  g_wt[6*WSET_B];        // pre-split MLP weight tiles
__device__ __align__(16) char  g_wtme[6*2*TILE_B];    // pre-split W_me tiles

extern __shared__ char dyn_smem[];

// ---------------- encoders --------------------------------------------------
__global__ void k_encode_nodes(const int* __restrict__ x,
                               const float* __restrict__ atom) {
    int n = blockIdx.x, h = threadIdx.x;
    float s = 0.f;
#pragma unroll
    for (int c = 0; c < 9; c++) {
        int id = x[n*9 + c];
        s += atom[(c*119 + id)*Hd + h];
    }
    g_node[n*Hd + h]   = s;
    g_hidden[n*Hd + h] = 0.f;
}

__global__ void k_encode_edges(const int* __restrict__ ea,
                               const float* __restrict__ bond) {
    int e = blockIdx.x, h = threadIdx.x;
    float s = 0.f;
#pragma unroll
    for (int c = 0; c < 3; c++) {
        int id = ea[e*3 + c];
        s += bond[(c*6 + id)*Hd + h];
    }
    g_edgefts[e*Hd + h] = s;
}

__global__ void k_init_eidx() {
    int i = blockIdx.x*blockDim.x + threadIdx.x;
    if (i < Gn*Nn*Nn) g_eidx[i] = -1;
}

__global__ void k_scatter(const int* __restrict__ src, const int* __restrict__ dst) {
    int e = blockIdx.x*blockDim.x + threadIdx.x;
    if (e >= Ed) return;
    int s = src[e], d = dst[e];
    int g  = s / Nn;
    int li = s % Nn;
    int lj = d % Nn;
    atomicMax(&g_eidx[(g*Nn + li)*Nn + lj], e);
}

// ---------------- one-time weight prep (W1, W2, Wme) -----------------------
__global__ void k_prepw(const float* __restrict__ Wl1, const float* __restrict__ Wl2,
                        const float* __restrict__ Wmeg) {
    int ls = blockIdx.y;
    const float* W1 = Wl1 + (size_t)ls*Hd*Hd;
    const float* W2 = Wl2 + (size_t)ls*Hd*Hd;
    const float* We = Wmeg + (size_t)ls*Hd*Hd;
    char* base  = g_wt + (size_t)ls*WSET_B;
    char* baseE = g_wtme + (size_t)ls*2*TILE_B;
    int n0 = blockIdx.x*8;
    for (int p = threadIdx.x; p < 8*64; p += 256) {
        int nl = p >> 6, k = (p & 63)*2;
        int n = n0 + nl;
        uint32_t off = (uint32_t)(n*ARS + k*2);
        split_store(base,            base + TILE_B,   off, W1[k*Hd + n], W1[(k+1)*Hd + n]);
        split_store(base + 2*TILE_B, base + 3*TILE_B, off, W2[k*Hd + n], W2[(k+1)*Hd + n]);
        split_store(baseE,           baseE + TILE_B,  off, We[k*Hd + n], We[(k+1)*Hd + n]);
    }
}

// ---------------- msg1/msg2 (ffma2), 256 thr / 16 nodes, y = stream --------
__global__ void k_msg12(const float* __restrict__ Wm1, const float* __restrict__ bm1g,
                        const float* __restrict__ Wm2, const float* __restrict__ bm2g,
                        const float* __restrict__ bmeg, const float* __restrict__ bmgg,
                        int layer) {
    int s = blockIdx.y, ls = layer*2 + s;
    const float* W1 = Wm1 + (size_t)ls*256*Hd;
    const float* W2 = Wm2 + (size_t)ls*256*Hd;
    __shared__ float zS[2][256*8];
    int tid = threadIdx.x;
    int grp = tid >> 7, h = tid & 127;
    int n0 = blockIdx.x*16 + grp*8;
    for (int idx = h; idx < 8*256; idx += 128) {
        int nn = idx >> 8, k = idx & 255;
        int n = n0 + nn;
        float v = (k < Hd) ? g_node[n*Hd + k] : g_hidden[n*Hd + (k - Hd)];
        zS[grp][k*8 + nn] = v;
    }
    __syncthreads();
    ull a1[4], a2[4];
#pragma unroll
    for (int p = 0; p < 4; p++) { a1[p] = 0ull; a2[p] = 0ull; }
    for (int k = 0; k < 256; k++) {
        ull w1 = pk1(W1[k*Hd + h]);
        ull w2 = pk1(W2[k*Hd + h]);
        const float2* zr = (const float2*)(zS[grp] + k*8);
#pragma unroll
        for (int p = 0; p < 4; p++) {
            float2 z = zr[p];
            ull zp = pk2(z.x, z.y);
            ffma2(a1[p], zp, w1);
            ffma2(a2[p], zp, w2);
        }
    }
    float bb1 = bm1g[ls*Hd + h] + bmeg[ls*Hd + h] + bmgg[ls*Hd + h];
    float bb2 = bm2g[ls*Hd + h];
    float* m1 = g_msg1 + (size_t)s*MSZ;
    float* m2 = g_msg2 + (size_t)s*MSZ;
#pragma unroll
    for (int p = 0; p < 4; p++) {
        float2 v1 = unpk(a1[p]), v2 = unpk(a2[p]);
        m1[(n0+2*p+0)*Hd + h] = v1.x + bb1;
        m1[(n0+2*p+1)*Hd + h] = v1.y + bb1;
        m2[(n0+2*p+0)*Hd + h] = v2.x + bb2;
        m2[(n0+2*p+1)*Hd + h] = v2.y + bb2;
    }
}

// ---------------- edge projection (HMMA + ldmatrix, 512 threads) -----------
#define EO_AHI 0
#define EO_ALO TILE_B
#define EO_WH  (2*TILE_B)
#define EO_WL  (3*TILE_B)
#define SMEM_EP (4*TILE_B)

__global__ void __launch_bounds__(512, 1) k_edgeproj_mma(int layer) {
    char* sh = dyn_smem;
    const uint32_t sb = s2u(sh);
    const int tid = threadIdx.x, w = tid >> 5, lane = tid & 31;
    const int gq = lane >> 2, t = lane & 3;
    const int rg = w >> 2, cg = w & 3;       // 4x4 warp grid
    const int R0 = rg*32, C0 = cg*32;
    const int s = blockIdx.y, ls = layer*2 + s;
    const int e0 = blockIdx.x*128;

    const uint32_t aoff = (uint32_t)(((lane & 7) + ((lane >> 3) & 1)*8)*ARS
                                     + ((lane >> 4) & 1)*16);
    const uint32_t boff = (uint32_t)((((lane >> 4) & 1)*8 + (lane & 7))*ARS
                                     + ((lane >> 3) & 1)*16);

    {
        const uint4* src = (const uint4*)(g_wtme + (size_t)ls*2*TILE_B);
        uint4* dst = (uint4*)(sh + EO_WH);
        for (int p = tid; p < 2*TILE_B/16; p += 512) dst[p] = src[p];
    }
    for (int p = tid; p < 128*64; p += 512) {
        int r = p >> 6, c = (p & 63)*2;
        float2 a = *(const float2*)(g_edgefts + (size_t)(e0 + r)*Hd + c);
        split_store(sh + EO_AHI, sh + EO_ALO, (uint32_t)(r*ARS + c*2), a.x, a.y);
    }
    __syncthreads();

    float acc[2][4][4];
#pragma unroll
    for (int mi = 0; mi < 2; mi++)
#pragma unroll
        for (int ni = 0; ni < 4; ni++)
#pragma unroll
            for (int q = 0; q < 4; q++) acc[mi][ni][q] = 0.f;

#pragma unroll
    for (int ks = 0; ks < 8; ks++) {
        uint32_t kbase = ks*32;
        uint32_t afh[2][4], afl[2][4], bh[2][4], bl2[2][4];
#pragma unroll
        for (int mi = 0; mi < 2; mi++) {
            uint32_t ro = (uint32_t)((R0 + mi*16)*ARS) + kbase + aoff;
            ldsm4(afh[mi], sb + EO_AHI + ro);
            ldsm4(afl[mi], sb + EO_ALO + ro);
        }
#pragma unroll
        for (int p = 0; p < 2; p++) {
            uint32_t no = (uint32_t)((C0 + p*16)*ARS) + kbase + boff;
            ldsm4(bh[p],  sb + EO_WH + no);
            ldsm4(bl2[p], sb + EO_WL + no);
        }
#pragma unroll
        for (int mi = 0; mi < 2; mi++)
#pragma unroll
            for (int p = 0; p < 2; p++)
#pragma unroll
                for (int hh = 0; hh < 2; hh++) {
                    int ni = p*2 + hh;
                    mma16816(acc[mi][ni], afh[mi], &bh[p][hh*2]);
                    mma16816(acc[mi][ni], afh[mi], &bl2[p][hh*2]);
                    mma16816(acc[mi][ni], afl[mi], &bh[p][hh*2]);
                }
    }

    float* ep = g_edgeproj + (size_t)s*EPZ;
#pragma unroll
    for (int mi = 0; mi < 2; mi++)
#pragma unroll
        for (int ni = 0; ni < 4; ni++) {
            int r = R0 + mi*16 + gq, c = C0 + ni*8 + t*2;
            *(float2*)(ep + (size_t)(e0 + r)*Hd + c) =
                make_float2(acc[mi][ni][0], acc[mi][ni][1]);
            *(float2*)(ep + (size_t)(e0 + r + 8)*Hd + c) =
                make_float2(acc[mi][ni][2], acc[mi][ni][3]);
        }
}

// ---------------- fused message MLP + max (512 threads, persistent) --------
#define O_AHI  0
#define O_ALO  26112
#define O_W1H  52224
#define O_W1L  (O_W1H + TILE_B)
#define O_W2H  (O_W1H + 2*TILE_B)
#define O_W2L  (O_W1H + 3*TILE_B)
#define O_B1   191488
#define O_M1   192000
#define O_EIX  192512
#define O_MAXR 192896
#define O_B2   193920
#define SMEM_FUSED 194432

__global__ void __launch_bounds__(512, 1)
k_fused_mma(int layer, const float* __restrict__ bl1, const float* __restrict__ bl2) {
    char* sh = dyn_smem;
    const uint32_t sb = s2u(sh);
    const int tid = threadIdx.x, w = tid >> 5, lane = tid & 31;
    const int gq = lane >> 2, t = lane & 3;
    const int rg = w >> 3, cg = w & 7;      // 2 x 8 warp grid
    const int R0 = rg*48, C0 = cg*16;

    const uint32_t aoff = (uint32_t)(((lane & 7) + ((lane >> 3) & 1)*8)*ARS
                                     + ((lane >> 4) & 1)*16);
    const uint32_t boff = (uint32_t)((((lane >> 4) & 1)*8 + (lane & 7))*ARS
                                     + ((lane >> 3) & 1)*16);

    float* b1s  = (float*)(sh + O_B1);
    float* b2s  = (float*)(sh + O_B2);
    float* m1S  = (float*)(sh + O_M1);
    int*   eixS = (int*)(sh + O_EIX);
    float* maxr = (float*)(sh + O_MAXR);

    int cur_s = -1;
    for (int tt = blockIdx.x; tt < 2*NGn; tt += gridDim.x) {
        const int s  = (tt >= NGn) ? 1 : 0;
        const int lt = tt - s*NGn;
        const int g  = lt / Nn, j = lt - g*Nn;
        const int ls = layer*2 + s;

        if (s != cur_s) {
            const uint4* src = (const uint4*)(g_wt + (size_t)ls*WSET_B);
            uint4* dst = (uint4*)(sh + O_W1H);
            for (int p = tid; p < WSET_B/16; p += 512) dst[p] = src[p];
            if (tid < Hd)       b1s[tid] = bl1[ls*Hd + tid];
            else if (tid < 256) b2s[tid - 128] = bl2[ls*Hd + (tid - 128)];
            cur_s = s;
        }

        const float* msg1  = g_msg1 + (size_t)s*MSZ;
        const float* msg2  = g_msg2 + (size_t)s*MSZ;
        const float* eproj = g_edgeproj + (size_t)s*EPZ;
        float* mmout = g_maxmsg + (size_t)s*MSZ;

        if (tid < Hd)       m1S[tid] = msg1[(g*Nn + j)*Hd + tid];
        else if (tid < 224) eixS[tid - 128] = g_eidx[(g*Nn + (tid - 128))*Nn + j];
        __syncthreads();

        for (int p = tid; p < Nn*64; p += 512) {
            int r = p >> 6, c = (p & 63)*2;
            float2 m2 = *(const float2*)(msg2 + (size_t)(g*Nn + r)*Hd + c);
            float f0 = m1S[c] + m2.x, f1 = m1S[c+1] + m2.y;
            int e = eixS[r];
            if (e >= 0) {
                float2 ep = *(const float2*)(eproj + (size_t)e*Hd + c);
                f0 += ep.x; f1 += ep.y;
            }
            f0 = fmaxf(f0, 0.f); f1 = fmaxf(f1, 0.f);
            split_store(sh + O_AHI, sh + O_ALO, (uint32_t)(r*ARS + c*2), f0, f1);
        }
        __syncthreads();

        float acc[3][2][4];
#pragma unroll
        for (int mi = 0; mi < 3; mi++)
#pragma unroll
            for (int ni = 0; ni < 2; ni++)
#pragma unroll
                for (int q = 0; q < 4; q++) acc[mi][ni][q] = 0.f;

        // ---- GEMM1 ----
#pragma unroll
        for (int ks = 0; ks < 8; ks++) {
            uint32_t kbase = ks*32;
            uint32_t afh[3][4], afl[3][4], bh[4], bl2r[4];
#pragma unroll
            for (int mi = 0; mi < 3; mi++) {
                uint32_t ro = (uint32_t)((R0 + mi*16)*ARS) + kbase + aoff;
                ldsm4(afh[mi], sb + O_AHI + ro);
                ldsm4(afl[mi], sb + O_ALO + ro);
            }
            {
                uint32_t no = (uint32_t)(C0*ARS) + kbase + boff;
                ldsm4(bh,   sb + O_W1H + no);
                ldsm4(bl2r, sb + O_W1L + no);
            }
#pragma unroll
            for (int mi = 0; mi < 3; mi++)
#pragma unroll
                for (int hh = 0; hh < 2; hh++) {
                    mma16816(acc[mi][hh], afh[mi], &bh[hh*2]);
                    mma16816(acc[mi][hh], afh[mi], &bl2r[hh*2]);
                    mma16816(acc[mi][hh], afl[mi], &bh[hh*2]);
                }
        }

        // ---- epilogue1 ----
        __syncthreads();
#pragma unroll
        for (int mi = 0; mi < 3; mi++) {
#pragma unroll
            for (int ni = 0; ni < 2; ni++) {
                int r = R0 + mi*16 + gq, c = C0 + ni*8 + t*2;
                float f0 = fmaxf(acc[mi][ni][0] + b1s[c],   0.f);
                float f1 = fmaxf(acc[mi][ni][1] + b1s[c+1], 0.f);
                split_store(sh + O_AHI, sh + O_ALO, (uint32_t)(r*ARS + c*2), f0, f1);
                float f2 = fmaxf(acc[mi][ni][2] + b1s[c],   0.f);
                float f3 = fmaxf(acc[mi][ni][3] + b1s[c+1], 0.f);
                split_store(sh + O_AHI, sh + O_ALO, (uint32_t)((r+8)*ARS + c*2), f2, f3);
            }
        }
        __syncthreads();

#pragma unroll
        for (int mi = 0; mi < 3; mi++)
#pragma unroll
            for (int ni = 0; ni < 2; ni++)
#pragma unroll
                for (int q = 0; q < 4; q++) acc[mi][ni][q] = 0.f;

        // ---- GEMM2 ----
#pragma unroll
        for (int ks = 0; ks < 8; ks++) {
            uint32_t kbase = ks*32;
            uint32_t afh[3][4], afl[3][4], bh[4], bl2r[4];
#pragma unroll
            for (int mi = 0; mi < 3; mi++) {
                uint32_t ro = (uint32_t)((R0 + mi*16)*ARS) + kbase + aoff;
                ldsm4(afh[mi], sb + O_AHI + ro);
                ldsm4(afl[mi], sb + O_ALO + ro);
            }
            {
                uint32_t no = (uint32_t)(C0*ARS) + kbase + boff;
                ldsm4(bh,   sb + O_W2H + no);
                ldsm4(bl2r, sb + O_W2L + no);
            }
#pragma unroll
            for (int mi = 0; mi < 3; mi++)
#pragma unroll
                for (int hh = 0; hh < 2; hh++) {
                    mma16816(acc[mi][hh], afh[mi], &bh[hh*2]);
                    mma16816(acc[mi][hh], afh[mi], &bl2r[hh*2]);
                    mma16816(acc[mi][hh], afl[mi], &bh[hh*2]);
                }
        }

        // ---- max over senders ----
#pragma unroll
        for (int ni = 0; ni < 2; ni++) {
            float v0 = fmaxf(acc[0][ni][0], acc[0][ni][2]);
            float v1 = fmaxf(acc[0][ni][1], acc[0][ni][3]);
#pragma unroll
            for (int mi = 1; mi < 3; mi++) {
                v0 = fmaxf(v0, fmaxf(acc[mi][ni][0], acc[mi][ni][2]));
                v1 = fmaxf(v1, fmaxf(acc[mi][ni][1], acc[mi][ni][3]));
            }
#pragma unroll
            for (int st = 4; st < 32; st <<= 1) {
                v0 = fmaxf(v0, __shfl_xor_sync(0xffffffffu, v0, st));
                v1 = fmaxf(v1, __shfl_xor_sync(0xffffffffu, v1, st));
            }
            if (gq == 0) {
                maxr[rg*128 + C0 + ni*8 + t*2]     = v0;
                maxr[rg*128 + C0 + ni*8 + t*2 + 1] = v1;
            }
        }
        __syncthreads();
        if (tid < Hd)
            mmout[(g*Nn + j)*Hd + tid] =
                fmaxf(maxr[tid], maxr[128 + tid]) + b2s[tid];
        __syncthreads();
    }
}

// ---------------- out + layernorm (ffma2-packed), gridDim.y = stream -------
__device__ __forceinline__ float blk_sum128(float v, volatile float* red) {
    int tid = threadIdx.x;
#pragma unroll
    for (int o = 16; o; o >>= 1) v += __shfl_xor_sync(0xffffffffu, v, o);
    if ((tid & 31) == 0) red[tid >> 5] = v;
    __syncthreads();
    float t = red[0] + red[1] + red[2] + red[3];
    __syncthreads();
    return t;
}

__global__ void k_outln(const float* __restrict__ Wo1g, const float* __restrict__ bo1g,
                        const float* __restrict__ Wo2g, const float* __restrict__ bo2g,
                        const float* __restrict__ lgg,  const float* __restrict__ lbg,
                        int layer) {
    int s = blockIdx.y, ls = layer*2 + s;
    const float* Wo1 = Wo1g + (size_t)ls*256*Hd;
    const float* Wo2 = Wo2g + (size_t)ls*Hd*Hd;
    __shared__ float zS[256*4];
    __shared__ float mmS[128*4];
    __shared__ float red[4];
    int tid = threadIdx.x, n0 = blockIdx.x*4;
    const float* mm = g_maxmsg + (size_t)s*MSZ;
    for (int idx = tid; idx < 1024; idx += 128) {
        int nn = idx >> 8, k = idx & 255;
        float v = (k < Hd) ? g_node[(n0+nn)*Hd + k] : g_hidden[(n0+nn)*Hd + (k - Hd)];
        zS[k*4 + nn] = v;
    }
    for (int idx = tid; idx < 512; idx += 128) {
        int nn = idx >> 7, k = idx & 127;
        mmS[k*4 + nn] = mm[(n0+nn)*Hd + k];
    }
    __syncthreads();
    int h = tid;
    float bb = bo1g[ls*Hd + h] + bo2g[ls*Hd + h];
    ull a01 = pk2(bb, bb), a23 = pk2(bb, bb);
    for (int k = 0; k < 256; k++) {
        ull w = pk1(Wo1[k*Hd + h]);
        const float2* zr = (const float2*)(zS + k*4);
        float2 z01 = zr[0], z23 = zr[1];
        ffma2(a01, pk2(z01.x, z01.y), w);
        ffma2(a23, pk2(z23.x, z23.y), w);
    }
    for (int k = 0; k < 128; k++) {
        ull w = pk1(Wo2[k*Hd + h]);
        const float2* zr = (const float2*)(mmS + k*4);
        float2 z01 = zr[0], z23 = zr[1];
        ffma2(a01, pk2(z01.x, z01.y), w);
        ffma2(a23, pk2(z23.x, z23.y), w);
    }
    float acc[4];
    {
        float2 v01 = unpk(a01), v23 = unpk(a23);
        acc[0] = v01.x; acc[1] = v01.y; acc[2] = v23.x; acc[3] = v23.y;
    }
    float lgv = lgg[ls*Hd + h], lbv = lbg[ls*Hd + h];
    float* ob = s ? g_out1 : g_out0;
    for (int nn = 0; nn < 4; nn++) {
        float v = fmaxf(acc[nn], 0.f);
        float mu = blk_sum128(v, red) * (1.f/128.f);
        float d = v - mu;
        float var = blk_sum128(d*d, red) * (1.f/128.f);
        float rstd = rsqrtf(var + 1e-5f);
        ob[(n0+nn)*Hd + h] = d*rstd*lgv + lbv;
    }
}

// ---------------- hidden = concat(out0,out1) @ W_red + b_red (ffma2) -------
__global__ void k_reduce(const float* __restrict__ Wred, const float* __restrict__ bred) {
    __shared__ float zz[256*4];
    int tid = threadIdx.x, n0 = blockIdx.x*4;
    for (int idx = tid; idx < 1024; idx += 128) {
        int nn = idx >> 8, k = idx & 255;
        float v = (k < Hd) ? g_out0[(n0+nn)*Hd + k] : g_out1[(n0+nn)*Hd + (k - Hd)];
        zz[k*4 + nn] = v;
    }
    __syncthreads();
    int h = tid;
    float bb = bred[h];
    ull a01 = pk2(bb, bb), a23 = pk2(bb, bb);
    for (int k = 0; k < 256; k++) {
        ull w = pk1(Wred[k*Hd + h]);
        const float2* zr = (const float2*)(zz + k*4);
        float2 z01 = zr[0], z23 = zr[1];
        ffma2(a01, pk2(z01.x, z01.y), w);
        ffma2(a23, pk2(z23.x, z23.y), w);
    }
    float2 v01 = unpk(a01), v23 = unpk(a23);
    g_hidden[(n0+0)*Hd + h] = v01.x;
    g_hidden[(n0+1)*Hd + h] = v01.y;
    g_hidden[(n0+2)*Hd + h] = v23.x;
    g_hidden[(n0+3)*Hd + h] = v23.y;
}

// ---------------- readout --------------------------------------------------
__global__ void k_final(const float* __restrict__ Wp1, const float* __restrict__ bp1,
                        const float* __restrict__ Wp2, const float* __restrict__ bp2,
                        float* __restrict__ out) {
    __shared__ float embS[128], h1S[128], red[4];
    int g = blockIdx.x, h = threadIdx.x;
    float s = 0.f;
    for (int n = 0; n < Nn; n++) s += g_hidden[(g*Nn + n)*Hd + h];
    embS[h] = s * (1.f/96.f);
    __syncthreads();
    float a = bp1[h];
    for (int k = 0; k < 128; k++) a += embS[k]*Wp1[k*Hd + h];
    h1S[h] = fmaxf(a, 0.f);
    __syncthreads();
    float v = h1S[h] * Wp2[h];
    float tot = blk_sum128(v, red);
    if (h == 0) out[g] = tot + bp2[0];
}

// ---------------- launch ---------------------------------------------------
extern "C" void kernel_launch(void* const* d_in, const int* in_sizes, int n_in,
                              void* d_out, int out_size) {
    int o = (n_in >= 32) ? 6 : 4;
    const int*   x    = (const int*)d_in[0];
    const int*   ea   = (const int*)d_in[1];
    const int*   src  = (const int*)d_in[2];
    const int*   dst  = (const int*)d_in[3];
    const float* atom = (const float*)d_in[o+0];
    const float* bond = (const float*)d_in[o+1];
    const float* Wm1  = (const float*)d_in[o+2];
    const float* bm1  = (const float*)d_in[o+3];
    const float* Wm2  = (const float*)d_in[o+4];
    const float* bm2  = (const float*)d_in[o+5];
    const float* Wme  = (const float*)d_in[o+6];
    const float* bme  = (const float*)d_in[o+7];
    const float* bmg  = (const float*)d_in[o+9];   // W_mg unused (graph_fts == 0)
    const float* Wl1  = (const float*)d_in[o+10];
    const float* bl1  = (const float*)d_in[o+11];
    const float* Wl2  = (const float*)d_in[o+12];
    const float* bl2  = (const float*)d_in[o+13];
    const float* Wo1  = (const float*)d_in[o+14];
    const float* bo1  = (const float*)d_in[o+15];
    const float* Wo2  = (const float*)d_in[o+16];
    const float* bo2  = (const float*)d_in[o+17];
    const float* lng  = (const float*)d_in[o+18];
    const float* lnb  = (const float*)d_in[o+19];
    const float* Wred = (const float*)d_in[o+20];
    const float* bred = (const float*)d_in[o+21];
    const float* Wp1  = (const float*)d_in[o+22];
    const float* bp1  = (const float*)d_in[o+23];
    const float* Wp2  = (const float*)d_in[o+24];
    const float* bp2  = (const float*)d_in[o+25];
    float* out = (float*)d_out;

    cudaFuncSetAttribute(k_fused_mma,    cudaFuncAttributeMaxDynamicSharedMemorySize, SMEM_FUSED);
    cudaFuncSetAttribute(k_edgeproj_mma, cudaFuncAttributeMaxDynamicSharedMemorySize, SMEM_EP);

    k_encode_nodes<<<NGn, 128>>>(x, atom);
    k_encode_edges<<<Ed, 128>>>(ea, bond);
    k_init_eidx<<<(Gn*Nn*Nn + 255)/256, 256>>>();
    k_scatter<<<(Ed + 255)/256, 256>>>(src, dst);
    k_prepw<<<dim3(16, 6), 256>>>(Wl1, Wl2, Wme);

    for (int i = 0; i < 3; i++) {
        k_msg12<<<dim3(NGn/16, 2), 256>>>(Wm1, bm1, Wm2, bm2, bme, bmg, i);
        k_edgeproj_mma<<<dim3(Ed/128, 2), 512, SMEM_EP>>>(i);
        k_fused_mma<<<148, 512, SMEM_FUSED>>>(i, bl1, bl2);
        k_outln<<<dim3(NGn/4, 2), 128>>>(Wo1, bo1, Wo2, bo2, lng, lnb, i);
        k_reduce<<<NGn/4, 128>>>(Wred + (size_t)i*256*Hd, bred + i*Hd);
    }
    k_final<<<Gn, 128>>>(Wp1, bp1, Wp2, bp2, out);
    (void)in_sizes; (void)out_size;
}

// round 16
// speedup vs baseline: 1.4848x; 1.0171x over previous
#include <cuda_runtime.h>
#include <cuda_bf16.h>
#include <math.h>
#include <stdint.h>

#define Gn  16
#define Nn  96
#define Hd  128
#define Ed  24576
#define NGn (Gn*Nn)   // 1536
#define MSZ (NGn*Hd)
#define EPZ (Ed*Hd)

typedef unsigned long long ull;

// ---------------- packed f32x2 helpers -------------------------------------
__device__ __forceinline__ ull pk1(float x) {
    ull r; asm("mov.b64 %0, {%1,%1};" : "=l"(r) : "f"(x)); return r;
}
__device__ __forceinline__ ull pk2(float x, float y) {
    ull r; asm("mov.b64 %0, {%1,%2};" : "=l"(r) : "f"(x), "f"(y)); return r;
}
__device__ __forceinline__ void ffma2(ull& d, ull a, ull b) {
    asm("fma.rn.f32x2 %0, %1, %2, %0;" : "+l"(d) : "l"(a), "l"(b));
}
__device__ __forceinline__ float2 unpk(ull v) {
    float2 f; asm("mov.b64 {%0,%1}, %2;" : "=f"(f.x), "=f"(f.y) : "l"(v)); return f;
}

// ---------------- misc helpers ---------------------------------------------
__device__ __forceinline__ uint32_t s2u(const void* p) {
    uint32_t a;
    asm("{ .reg .u64 t; cvta.to.shared.u64 t, %1; cvt.u32.u64 %0, t; }" : "=r"(a) : "l"(p));
    return a;
}
__device__ __forceinline__ uint32_t pkbf(float lo, float hi) {
    uint32_t r; asm("cvt.rn.bf16x2.f32 %0, %1, %2;" : "=r"(r) : "f"(hi), "f"(lo)); return r;
}
__device__ __forceinline__ void split_store(char* hiT, char* loT, uint32_t off,
                                            float f0, float f1) {
    uint32_t h = pkbf(f0, f1);
    float h0 = __uint_as_float(h << 16);
    float h1 = __uint_as_float(h & 0xffff0000u);
    uint32_t l = pkbf(f0 - h0, f1 - h1);
    *(uint32_t*)(hiT + off) = h;
    *(uint32_t*)(loT + off) = l;
}

// HMMA m16n8k16 bf16 -> f32 accumulate (arch-agnostic PTX, sm_80+)
__device__ __forceinline__ void mma16816(float* d, const uint32_t* a, const uint32_t* b) {
    asm volatile(
        "mma.sync.aligned.m16n8k16.row.col.f32.bf16.bf16.f32 "
        "{%0,%1,%2,%3}, {%4,%5,%6,%7}, {%8,%9}, {%0,%1,%2,%3};"
        : "+f"(d[0]), "+f"(d[1]), "+f"(d[2]), "+f"(d[3])
        : "r"(a[0]), "r"(a[1]), "r"(a[2]), "r"(a[3]), "r"(b[0]), "r"(b[1]));
}
// ldmatrix x4 (sm_75+, arch-agnostic)
__device__ __forceinline__ void ldsm4(uint32_t* r, uint32_t addr) {
    asm volatile("ldmatrix.sync.aligned.m8n8.x4.shared.b16 {%0,%1,%2,%3}, [%4];"
        : "=r"(r[0]), "=r"(r[1]), "=r"(r[2]), "=r"(r[3]) : "r"(addr));
}

// ---------------- scratch ---------------------------------------------------
#define ARS  272              // tile row stride in bytes (136 bf16)
#define TILE_B 34816          // 128 rows * 272 B
#define WSET_B (4*TILE_B)     // W1H,W1L,W2H,W2L contiguous = 139264 B

__device__ __align__(16) float g_node[MSZ];
__device__ __align__(16) float g_hidden[MSZ];
__device__ __align__(16) float g_edgefts[EPZ];
__device__ __align__(16) float g_edgeproj[2*EPZ];     // per-stream, per-layer (L2-hot)
__device__              int   g_eidx[Gn*Nn*Nn];
__device__ __align__(16) float g_msg1[2*MSZ];
__device__ __align__(16) float g_msg2[2*MSZ];
__device__ __align__(16) float g_maxmsg[2*MSZ];
__device__ __align__(16) float g_out0[MSZ];
__device__ __align__(16) float g_out1[MSZ];
__device__ __align__(16) char  g_wt[6*WSET_B];        // pre-split MLP weight tiles
__device__ __align__(16) char  g_wtme[6*2*TILE_B];    // pre-split W_me tiles
__device__ unsigned g_barc = 0;                       // grid barrier counter

extern __shared__ char dyn_smem[];

// software grid barrier (valid: 148 blocks, all co-resident at 1 block/SM)
__device__ __forceinline__ void gridbar() {
    __syncthreads();
    __threadfence();
    if (threadIdx.x == 0) {
        unsigned arr = atomicAdd(&g_barc, 1u);
        unsigned tgt = (arr/148u + 1u)*148u;
        while (*(volatile unsigned*)&g_barc < tgt) { }
        __threadfence();
    }
    __syncthreads();
}

// ---------------- encoders --------------------------------------------------
__global__ void k_encode_nodes(const int* __restrict__ x,
                               const float* __restrict__ atom) {
    int n = blockIdx.x, h = threadIdx.x;
    float s = 0.f;
#pragma unroll
    for (int c = 0; c < 9; c++) {
        int id = x[n*9 + c];
        s += atom[(c*119 + id)*Hd + h];
    }
    g_node[n*Hd + h]   = s;
    g_hidden[n*Hd + h] = 0.f;
}

__global__ void k_encode_edges(const int* __restrict__ ea,
                               const float* __restrict__ bond) {
    int e = blockIdx.x, h = threadIdx.x;
    float s = 0.f;
#pragma unroll
    for (int c = 0; c < 3; c++) {
        int id = ea[e*3 + c];
        s += bond[(c*6 + id)*Hd + h];
    }
    g_edgefts[e*Hd + h] = s;
}

__global__ void k_init_eidx() {
    int i = blockIdx.x*blockDim.x + threadIdx.x;
    if (i < Gn*Nn*Nn) g_eidx[i] = -1;
}

__global__ void k_scatter(const int* __restrict__ src, const int* __restrict__ dst) {
    int e = blockIdx.x*blockDim.x + threadIdx.x;
    if (e >= Ed) return;
    int s = src[e], d = dst[e];
    int g  = s / Nn;
    int li = s % Nn;
    int lj = d % Nn;
    atomicMax(&g_eidx[(g*Nn + li)*Nn + lj], e);
}

// ---------------- one-time weight prep (W1, W2, Wme) -----------------------
__global__ void k_prepw(const float* __restrict__ Wl1, const float* __restrict__ Wl2,
                        const float* __restrict__ Wmeg) {
    int ls = blockIdx.y;
    const float* W1 = Wl1 + (size_t)ls*Hd*Hd;
    const float* W2 = Wl2 + (size_t)ls*Hd*Hd;
    const float* We = Wmeg + (size_t)ls*Hd*Hd;
    char* base  = g_wt + (size_t)ls*WSET_B;
    char* baseE = g_wtme + (size_t)ls*2*TILE_B;
    int n0 = blockIdx.x*8;
    for (int p = threadIdx.x; p < 8*64; p += 256) {
        int nl = p >> 6, k = (p & 63)*2;
        int n = n0 + nl;
        uint32_t off = (uint32_t)(n*ARS + k*2);
        split_store(base,            base + TILE_B,   off, W1[k*Hd + n], W1[(k+1)*Hd + n]);
        split_store(base + 2*TILE_B, base + 3*TILE_B, off, W2[k*Hd + n], W2[(k+1)*Hd + n]);
        split_store(baseE,           baseE + TILE_B,  off, We[k*Hd + n], We[(k+1)*Hd + n]);
    }
}

// ---------------- per-layer mega kernel ------------------------------------
// grid = 148 blocks x 512 threads; smem = 194432
// Phase A: 96 msg12 units (32 nodes each) + 384 edgeproj units (128 edges)
// grid barrier
// Phase B: 3072 fused (stream,g,j) tiles
#define O_AHI  0
#define O_ALO  26112
#define O_W1H  52224
#define O_W1L  (O_W1H + TILE_B)
#define O_W2H  (O_W1H + 2*TILE_B)
#define O_W2L  (O_W1H + 3*TILE_B)
#define O_B1   191488
#define O_M1   192000
#define O_EIX  192512
#define O_MAXR 192896
#define O_B2   193920
#define SMEM_FUSED 194432
// edgeproj-unit local smem layout (flat 4 x TILE_B)
#define EP_AHI 0
#define EP_ALO TILE_B
#define EP_WH  (2*TILE_B)
#define EP_WL  (3*TILE_B)

__global__ void __launch_bounds__(512, 1)
k_layer(int layer,
        const float* __restrict__ Wm1, const float* __restrict__ bm1g,
        const float* __restrict__ Wm2, const float* __restrict__ bm2g,
        const float* __restrict__ bmeg, const float* __restrict__ bmgg,
        const float* __restrict__ bl1, const float* __restrict__ bl2) {
    char* sh = dyn_smem;
    const uint32_t sb = s2u(sh);
    const int tid = threadIdx.x, w = tid >> 5, lane = tid & 31;
    const int gq = lane >> 2, t = lane & 3;

    const uint32_t aoff = (uint32_t)(((lane & 7) + ((lane >> 3) & 1)*8)*ARS
                                     + ((lane >> 4) & 1)*16);
    const uint32_t boff = (uint32_t)((((lane >> 4) & 1)*8 + (lane & 7))*ARS
                                     + ((lane >> 3) & 1)*16);

    // ================= Phase A: msg12 + edgeproj units =================
    for (int u = blockIdx.x; u < 96 + 384; u += 148) {
        if (u < 96) {
            // ---- msg12 unit: 32 nodes, stream s (bit-identical body) ----
            int s = u / 48, chunk = u % 48, ls = layer*2 + s;
            const float* W1 = Wm1 + (size_t)ls*256*Hd;
            const float* W2 = Wm2 + (size_t)ls*256*Hd;
            int grp = tid >> 7, h = tid & 127;
            int n0 = chunk*32 + grp*8;
            float* zS = (float*)(sh) + grp*2048;
            for (int idx = h; idx < 8*256; idx += 128) {
                int nn = idx >> 8, k = idx & 255;
                int n = n0 + nn;
                float v = (k < Hd) ? g_node[n*Hd + k] : g_hidden[n*Hd + (k - Hd)];
                zS[k*8 + nn] = v;
            }
            __syncthreads();
            ull a1[4], a2[4];
#pragma unroll
            for (int p = 0; p < 4; p++) { a1[p] = 0ull; a2[p] = 0ull; }
            for (int k = 0; k < 256; k++) {
                ull w1 = pk1(W1[k*Hd + h]);
                ull w2 = pk1(W2[k*Hd + h]);
                const float2* zr = (const float2*)(zS + k*8);
#pragma unroll
                for (int p = 0; p < 4; p++) {
                    float2 z = zr[p];
                    ull zp = pk2(z.x, z.y);
                    ffma2(a1[p], zp, w1);
                    ffma2(a2[p], zp, w2);
                }
            }
            float bb1 = bm1g[ls*Hd + h] + bmeg[ls*Hd + h] + bmgg[ls*Hd + h];
            float bb2 = bm2g[ls*Hd + h];
            float* m1 = g_msg1 + (size_t)s*MSZ;
            float* m2 = g_msg2 + (size_t)s*MSZ;
#pragma unroll
            for (int p = 0; p < 4; p++) {
                float2 v1 = unpk(a1[p]), v2 = unpk(a2[p]);
                m1[(n0+2*p+0)*Hd + h] = v1.x + bb1;
                m1[(n0+2*p+1)*Hd + h] = v1.y + bb1;
                m2[(n0+2*p+0)*Hd + h] = v2.x + bb2;
                m2[(n0+2*p+1)*Hd + h] = v2.y + bb2;
            }
            __syncthreads();
        } else {
            // ---- edgeproj unit: 128 edges, stream s (bit-identical) ----
            int v2u = u - 96;
            int s = v2u / 192, tile = v2u % 192, ls = layer*2 + s;
            const int e0 = tile*128;
            const int rg = w >> 2, cg = w & 3;     // 4x4 warp grid
            const int R0 = rg*32, C0 = cg*32;
            {
                const uint4* src = (const uint4*)(g_wtme + (size_t)ls*2*TILE_B);
                uint4* dst = (uint4*)(sh + EP_WH);
                for (int p = tid; p < 2*TILE_B/16; p += 512) dst[p] = src[p];
            }
            for (int p = tid; p < 128*64; p += 512) {
                int r = p >> 6, c = (p & 63)*2;
                float2 a = *(const float2*)(g_edgefts + (size_t)(e0 + r)*Hd + c);
                split_store(sh + EP_AHI, sh + EP_ALO, (uint32_t)(r*ARS + c*2), a.x, a.y);
            }
            __syncthreads();

            float acc[2][4][4];
#pragma unroll
            for (int mi = 0; mi < 2; mi++)
#pragma unroll
                for (int ni = 0; ni < 4; ni++)
#pragma unroll
                    for (int q = 0; q < 4; q++) acc[mi][ni][q] = 0.f;

#pragma unroll
            for (int ks = 0; ks < 8; ks++) {
                uint32_t kbase = ks*32;
                uint32_t afh[2][4], afl[2][4], bh[2][4], bl2[2][4];
#pragma unroll
                for (int mi = 0; mi < 2; mi++) {
                    uint32_t ro = (uint32_t)((R0 + mi*16)*ARS) + kbase + aoff;
                    ldsm4(afh[mi], sb + EP_AHI + ro);
                    ldsm4(afl[mi], sb + EP_ALO + ro);
                }
#pragma unroll
                for (int p = 0; p < 2; p++) {
                    uint32_t no = (uint32_t)((C0 + p*16)*ARS) + kbase + boff;
                    ldsm4(bh[p],  sb + EP_WH + no);
                    ldsm4(bl2[p], sb + EP_WL + no);
                }
#pragma unroll
                for (int mi = 0; mi < 2; mi++)
#pragma unroll
                    for (int p = 0; p < 2; p++)
#pragma unroll
                        for (int hh = 0; hh < 2; hh++) {
                            int ni = p*2 + hh;
                            mma16816(acc[mi][ni], afh[mi], &bh[p][hh*2]);
                            mma16816(acc[mi][ni], afh[mi], &bl2[p][hh*2]);
                            mma16816(acc[mi][ni], afl[mi], &bh[p][hh*2]);
                        }
            }

            float* ep = g_edgeproj + (size_t)s*EPZ;
#pragma unroll
            for (int mi = 0; mi < 2; mi++)
#pragma unroll
                for (int ni = 0; ni < 4; ni++) {
                    int r = R0 + mi*16 + gq, c = C0 + ni*8 + t*2;
                    *(float2*)(ep + (size_t)(e0 + r)*Hd + c) =
                        make_float2(acc[mi][ni][0], acc[mi][ni][1]);
                    *(float2*)(ep + (size_t)(e0 + r + 8)*Hd + c) =
                        make_float2(acc[mi][ni][2], acc[mi][ni][3]);
                }
            __syncthreads();
        }
    }

    gridbar();

    // ================= Phase B: fused message MLP + max =================
    const int rg = w >> 3, cg = w & 7;      // 2 x 8 warp grid
    const int R0 = rg*48, C0 = cg*16;

    float* b1s  = (float*)(sh + O_B1);
    float* b2s  = (float*)(sh + O_B2);
    float* m1S  = (float*)(sh + O_M1);
    int*   eixS = (int*)(sh + O_EIX);
    float* maxr = (float*)(sh + O_MAXR);

    int cur_s = -1;
    for (int tt = blockIdx.x; tt < 2*NGn; tt += gridDim.x) {
        const int s  = (tt >= NGn) ? 1 : 0;
        const int lt = tt - s*NGn;
        const int g  = lt / Nn, j = lt - g*Nn;
        const int ls = layer*2 + s;

        if (s != cur_s) {
            const uint4* src = (const uint4*)(g_wt + (size_t)ls*WSET_B);
            uint4* dst = (uint4*)(sh + O_W1H);
            for (int p = tid; p < WSET_B/16; p += 512) dst[p] = src[p];
            if (tid < Hd)       b1s[tid] = bl1[ls*Hd + tid];
            else if (tid < 256) b2s[tid - 128] = bl2[ls*Hd + (tid - 128)];
            cur_s = s;
        }

        const float* msg1  = g_msg1 + (size_t)s*MSZ;
        const float* msg2  = g_msg2 + (size_t)s*MSZ;
        const float* eproj = g_edgeproj + (size_t)s*EPZ;
        float* mmout = g_maxmsg + (size_t)s*MSZ;

        if (tid < Hd)       m1S[tid] = msg1[(g*Nn + j)*Hd + tid];
        else if (tid < 224) eixS[tid - 128] = g_eidx[(g*Nn + (tid - 128))*Nn + j];
        __syncthreads();

        for (int p = tid; p < Nn*64; p += 512) {
            int r = p >> 6, c = (p & 63)*2;
            float2 m2 = *(const float2*)(msg2 + (size_t)(g*Nn + r)*Hd + c);
            float f0 = m1S[c] + m2.x, f1 = m1S[c+1] + m2.y;
            int e = eixS[r];
            if (e >= 0) {
                float2 ep = *(const float2*)(eproj + (size_t)e*Hd + c);
                f0 += ep.x; f1 += ep.y;
            }
            f0 = fmaxf(f0, 0.f); f1 = fmaxf(f1, 0.f);
            split_store(sh + O_AHI, sh + O_ALO, (uint32_t)(r*ARS + c*2), f0, f1);
        }
        __syncthreads();

        float acc[3][2][4];
#pragma unroll
        for (int mi = 0; mi < 3; mi++)
#pragma unroll
            for (int ni = 0; ni < 2; ni++)
#pragma unroll
                for (int q = 0; q < 4; q++) acc[mi][ni][q] = 0.f;

        // ---- GEMM1 ----
#pragma unroll
        for (int ks = 0; ks < 8; ks++) {
            uint32_t kbase = ks*32;
            uint32_t afh[3][4], afl[3][4], bh[4], bl2r[4];
#pragma unroll
            for (int mi = 0; mi < 3; mi++) {
                uint32_t ro = (uint32_t)((R0 + mi*16)*ARS) + kbase + aoff;
                ldsm4(afh[mi], sb + O_AHI + ro);
                ldsm4(afl[mi], sb + O_ALO + ro);
            }
            {
                uint32_t no = (uint32_t)(C0*ARS) + kbase + boff;
                ldsm4(bh,   sb + O_W1H + no);
                ldsm4(bl2r, sb + O_W1L + no);
            }
#pragma unroll
            for (int mi = 0; mi < 3; mi++)
#pragma unroll
                for (int hh = 0; hh < 2; hh++) {
                    mma16816(acc[mi][hh], afh[mi], &bh[hh*2]);
                    mma16816(acc[mi][hh], afh[mi], &bl2r[hh*2]);
                    mma16816(acc[mi][hh], afl[mi], &bh[hh*2]);
                }
        }

        // ---- epilogue1 ----
        __syncthreads();
#pragma unroll
        for (int mi = 0; mi < 3; mi++) {
#pragma unroll
            for (int ni = 0; ni < 2; ni++) {
                int r = R0 + mi*16 + gq, c = C0 + ni*8 + t*2;
                float f0 = fmaxf(acc[mi][ni][0] + b1s[c],   0.f);
                float f1 = fmaxf(acc[mi][ni][1] + b1s[c+1], 0.f);
                split_store(sh + O_AHI, sh + O_ALO, (uint32_t)(r*ARS + c*2), f0, f1);
                float f2 = fmaxf(acc[mi][ni][2] + b1s[c],   0.f);
                float f3 = fmaxf(acc[mi][ni][3] + b1s[c+1], 0.f);
                split_store(sh + O_AHI, sh + O_ALO, (uint32_t)((r+8)*ARS + c*2), f2, f3);
            }
        }
        __syncthreads();

#pragma unroll
        for (int mi = 0; mi < 3; mi++)
#pragma unroll
            for (int ni = 0; ni < 2; ni++)
#pragma unroll
                for (int q = 0; q < 4; q++) acc[mi][ni][q] = 0.f;

        // ---- GEMM2 ----
#pragma unroll
        for (int ks = 0; ks < 8; ks++) {
            uint32_t kbase = ks*32;
            uint32_t afh[3][4], afl[3][4], bh[4], bl2r[4];
#pragma unroll
            for (int mi = 0; mi < 3; mi++) {
                uint32_t ro = (uint32_t)((R0 + mi*16)*ARS) + kbase + aoff;
                ldsm4(afh[mi], sb + O_AHI + ro);
                ldsm4(afl[mi], sb + O_ALO + ro);
            }
            {
                uint32_t no = (uint32_t)(C0*ARS) + kbase + boff;
                ldsm4(bh,   sb + O_W2H + no);
                ldsm4(bl2r, sb + O_W2L + no);
            }
#pragma unroll
            for (int mi = 0; mi < 3; mi++)
#pragma unroll
                for (int hh = 0; hh < 2; hh++) {
                    mma16816(acc[mi][hh], afh[mi], &bh[hh*2]);
                    mma16816(acc[mi][hh], afh[mi], &bl2r[hh*2]);
                    mma16816(acc[mi][hh], afl[mi], &bh[hh*2]);
                }
        }

        // ---- max over senders ----
#pragma unroll
        for (int ni = 0; ni < 2; ni++) {
            float v0 = fmaxf(acc[0][ni][0], acc[0][ni][2]);
            float v1 = fmaxf(acc[0][ni][1], acc[0][ni][3]);
#pragma unroll
            for (int mi = 1; mi < 3; mi++) {
                v0 = fmaxf(v0, fmaxf(acc[mi][ni][0], acc[mi][ni][2]));
                v1 = fmaxf(v1, fmaxf(acc[mi][ni][1], acc[mi][ni][3]));
            }
#pragma unroll
            for (int st = 4; st < 32; st <<= 1) {
                v0 = fmaxf(v0, __shfl_xor_sync(0xffffffffu, v0, st));
                v1 = fmaxf(v1, __shfl_xor_sync(0xffffffffu, v1, st));
            }
            if (gq == 0) {
                maxr[rg*128 + C0 + ni*8 + t*2]     = v0;
                maxr[rg*128 + C0 + ni*8 + t*2 + 1] = v1;
            }
        }
        __syncthreads();
        if (tid < Hd)
            mmout[(g*Nn + j)*Hd + tid] =
                fmaxf(maxr[tid], maxr[128 + tid]) + b2s[tid];
        __syncthreads();
    }
}

// ---------------- out + layernorm (ffma2-packed), gridDim.y = stream -------
__device__ __forceinline__ float blk_sum128(float v, volatile float* red) {
    int tid = threadIdx.x;
#pragma unroll
    for (int o = 16; o; o >>= 1) v += __shfl_xor_sync(0xffffffffu, v, o);
    if ((tid & 31) == 0) red[tid >> 5] = v;
    __syncthreads();
    float t = red[0] + red[1] + red[2] + red[3];
    __syncthreads();
    return t;
}

__global__ void k_outln(const float* __restrict__ Wo1g, const float* __restrict__ bo1g,
                        const float* __restrict__ Wo2g, const float* __restrict__ bo2g,
                        const float* __restrict__ lgg,  const float* __restrict__ lbg,
                        int layer) {
    int s = blockIdx.y, ls = layer*2 + s;
    const float* Wo1 = Wo1g + (size_t)ls*256*Hd;
    const float* Wo2 = Wo2g + (size_t)ls*Hd*Hd;
    __shared__ float zS[256*4];
    __shared__ float mmS[128*4];
    __shared__ float red[4];
    int tid = threadIdx.x, n0 = blockIdx.x*4;
    const float* mm = g_maxmsg + (size_t)s*MSZ;
    for (int idx = tid; idx < 1024; idx += 128) {
        int nn = idx >> 8, k = idx & 255;
        float v = (k < Hd) ? g_node[(n0+nn)*Hd + k] : g_hidden[(n0+nn)*Hd + (k - Hd)];
        zS[k*4 + nn] = v;
    }
    for (int idx = tid; idx < 512; idx += 128) {
        int nn = idx >> 7, k = idx & 127;
        mmS[k*4 + nn] = mm[(n0+nn)*Hd + k];
    }
    __syncthreads();
    int h = tid;
    float bb = bo1g[ls*Hd + h] + bo2g[ls*Hd + h];
    ull a01 = pk2(bb, bb), a23 = pk2(bb, bb);
    for (int k = 0; k < 256; k++) {
        ull w = pk1(Wo1[k*Hd + h]);
        const float2* zr = (const float2*)(zS + k*4);
        float2 z01 = zr[0], z23 = zr[1];
        ffma2(a01, pk2(z01.x, z01.y), w);
        ffma2(a23, pk2(z23.x, z23.y), w);
    }
    for (int k = 0; k < 128; k++) {
        ull w = pk1(Wo2[k*Hd + h]);
        const float2* zr = (const float2*)(mmS + k*4);
        float2 z01 = zr[0], z23 = zr[1];
        ffma2(a01, pk2(z01.x, z01.y), w);
        ffma2(a23, pk2(z23.x, z23.y), w);
    }
    float acc[4];
    {
        float2 v01 = unpk(a01), v23 = unpk(a23);
        acc[0] = v01.x; acc[1] = v01.y; acc[2] = v23.x; acc[3] = v23.y;
    }
    float lgv = lgg[ls*Hd + h], lbv = lbg[ls*Hd + h];
    float* ob = s ? g_out1 : g_out0;
    for (int nn = 0; nn < 4; nn++) {
        float v = fmaxf(acc[nn], 0.f);
        float mu = blk_sum128(v, red) * (1.f/128.f);
        float d = v - mu;
        float var = blk_sum128(d*d, red) * (1.f/128.f);
        float rstd = rsqrtf(var + 1e-5f);
        ob[(n0+nn)*Hd + h] = d*rstd*lgv + lbv;
    }
}

// ---------------- hidden = concat(out0,out1) @ W_red + b_red (ffma2) -------
__global__ void k_reduce(const float* __restrict__ Wred, const float* __restrict__ bred) {
    __shared__ float zz[256*4];
    int tid = threadIdx.x, n0 = blockIdx.x*4;
    for (int idx = tid; idx < 1024; idx += 128) {
        int nn = idx >> 8, k = idx & 255;
        float v = (k < Hd) ? g_out0[(n0+nn)*Hd + k] : g_out1[(n0+nn)*Hd + (k - Hd)];
        zz[k*4 + nn] = v;
    }
    __syncthreads();
    int h = tid;
    float bb = bred[h];
    ull a01 = pk2(bb, bb), a23 = pk2(bb, bb);
    for (int k = 0; k < 256; k++) {
        ull w = pk1(Wred[k*Hd + h]);
        const float2* zr = (const float2*)(zz + k*4);
        float2 z01 = zr[0], z23 = zr[1];
        ffma2(a01, pk2(z01.x, z01.y), w);
        ffma2(a23, pk2(z23.x, z23.y), w);
    }
    float2 v01 = unpk(a01), v23 = unpk(a23);
    g_hidden[(n0+0)*Hd + h] = v01.x;
    g_hidden[(n0+1)*Hd + h] = v01.y;
    g_hidden[(n0+2)*Hd + h] = v23.x;
    g_hidden[(n0+3)*Hd + h] = v23.y;
}

// ---------------- readout --------------------------------------------------
__global__ void k_final(const float* __restrict__ Wp1, const float* __restrict__ bp1,
                        const float* __restrict__ Wp2, const float* __restrict__ bp2,
                        float* __restrict__ out) {
    __shared__ float embS[128], h1S[128], red[4];
    int g = blockIdx.x, h = threadIdx.x;
    float s = 0.f;
    for (int n = 0; n < Nn; n++) s += g_hidden[(g*Nn + n)*Hd + h];
    embS[h] = s * (1.f/96.f);
    __syncthreads();
    float a = bp1[h];
    for (int k = 0; k < 128; k++) a += embS[k]*Wp1[k*Hd + h];
    h1S[h] = fmaxf(a, 0.f);
    __syncthreads();
    float v = h1S[h] * Wp2[h];
    float tot = blk_sum128(v, red);
    if (h == 0) out[g] = tot + bp2[0];
}

// ---------------- launch ---------------------------------------------------
extern "C" void kernel_launch(void* const* d_in, const int* in_sizes, int n_in,
                              void* d_out, int out_size) {
    int o = (n_in >= 32) ? 6 : 4;
    const int*   x    = (const int*)d_in[0];
    const int*   ea   = (const int*)d_in[1];
    const int*   src  = (const int*)d_in[2];
    const int*   dst  = (const int*)d_in[3];
    const float* atom = (const float*)d_in[o+0];
    const float* bond = (const float*)d_in[o+1];
    const float* Wm1  = (const float*)d_in[o+2];
    const float* bm1  = (const float*)d_in[o+3];
    const float* Wm2  = (const float*)d_in[o+4];
    const float* bm2  = (const float*)d_in[o+5];
    const float* Wme  = (const float*)d_in[o+6];
    const float* bme  = (const float*)d_in[o+7];
    const float* bmg  = (const float*)d_in[o+9];   // W_mg unused (graph_fts == 0)
    const float* Wl1  = (const float*)d_in[o+10];
    const float* bl1  = (const float*)d_in[o+11];
    const float* Wl2  = (const float*)d_in[o+12];
    const float* bl2  = (const float*)d_in[o+13];
    const float* Wo1  = (const float*)d_in[o+14];
    const float* bo1  = (const float*)d_in[o+15];
    const float* Wo2  = (const float*)d_in[o+16];
    const float* bo2  = (const float*)d_in[o+17];
    const float* lng  = (const float*)d_in[o+18];
    const float* lnb  = (const float*)d_in[o+19];
    const float* Wred = (const float*)d_in[o+20];
    const float* bred = (const float*)d_in[o+21];
    const float* Wp1  = (const float*)d_in[o+22];
    const float* bp1  = (const float*)d_in[o+23];
    const float* Wp2  = (const float*)d_in[o+24];
    const float* bp2  = (const float*)d_in[o+25];
    float* out = (float*)d_out;

    cudaFuncSetAttribute(k_layer, cudaFuncAttributeMaxDynamicSharedMemorySize, SMEM_FUSED);

    k_encode_nodes<<<NGn, 128>>>(x, atom);
    k_encode_edges<<<Ed, 128>>>(ea, bond);
    k_init_eidx<<<(Gn*Nn*Nn + 255)/256, 256>>>();
    k_scatter<<<(Ed + 255)/256, 256>>>(src, dst);
    k_prepw<<<dim3(16, 6), 256>>>(Wl1, Wl2, Wme);

    for (int i = 0; i < 3; i++) {
        k_layer<<<148, 512, SMEM_FUSED>>>(i, Wm1, bm1, Wm2, bm2, bme, bmg, bl1, bl2);
        k_outln<<<dim3(NGn/4, 2), 128>>>(Wo1, bo1, Wo2, bo2, lng, lnb, i);
        k_reduce<<<NGn/4, 128>>>(Wred + (size_t)i*256*Hd, bred + i*Hd);
    }
    k_final<<<Gn, 128>>>(Wp1, bp1, Wp2, bp2, out);
    (void)in_sizes; (void)out_size;
}